// round 1
// baseline (speedup 1.0000x reference)
#include <cuda_runtime.h>
#include <math.h>

#define BB 2
#define CC 64
#define HHH 48
#define WWW 48
#define LL 2304
#define NHH 8
#define DKK 64
#define DVV 128
#define DNN 128
#define NSS 16
#define CM 256
#define BHN (BB*NHH)

// ---------------- scratch (static device globals; no runtime alloc) ----------
__device__ float g_q[BHN*LL*DKK];
__device__ float g_k[BHN*LL*DKK];
__device__ float g_v[BHN*LL*DVV];
__device__ float g_logsnr[BB*LL];
__device__ float g_S[(size_t)BHN*LL*LL];      // 340 MB score/prob scratch
__device__ float g_o[BB*LL*NHH*DVV];
__device__ float g_tok[BB*LL*CC];
__device__ float g_z[BB*LL*DNN];
__device__ float g_x1pre[BB*DNN*LL];
__device__ float g_x1[BB*DNN*LL];
__device__ float g_dt[BB*4*DNN*LL];
__device__ float g_u[BB*4*DNN*LL];
__device__ float g_Bsc[BB*4*LL*NSS];
__device__ float g_Csc[BB*4*LL*NSS];
__device__ float g_ys[BB*4*DNN*LL];
__device__ float g_x2[BB*LL*CC];
__device__ float g_xn[BB*LL*CC];
__device__ float g_h1[BB*CM*LL];
__device__ float g_h2[BB*CM*LL];

// ---------------- helpers ----------------------------------------------------
__device__ __forceinline__ float silu_f(float x){ return x/(1.f+__expf(-x)); }
__device__ __forceinline__ float gelu_f(float x){ return 0.5f*x*(1.f+erff(x*0.70710678118654752440f)); }
__device__ __forceinline__ float softplus_f(float x){ return fmaxf(x,0.f)+log1pf(__expf(-fabsf(x))); }

// ---------------- K1: log(snr+1e-4) ------------------------------------------
__global__ void k_logsnr(const float* __restrict__ snr){
    int i = blockIdx.x*256 + threadIdx.x;
    if(i < BB*LL) g_logsnr[i] = logf(snr[i] + 1e-4f);
}

// ---------------- K2: QKV projections ----------------------------------------
// x_tok[b,l,c] = enc[b,c,l]; q/k = x@W (C x 512), v = x@Wv (C x 1024)
__global__ void k_qkv(const float* __restrict__ enc, const float* __restrict__ wq,
                      const float* __restrict__ wk, const float* __restrict__ wv){
    __shared__ float Xs[64][65];  // [c][l]
    __shared__ float Ws[64][65];  // [c][j]
    int b = blockIdx.z;
    int l0 = blockIdx.x*64;
    int t  = blockIdx.y;
    const float* wptr; int j0, wwid, which;
    if(t < 8){ wptr=wq; j0=t*64; wwid=512; which=0; }
    else if(t < 16){ wptr=wk; j0=(t-8)*64; wwid=512; which=1; }
    else { wptr=wv; j0=(t-16)*64; wwid=1024; which=2; }
    int tid = threadIdx.x;
    for(int i=tid;i<4096;i+=256){
        int c=i>>6, ll=i&63;
        Xs[c][ll] = enc[(size_t)(b*CC+c)*LL + l0 + ll];
    }
    for(int i=tid;i<4096;i+=256){
        int c=i>>6, jj=i&63;
        Ws[c][jj] = wptr[(size_t)c*wwid + j0 + jj];
    }
    __syncthreads();
    int rg=tid>>4, cg=tid&15; int r0=rg*4, c0=cg*4;
    float acc[4][4] = {};
    #pragma unroll 8
    for(int c=0;c<64;c++){
        float a0=Xs[c][r0],a1=Xs[c][r0+1],a2=Xs[c][r0+2],a3=Xs[c][r0+3];
        float b0=Ws[c][c0],b1=Ws[c][c0+1],b2=Ws[c][c0+2],b3=Ws[c][c0+3];
        acc[0][0]+=a0*b0; acc[0][1]+=a0*b1; acc[0][2]+=a0*b2; acc[0][3]+=a0*b3;
        acc[1][0]+=a1*b0; acc[1][1]+=a1*b1; acc[1][2]+=a1*b2; acc[1][3]+=a1*b3;
        acc[2][0]+=a2*b0; acc[2][1]+=a2*b1; acc[2][2]+=a2*b2; acc[2][3]+=a2*b3;
        acc[3][0]+=a3*b0; acc[3][1]+=a3*b1; acc[3][2]+=a3*b2; acc[3][3]+=a3*b3;
    }
    #pragma unroll
    for(int m=0;m<4;m++){
        int l = l0+r0+m;
        #pragma unroll
        for(int n=0;n<4;n++){
            int j = j0+c0+n;
            float v = acc[m][n];
            if(which==0){ int h=j>>6, dk=j&63; g_q[((size_t)(b*8+h)*LL+l)*64+dk]=v; }
            else if(which==1){ int h=j>>6, dk=j&63; g_k[((size_t)(b*8+h)*LL+l)*64+dk]=v; }
            else { int h=j>>7, dv=j&127; g_v[((size_t)(b*8+h)*LL+l)*128+dv]=v; }
        }
    }
}

// ---------------- K3: scores = QK^T/8 + log(snr) ------------------------------
__global__ void k_scores(){
    __shared__ float Qs[64][68];
    __shared__ float Ks[64][68];
    int bh = blockIdx.z;
    int i0 = blockIdx.y*64, j0 = blockIdx.x*64;
    int b = bh>>3;
    int tid = threadIdx.x;
    const float* qp = g_q + (size_t)bh*LL*64;
    const float* kp = g_k + (size_t)bh*LL*64;
    for(int i=tid*4;i<4096;i+=1024){
        int r=i>>6, c=i&63;
        *(float4*)&Qs[r][c] = *(const float4*)(qp + (size_t)(i0+r)*64 + c);
        *(float4*)&Ks[r][c] = *(const float4*)(kp + (size_t)(j0+r)*64 + c);
    }
    __syncthreads();
    int rg=tid>>4, cg=tid&15; int r0=rg*4, c0=cg*4;
    float acc[4][4] = {};
    #pragma unroll
    for(int k4=0;k4<64;k4+=4){
        float4 a[4], bv[4];
        #pragma unroll
        for(int m=0;m<4;m++) a[m]  = *(const float4*)&Qs[r0+m][k4];
        #pragma unroll
        for(int n=0;n<4;n++) bv[n] = *(const float4*)&Ks[c0+n][k4];
        #pragma unroll
        for(int m=0;m<4;m++)
            #pragma unroll
            for(int n=0;n<4;n++)
                acc[m][n] += a[m].x*bv[n].x + a[m].y*bv[n].y + a[m].z*bv[n].z + a[m].w*bv[n].w;
    }
    float* sp = g_S + (size_t)bh*LL*LL;
    #pragma unroll
    for(int m=0;m<4;m++){
        #pragma unroll
        for(int n=0;n<4;n++){
            int j = j0+c0+n;
            sp[(size_t)(i0+r0+m)*LL + j] = acc[m][n]*0.125f + g_logsnr[b*LL + j];
        }
    }
}

// ---------------- K4: row softmax --------------------------------------------
__global__ void k_softmax(){
    __shared__ float row[LL];
    __shared__ float red[256];
    int bh = blockIdx.y, i = blockIdx.x, tid = threadIdx.x;
    float* sp = g_S + ((size_t)bh*LL + i)*LL;
    float mx = -1e30f;
    for(int j=tid;j<LL;j+=256){ float v=sp[j]; row[j]=v; mx=fmaxf(mx,v); }
    red[tid]=mx; __syncthreads();
    for(int s=128;s>0;s>>=1){ if(tid<s) red[tid]=fmaxf(red[tid],red[tid+s]); __syncthreads(); }
    mx = red[0];
    __syncthreads();
    float sum=0.f;
    for(int j=tid;j<LL;j+=256){ float e=__expf(row[j]-mx); row[j]=e; sum+=e; }
    red[tid]=sum; __syncthreads();
    for(int s=128;s>0;s>>=1){ if(tid<s) red[tid]+=red[tid+s]; __syncthreads(); }
    float inv = 1.f/red[0];
    for(int j=tid;j<LL;j+=256) sp[j] = row[j]*inv;
}

// ---------------- K5: O = P @ V ----------------------------------------------
__global__ void k_pv(){
    __shared__ float Ps[64][36];
    __shared__ float Vs[32][132];
    int bh = blockIdx.y, i0 = blockIdx.x*64, tid = threadIdx.x;
    int b = bh>>3, h = bh&7;
    const float* sp = g_S + (size_t)bh*LL*LL;
    const float* vp = g_v + (size_t)bh*LL*128;
    int rr=(tid>>3)*2, c0=(tid&7)*16;
    float acc[32] = {};
    for(int j0=0;j0<LL;j0+=32){
        __syncthreads();
        for(int idx=tid*4; idx<64*32; idx+=1024){
            int r=idx>>5, c=idx&31;
            *(float4*)&Ps[r][c] = *(const float4*)(sp + (size_t)(i0+r)*LL + j0 + c);
        }
        for(int idx=tid*4; idx<32*128; idx+=1024){
            int r=idx>>7, c=idx&127;
            *(float4*)&Vs[r][c] = *(const float4*)(vp + (size_t)(j0+r)*128 + c);
        }
        __syncthreads();
        #pragma unroll 4
        for(int j=0;j<32;j++){
            float a0=Ps[rr][j], a1=Ps[rr+1][j];
            #pragma unroll
            for(int cc=0;cc<16;cc+=4){
                float4 v = *(const float4*)&Vs[j][c0+cc];
                acc[cc  ] += a0*v.x; acc[cc+1] += a0*v.y; acc[cc+2] += a0*v.z; acc[cc+3] += a0*v.w;
                acc[16+cc  ] += a1*v.x; acc[16+cc+1] += a1*v.y; acc[16+cc+2] += a1*v.z; acc[16+cc+3] += a1*v.w;
            }
        }
    }
    float* op = g_o + (size_t)(b*LL + i0)*1024 + h*128;
    #pragma unroll
    for(int m=0;m<2;m++)
        #pragma unroll
        for(int cc=0;cc<16;cc++)
            op[(size_t)(rr+m)*1024 + c0+cc] = acc[m*16+cc];
}

// ---------------- K6: o@fc + residual + attn LN -> tokens ---------------------
__global__ void k_attnout(const float* __restrict__ enc, const float* __restrict__ fc,
                          const float* __restrict__ lnw, const float* __restrict__ lnb){
    __shared__ float os[1024];
    __shared__ float part[4][64];
    __shared__ float vbuf[64];
    __shared__ float r1[64], r2[64];
    int b=blockIdx.y, l=blockIdx.x, tid=threadIdx.x;
    const float* op = g_o + (size_t)(b*LL+l)*1024;
    for(int i=tid;i<1024;i+=256) os[i]=op[i];
    __syncthreads();
    int c=tid&63, q=tid>>6;
    float acc=0.f;
    int m0=q*256;
    #pragma unroll 8
    for(int mm=0;mm<256;mm++) acc += os[m0+mm]*fc[(size_t)(m0+mm)*64+c];
    part[q][c]=acc;
    __syncthreads();
    if(tid<64){
        float v = part[0][tid]+part[1][tid]+part[2][tid]+part[3][tid]
                + enc[(size_t)(b*CC+tid)*LL + l];
        vbuf[tid]=v; r1[tid]=v; r2[tid]=v*v;
    }
    __syncthreads();
    for(int s=32;s>0;s>>=1){ if(tid<s){ r1[tid]+=r1[tid+s]; r2[tid]+=r2[tid+s]; } __syncthreads(); }
    if(tid<64){
        float mean=r1[0]*(1.f/64.f);
        float var =r2[0]*(1.f/64.f)-mean*mean;
        float v=vbuf[tid];
        g_tok[(size_t)(b*LL+l)*64+tid] = (v-mean)*rsqrtf(var+1e-5f)*lnw[tid]+lnb[tid];
    }
}

// ---------------- K7: tok @ ss_in_w -> x1pre (B,DN,L) & z (B,L,DN) -------------
__global__ void k_xz(const float* __restrict__ win){
    __shared__ float Xs[64][65];  // [c][l]
    __shared__ float Ws[64][65];  // [c][j]
    int b=blockIdx.z, j0=blockIdx.y*64, l0=blockIdx.x*64, tid=threadIdx.x;
    for(int i=tid;i<4096;i+=256){
        int ll=i>>6, c=i&63;
        Xs[c][ll] = g_tok[(size_t)(b*LL+l0+ll)*64 + c];
    }
    for(int i=tid;i<4096;i+=256){
        int c=i>>6, jj=i&63;
        Ws[c][jj] = win[(size_t)c*256 + j0 + jj];
    }
    __syncthreads();
    int rg=tid>>4, cg=tid&15; int r0=rg*4, c0=cg*4;
    float acc[4][4]={};
    #pragma unroll 8
    for(int c=0;c<64;c++){
        float a0=Xs[c][r0],a1=Xs[c][r0+1],a2=Xs[c][r0+2],a3=Xs[c][r0+3];
        float b0=Ws[c][c0],b1=Ws[c][c0+1],b2=Ws[c][c0+2],b3=Ws[c][c0+3];
        acc[0][0]+=a0*b0; acc[0][1]+=a0*b1; acc[0][2]+=a0*b2; acc[0][3]+=a0*b3;
        acc[1][0]+=a1*b0; acc[1][1]+=a1*b1; acc[1][2]+=a1*b2; acc[1][3]+=a1*b3;
        acc[2][0]+=a2*b0; acc[2][1]+=a2*b1; acc[2][2]+=a2*b2; acc[2][3]+=a2*b3;
        acc[3][0]+=a3*b0; acc[3][1]+=a3*b1; acc[3][2]+=a3*b2; acc[3][3]+=a3*b3;
    }
    #pragma unroll
    for(int m=0;m<4;m++){
        int l=l0+r0+m;
        #pragma unroll
        for(int n=0;n<4;n++){
            int j=j0+c0+n; float v=acc[m][n];
            if(j<128) g_x1pre[((size_t)b*128+j)*LL + l] = v;
            else      g_z[(size_t)(b*LL+l)*128 + (j-128)] = v;
        }
    }
}

// ---------------- K8: depthwise 3x3 + bias + silu ------------------------------
__global__ void k_dwconv(const float* __restrict__ wconv, const float* __restrict__ bias){
    __shared__ float pl[HHH*WWW];
    int b=blockIdx.y, d=blockIdx.x, tid=threadIdx.x;
    const float* ip = g_x1pre + (size_t)(b*DNN+d)*LL;
    for(int i=tid;i<LL;i+=256) pl[i]=ip[i];
    __syncthreads();
    float w[9];
    #pragma unroll
    for(int i=0;i<9;i++) w[i]=wconv[d*9+i];
    float bb = bias[d];
    float* op = g_x1 + (size_t)(b*DNN+d)*LL;
    for(int p=tid;p<LL;p+=256){
        int h=p/WWW, x=p%WWW;
        float s=bb;
        #pragma unroll
        for(int kh=0;kh<3;kh++){
            int ih=h+kh-1;
            if(ih<0||ih>=HHH) continue;
            #pragma unroll
            for(int kw=0;kw<3;kw++){
                int iw=x+kw-1;
                if(iw<0||iw>=WWW) continue;
                s += w[kh*3+kw]*pl[ih*WWW+iw];
            }
        }
        op[p] = silu_f(s);
    }
}

// ---------------- K9: x_dbl + dts/B/C extraction -------------------------------
__global__ void k_xdbl(const float* __restrict__ xproj, const float* __restrict__ dtw,
                       const float* __restrict__ dtb){
    __shared__ float xs_s[128][32];
    __shared__ float pj_s[36*128];
    __shared__ float xd_s[36][33];
    int b=blockIdx.z, k=blockIdx.y, l0=blockIdx.x*32;
    int bk=b*4+k, tid=threadIdx.x;
    for(int i=tid;i<36*128;i+=256) pj_s[i]=xproj[(size_t)k*36*128+i];
    const float* x1p = g_x1 + (size_t)b*128*LL;
    for(int i=tid;i<128*32;i+=256){
        int d=i>>5, ll=i&31;
        int lp=l0+ll, src;
        if(k==0) src=lp;
        else if(k==1) src=(lp%48)*48 + lp/48;
        else if(k==2) src=LL-1-lp;
        else { int t2=LL-1-lp; src=(t2%48)*48 + t2/48; }
        xs_s[d][ll]=x1p[(size_t)d*LL+src];
    }
    __syncthreads();
    {
        int ll=tid&31, g=tid>>5;
        for(int c=g;c<36;c+=8){
            float s=0.f;
            #pragma unroll 8
            for(int d=0;d<128;d++) s += pj_s[c*128+d]*xs_s[d][ll];
            xd_s[c][ll]=s;
        }
    }
    __syncthreads();
    {
        int ll=tid&31, g=tid>>5;
        float r0v=xd_s[0][ll],r1v=xd_s[1][ll],r2v=xd_s[2][ll],r3v=xd_s[3][ll];
        for(int i=0;i<16;i++){
            int d=g*16+i;
            const float* w=dtw+((size_t)k*128+d)*4;
            float dv=r0v*w[0]+r1v*w[1]+r2v*w[2]+r3v*w[3]+dtb[k*128+d];
            float sp=softplus_f(dv);
            size_t o=((size_t)bk*128+d)*LL + l0+ll;
            g_dt[o]=sp;
            g_u[o]=sp*xs_s[d][ll];
        }
    }
    for(int idx=tid;idx<32*16;idx+=256){
        int ll=idx>>4, n=idx&15;
        size_t o=((size_t)bk*LL + l0+ll)*16 + n;
        g_Bsc[o]=xd_s[4+n][ll];
        g_Csc[o]=xd_s[20+n][ll];
    }
}

// ---------------- K10: selective scan ------------------------------------------
// one 16-lane half-warp per (b,k,d) chain; lane n owns state n
__global__ void k_scan(const float* __restrict__ Alog){
    int lane=threadIdx.x;
    int half=lane>>4, n=lane&15;
    int ci = blockIdx.x*2 + half;    // 0..1023 == (b*4+k)*128 + d
    int bk = ci>>7, d = ci&127, k = bk&3;
    const float* dtp = g_dt + (size_t)ci*LL;
    const float* up  = g_u  + (size_t)ci*LL;
    const float* Bp  = g_Bsc + (size_t)bk*LL*16;
    const float* Cp  = g_Csc + (size_t)bk*LL*16;
    float* yp = g_ys + (size_t)ci*LL;
    float A = -__expf(Alog[((size_t)k*128+d)*16 + n]);
    float h = 0.f;
    #pragma unroll 4
    for(int l=0;l<LL;l++){
        float dt = dtp[l];
        float u  = up[l];
        float Bn = Bp[l*16+n];
        float Cn = Cp[l*16+n];
        float dA = __expf(dt*A);
        h = h*dA + u*Bn;
        float y = h*Cn;
        y += __shfl_xor_sync(0xffffffffu, y, 8);
        y += __shfl_xor_sync(0xffffffffu, y, 4);
        y += __shfl_xor_sync(0xffffffffu, y, 2);
        y += __shfl_xor_sync(0xffffffffu, y, 1);
        if(n==0) yp[l]=y;
    }
}

// ---------------- K11: direction merge + ss LN + gating + out proj + ffn LN ----
__global__ void k_combine(const float* __restrict__ enc, const float* __restrict__ snr,
                          const float* __restrict__ Dw,  const float* __restrict__ nw,
                          const float* __restrict__ nb,  const float* __restrict__ outw,
                          const float* __restrict__ fw,  const float* __restrict__ fb){
    __shared__ float yv[128];
    __shared__ float ra[128], rb[128];
    __shared__ float pbuf[128];
    __shared__ float x2s[64];
    __shared__ float rc[64], rd[64];
    int b=blockIdx.y, l=blockIdx.x, tid=threadIdx.x;  // 128 threads
    int hh=l/48, ww=l%48;
    int m = ww*48 + hh;
    int fl = LL-1-l, fm = LL-1-m;
    int d = tid;
    size_t base = (size_t)b*4*128*LL;
    float y = g_ys[base + ((size_t)(0*128+d))*LL + l]
            + g_ys[base + ((size_t)(2*128+d))*LL + fl]
            + g_ys[base + ((size_t)(1*128+d))*LL + m]
            + g_ys[base + ((size_t)(3*128+d))*LL + fm];
    float sD = Dw[0*128+d]+Dw[1*128+d]+Dw[2*128+d]+Dw[3*128+d];
    y += sD * g_x1[(size_t)(b*128+d)*LL + l];
    // LN over 128
    ra[tid]=y; rb[tid]=y*y; __syncthreads();
    for(int s=64;s>0;s>>=1){ if(tid<s){ ra[tid]+=ra[tid+s]; rb[tid]+=rb[tid+s]; } __syncthreads(); }
    float mean = ra[0]*(1.f/128.f);
    float var  = rb[0]*(1.f/128.f)-mean*mean;
    float ln = (y-mean)*rsqrtf(var+1e-5f)*nw[d]+nb[d];
    float z  = g_z[(size_t)(b*LL+l)*128+d];
    yv[d] = ln * silu_f(z) * snr[b*LL+l];
    __syncthreads();
    // out proj (128 -> 64), split reduction over halves of d
    int c=tid&63, hf=tid>>6;
    float acc=0.f;
    #pragma unroll 8
    for(int dd=hf*64; dd<hf*64+64; dd++) acc += yv[dd]*outw[(size_t)dd*64+c];
    pbuf[tid]=acc; __syncthreads();
    if(tid<64){
        float x2 = pbuf[tid]+pbuf[tid+64] + enc[(size_t)(b*CC+tid)*LL + l];
        x2s[tid]=x2;
        g_x2[(size_t)(b*LL+l)*64+tid]=x2;
        rc[tid]=x2; rd[tid]=x2*x2;
    }
    __syncthreads();
    for(int s=32;s>0;s>>=1){ if(tid<s){ rc[tid]+=rc[tid+s]; rd[tid]+=rd[tid+s]; } __syncthreads(); }
    if(tid<64){
        float mn=rc[0]*(1.f/64.f);
        float vr=rd[0]*(1.f/64.f)-mn*mn;
        g_xn[(size_t)(b*LL+l)*64+tid] = (x2s[tid]-mn)*rsqrtf(vr+1e-5f)*fw[tid]+fb[tid];
    }
}

// ---------------- K12: ffn1 = gelu(xn @ w1^T) -> (B,256,L) ---------------------
__global__ void k_ffn1(const float* __restrict__ w1){
    __shared__ float Xs[64][65];  // [c][l]
    __shared__ float Ws[64][65];  // [c][o]
    int b=blockIdx.z, o0=blockIdx.y*64, l0=blockIdx.x*64, tid=threadIdx.x;
    for(int i=tid;i<4096;i+=256){
        int ll=i>>6, c=i&63;
        Xs[c][ll]=g_xn[(size_t)(b*LL+l0+ll)*64+c];
    }
    for(int i=tid;i<4096;i+=256){
        int oo=i>>6, c=i&63;
        Ws[c][oo]=w1[(size_t)(o0+oo)*64+c];
    }
    __syncthreads();
    int rg=tid>>4, cg=tid&15; int r0=rg*4, c0=cg*4;
    float acc[4][4]={};
    #pragma unroll 8
    for(int c=0;c<64;c++){
        float a0=Xs[c][r0],a1=Xs[c][r0+1],a2=Xs[c][r0+2],a3=Xs[c][r0+3];
        float b0=Ws[c][c0],b1=Ws[c][c0+1],b2=Ws[c][c0+2],b3=Ws[c][c0+3];
        acc[0][0]+=a0*b0; acc[0][1]+=a0*b1; acc[0][2]+=a0*b2; acc[0][3]+=a0*b3;
        acc[1][0]+=a1*b0; acc[1][1]+=a1*b1; acc[1][2]+=a1*b2; acc[1][3]+=a1*b3;
        acc[2][0]+=a2*b0; acc[2][1]+=a2*b1; acc[2][2]+=a2*b2; acc[2][3]+=a2*b3;
        acc[3][0]+=a3*b0; acc[3][1]+=a3*b1; acc[3][2]+=a3*b2; acc[3][3]+=a3*b3;
    }
    #pragma unroll
    for(int m=0;m<4;m++)
        #pragma unroll
        for(int n=0;n<4;n++)
            g_h1[(size_t)(b*256+o0+c0+n)*LL + l0+r0+m] = gelu_f(acc[m][n]);
}

// ---------------- K13: depthwise 3x3 + gelu (256 ch) ---------------------------
__global__ void k_dwgelu(const float* __restrict__ wconv){
    __shared__ float pl[HHH*WWW];
    int b=blockIdx.y, d=blockIdx.x, tid=threadIdx.x;
    const float* ip = g_h1 + (size_t)(b*CM+d)*LL;
    for(int i=tid;i<LL;i+=256) pl[i]=ip[i];
    __syncthreads();
    float w[9];
    #pragma unroll
    for(int i=0;i<9;i++) w[i]=wconv[d*9+i];
    float* op = g_h2 + (size_t)(b*CM+d)*LL;
    for(int p=tid;p<LL;p+=256){
        int h=p/WWW, x=p%WWW;
        float s=0.f;
        #pragma unroll
        for(int kh=0;kh<3;kh++){
            int ih=h+kh-1;
            if(ih<0||ih>=HHH) continue;
            #pragma unroll
            for(int kw=0;kw<3;kw++){
                int iw=x+kw-1;
                if(iw<0||iw>=WWW) continue;
                s += w[kh*3+kw]*pl[ih*WWW+iw];
            }
        }
        op[p] = gelu_f(s);
    }
}

// ---------------- K14: ffn2 + residual + NCHW output ---------------------------
__global__ void k_ffn2(const float* __restrict__ w2, float* __restrict__ out){
    __shared__ float Hs[64][65];  // [m][l]
    __shared__ float Ws[64][65];  // [m][c]
    int b=blockIdx.y, l0=blockIdx.x*64, tid=threadIdx.x;
    int rg=tid>>4, cg=tid&15; int r0=rg*4, c0=cg*4;
    float acc[4][4]={};
    for(int m0=0;m0<256;m0+=64){
        __syncthreads();
        for(int i=tid;i<4096;i+=256){
            int mm=i>>6, ll=i&63;
            Hs[mm][ll]=g_h2[(size_t)(b*256+m0+mm)*LL + l0+ll];
        }
        for(int i=tid;i<4096;i+=256){
            int c=i>>6, mm=i&63;
            Ws[mm][c]=w2[(size_t)c*256 + m0+mm];
        }
        __syncthreads();
        #pragma unroll 8
        for(int mm=0;mm<64;mm++){
            float a0=Hs[mm][r0],a1=Hs[mm][r0+1],a2=Hs[mm][r0+2],a3=Hs[mm][r0+3];
            float b0=Ws[mm][c0],b1=Ws[mm][c0+1],b2=Ws[mm][c0+2],b3=Ws[mm][c0+3];
            acc[0][0]+=a0*b0; acc[0][1]+=a0*b1; acc[0][2]+=a0*b2; acc[0][3]+=a0*b3;
            acc[1][0]+=a1*b0; acc[1][1]+=a1*b1; acc[1][2]+=a1*b2; acc[1][3]+=a1*b3;
            acc[2][0]+=a2*b0; acc[2][1]+=a2*b1; acc[2][2]+=a2*b2; acc[2][3]+=a2*b3;
            acc[3][0]+=a3*b0; acc[3][1]+=a3*b1; acc[3][2]+=a3*b2; acc[3][3]+=a3*b3;
        }
    }
    #pragma unroll
    for(int m=0;m<4;m++){
        int l=l0+r0+m;
        #pragma unroll
        for(int n=0;n<4;n++){
            int c=c0+n;
            out[(size_t)(b*64+c)*LL + l] = acc[m][n] + g_x2[(size_t)(b*LL+l)*64+c];
        }
    }
}

// ---------------- launch --------------------------------------------------------
extern "C" void kernel_launch(void* const* d_in, const int* in_sizes, int n_in,
                              void* d_out, int out_size){
    (void)in_sizes; (void)n_in; (void)out_size;
    const float* enc       = (const float*)d_in[0];
    const float* snr       = (const float*)d_in[1];
    const float* attn_wq   = (const float*)d_in[2];
    const float* attn_wk   = (const float*)d_in[3];
    const float* attn_wv   = (const float*)d_in[4];
    const float* attn_fc   = (const float*)d_in[5];
    const float* attn_ln_w = (const float*)d_in[6];
    const float* attn_ln_b = (const float*)d_in[7];
    const float* ss_in_w   = (const float*)d_in[8];
    const float* ss_conv_w = (const float*)d_in[9];
    const float* ss_conv_b = (const float*)d_in[10];
    const float* ss_xproj  = (const float*)d_in[11];
    const float* ss_dt_w   = (const float*)d_in[12];
    const float* ss_dt_b   = (const float*)d_in[13];
    const float* ss_Alog   = (const float*)d_in[14];
    const float* ss_D      = (const float*)d_in[15];
    const float* ss_norm_w = (const float*)d_in[16];
    const float* ss_norm_b = (const float*)d_in[17];
    const float* ss_out_w  = (const float*)d_in[18];
    const float* ffn_ln_w  = (const float*)d_in[19];
    const float* ffn_ln_b  = (const float*)d_in[20];
    const float* ffn_w1    = (const float*)d_in[21];
    const float* ffn_dw    = (const float*)d_in[22];
    const float* ffn_w2    = (const float*)d_in[23];
    float* out = (float*)d_out;

    k_logsnr<<<(BB*LL+255)/256, 256>>>(snr);
    k_qkv   <<<dim3(LL/64, 32, BB), 256>>>(enc, attn_wq, attn_wk, attn_wv);
    k_scores<<<dim3(LL/64, LL/64, BHN), 256>>>();
    k_softmax<<<dim3(LL, BHN), 256>>>();
    k_pv    <<<dim3(LL/64, BHN), 256>>>();
    k_attnout<<<dim3(LL, BB), 256>>>(enc, attn_fc, attn_ln_w, attn_ln_b);
    k_xz    <<<dim3(LL/64, 4, BB), 256>>>(ss_in_w);
    k_dwconv<<<dim3(DNN, BB), 256>>>(ss_conv_w, ss_conv_b);
    k_xdbl  <<<dim3(LL/32, 4, BB), 256>>>(ss_xproj, ss_dt_w, ss_dt_b);
    k_scan  <<<BB*4*DNN/2, 32>>>(ss_Alog);
    k_combine<<<dim3(LL, BB), 128>>>(enc, snr, ss_D, ss_norm_w, ss_norm_b,
                                     ss_out_w, ffn_ln_w, ffn_ln_b);
    k_ffn1  <<<dim3(LL/64, CM/64, BB), 256>>>(ffn_w1);
    k_dwgelu<<<dim3(CM, BB), 256>>>(ffn_dw);
    k_ffn2  <<<dim3(LL/64, BB), 256>>>(ffn_w2, out);
}

// round 2
// speedup vs baseline: 2.3142x; 2.3142x over previous
#include <cuda_runtime.h>
#include <math.h>

#define BB 2
#define CC 64
#define HHH 48
#define WWW 48
#define LL 2304
#define NHH 8
#define DKK 64
#define DVV 128
#define DNN 128
#define NSS 16
#define CM 256
#define BHN (BB*NHH)

// ---------------- scratch (static device globals; no runtime alloc) ----------
__device__ float g_q[BHN*LL*DKK];
__device__ float g_k[BHN*LL*DKK];
__device__ float g_v[BHN*LL*DVV];
__device__ float g_logsnr[BB*LL];
__device__ float g_o[BB*LL*NHH*DVV];
__device__ float g_tok[BB*LL*CC];
__device__ float g_z[BB*LL*DNN];
__device__ float g_x1pre[BB*DNN*LL];
__device__ float g_x1[BB*DNN*LL];
__device__ float g_dt[BB*4*DNN*LL];
__device__ float g_u[BB*4*DNN*LL];
__device__ float g_Bsc[BB*4*LL*NSS];
__device__ float g_Csc[BB*4*LL*NSS];
__device__ float g_ys[BB*4*DNN*LL];
__device__ float g_x2[BB*LL*CC];
__device__ float g_xn[BB*LL*CC];
__device__ float g_h1[BB*CM*LL];
__device__ float g_h2[BB*CM*LL];

// ---------------- helpers ----------------------------------------------------
__device__ __forceinline__ float silu_f(float x){ return x/(1.f+__expf(-x)); }
__device__ __forceinline__ float gelu_f(float x){ return 0.5f*x*(1.f+erff(x*0.70710678118654752440f)); }
__device__ __forceinline__ float softplus_f(float x){ return fmaxf(x,0.f)+log1pf(__expf(-fabsf(x))); }

// ---------------- K1: log(snr+1e-4) ------------------------------------------
__global__ void k_logsnr(const float* __restrict__ snr){
    int i = blockIdx.x*256 + threadIdx.x;
    if(i < BB*LL) g_logsnr[i] = logf(snr[i] + 1e-4f);
}

// ---------------- K2: QKV projections ----------------------------------------
__global__ void k_qkv(const float* __restrict__ enc, const float* __restrict__ wq,
                      const float* __restrict__ wk, const float* __restrict__ wv){
    __shared__ float Xs[64][65];  // [c][l]
    __shared__ float Ws[64][65];  // [c][j]
    int b = blockIdx.z;
    int l0 = blockIdx.x*64;
    int t  = blockIdx.y;
    const float* wptr; int j0, wwid, which;
    if(t < 8){ wptr=wq; j0=t*64; wwid=512; which=0; }
    else if(t < 16){ wptr=wk; j0=(t-8)*64; wwid=512; which=1; }
    else { wptr=wv; j0=(t-16)*64; wwid=1024; which=2; }
    int tid = threadIdx.x;
    for(int i=tid;i<4096;i+=256){
        int c=i>>6, ll=i&63;
        Xs[c][ll] = enc[(size_t)(b*CC+c)*LL + l0 + ll];
    }
    for(int i=tid;i<4096;i+=256){
        int c=i>>6, jj=i&63;
        Ws[c][jj] = wptr[(size_t)c*wwid + j0 + jj];
    }
    __syncthreads();
    int rg=tid>>4, cg=tid&15; int r0=rg*4, c0=cg*4;
    float acc[4][4] = {};
    #pragma unroll 8
    for(int c=0;c<64;c++){
        float a0=Xs[c][r0],a1=Xs[c][r0+1],a2=Xs[c][r0+2],a3=Xs[c][r0+3];
        float b0=Ws[c][c0],b1=Ws[c][c0+1],b2=Ws[c][c0+2],b3=Ws[c][c0+3];
        acc[0][0]+=a0*b0; acc[0][1]+=a0*b1; acc[0][2]+=a0*b2; acc[0][3]+=a0*b3;
        acc[1][0]+=a1*b0; acc[1][1]+=a1*b1; acc[1][2]+=a1*b2; acc[1][3]+=a1*b3;
        acc[2][0]+=a2*b0; acc[2][1]+=a2*b1; acc[2][2]+=a2*b2; acc[2][3]+=a2*b3;
        acc[3][0]+=a3*b0; acc[3][1]+=a3*b1; acc[3][2]+=a3*b2; acc[3][3]+=a3*b3;
    }
    #pragma unroll
    for(int m=0;m<4;m++){
        int l = l0+r0+m;
        #pragma unroll
        for(int n=0;n<4;n++){
            int j = j0+c0+n;
            float v = acc[m][n];
            if(which==0){ int h=j>>6, dk=j&63; g_q[((size_t)(b*8+h)*LL+l)*64+dk]=v; }
            else if(which==1){ int h=j>>6, dk=j&63; g_k[((size_t)(b*8+h)*LL+l)*64+dk]=v; }
            else { int h=j>>7, dv=j&127; g_v[((size_t)(b*8+h)*LL+l)*128+dv]=v; }
        }
    }
}

// ---------------- K3: fused flash attention (scores+softmax+PV) ----------------
// i-tile 128 rows, j-tile 64 cols, 256 threads, online softmax.
__global__ void __launch_bounds__(256,1) k_flash(){
    extern __shared__ float sm[];
    float* Qt   = sm;                 // [64][132] transposed Q (k-major)
    float* Kt   = Qt + 64*132;        // [64][68]  transposed K
    float* Vs   = Kt + 64*68;         // [64][132] V direct
    float* Ss   = Vs + 64*132;        // [128][68] raw scores
    float* Pt   = Ss + 128*68;        // [64][132] transposed probs
    float* lssh = Pt + 64*132;        // [64] logsnr tile
    float* mrow = lssh + 64;          // [128]
    float* lrow = mrow + 128;         // [128]
    float* srow = lrow + 128;         // [128]

    int bh = blockIdx.y; int b = bh>>3, h = bh&7;
    int i0 = blockIdx.x*128;
    int tid = threadIdx.x;
    const float* qp = g_q + (size_t)bh*LL*64;
    const float* kp = g_k + (size_t)bh*LL*64;
    const float* vp = g_v + (size_t)bh*LL*128;

    // load Q tile transposed: Qt[k][r]
    for(int idx=tid*4; idx<128*64; idx+=1024){
        int r=idx>>6, k=idx&63;
        float4 v = *(const float4*)(qp + (size_t)(i0+r)*64 + k);
        Qt[(k  )*132 + r] = v.x;
        Qt[(k+1)*132 + r] = v.y;
        Qt[(k+2)*132 + r] = v.z;
        Qt[(k+3)*132 + r] = v.w;
    }
    if(tid<128){ mrow[tid] = -1e30f; lrow[tid] = 0.f; }

    float O[64];
    #pragma unroll
    for(int i=0;i<64;i++) O[i]=0.f;

    int rg=tid>>4, cg=tid&15;
    int r0=rg*8, c0=cg*4, c0v=cg*8;
    int rsm=tid>>1, half=tid&1;

    __syncthreads();

    for(int j0=0;j0<LL;j0+=64){
        // K tile transposed, V tile direct, logsnr tile
        for(int idx=tid*4; idx<64*64; idx+=1024){
            int r=idx>>6, k=idx&63;
            float4 v = *(const float4*)(kp + (size_t)(j0+r)*64 + k);
            Kt[(k  )*68 + r] = v.x;
            Kt[(k+1)*68 + r] = v.y;
            Kt[(k+2)*68 + r] = v.z;
            Kt[(k+3)*68 + r] = v.w;
        }
        for(int idx=tid*4; idx<64*128; idx+=1024){
            int r=idx>>7, c=idx&127;
            *(float4*)&Vs[r*132+c] = *(const float4*)(vp + (size_t)(j0+r)*128 + c);
        }
        if(tid<64) lssh[tid] = g_logsnr[b*LL + j0 + tid];
        __syncthreads();

        // --- S = Q K^T (8 rows x 4 cols per thread) ---
        float acc[8][4];
        #pragma unroll
        for(int i=0;i<8;i++){ acc[i][0]=0.f; acc[i][1]=0.f; acc[i][2]=0.f; acc[i][3]=0.f; }
        #pragma unroll 4
        for(int k=0;k<64;k++){
            float4 q0 = *(float4*)&Qt[k*132 + r0];
            float4 q1 = *(float4*)&Qt[k*132 + r0 + 4];
            float4 kv = *(float4*)&Kt[k*68 + c0];
            acc[0][0]+=q0.x*kv.x; acc[0][1]+=q0.x*kv.y; acc[0][2]+=q0.x*kv.z; acc[0][3]+=q0.x*kv.w;
            acc[1][0]+=q0.y*kv.x; acc[1][1]+=q0.y*kv.y; acc[1][2]+=q0.y*kv.z; acc[1][3]+=q0.y*kv.w;
            acc[2][0]+=q0.z*kv.x; acc[2][1]+=q0.z*kv.y; acc[2][2]+=q0.z*kv.z; acc[2][3]+=q0.z*kv.w;
            acc[3][0]+=q0.w*kv.x; acc[3][1]+=q0.w*kv.y; acc[3][2]+=q0.w*kv.z; acc[3][3]+=q0.w*kv.w;
            acc[4][0]+=q1.x*kv.x; acc[4][1]+=q1.x*kv.y; acc[4][2]+=q1.x*kv.z; acc[4][3]+=q1.x*kv.w;
            acc[5][0]+=q1.y*kv.x; acc[5][1]+=q1.y*kv.y; acc[5][2]+=q1.y*kv.z; acc[5][3]+=q1.y*kv.w;
            acc[6][0]+=q1.z*kv.x; acc[6][1]+=q1.z*kv.y; acc[6][2]+=q1.z*kv.z; acc[6][3]+=q1.z*kv.w;
            acc[7][0]+=q1.w*kv.x; acc[7][1]+=q1.w*kv.y; acc[7][2]+=q1.w*kv.z; acc[7][3]+=q1.w*kv.w;
        }
        #pragma unroll
        for(int i=0;i<8;i++){
            float4 w; w.x=acc[i][0]; w.y=acc[i][1]; w.z=acc[i][2]; w.w=acc[i][3];
            *(float4*)&Ss[(r0+i)*68 + c0] = w;
        }
        __syncthreads();

        // --- online softmax: 2 threads per row, 32 cols each ---
        {
            float mold = mrow[rsm];
            float tmax = -1e30f;
            int jb = half*32;
            #pragma unroll 8
            for(int jj=0;jj<32;jj++){
                float s = Ss[rsm*68 + jb + jj]*0.125f + lssh[jb+jj];
                tmax = fmaxf(tmax, s);
            }
            tmax = fmaxf(tmax, __shfl_xor_sync(0xffffffffu, tmax, 1));
            float mnew = fmaxf(mold, tmax);
            float sc = __expf(mold - mnew);
            float psum = 0.f;
            #pragma unroll 8
            for(int jj=0;jj<32;jj++){
                int j = jb + jj;
                float p = __expf(Ss[rsm*68 + j]*0.125f + lssh[j] - mnew);
                Pt[j*132 + rsm] = p;
                psum += p;
            }
            psum += __shfl_xor_sync(0xffffffffu, psum, 1);
            if(half==0){
                srow[rsm] = sc;
                mrow[rsm] = mnew;
                lrow[rsm] = lrow[rsm]*sc + psum;
            }
        }
        __syncthreads();

        // --- rescale O, accumulate P @ V (8 rows x 8 cols per thread) ---
        {
            float scl[8];
            #pragma unroll
            for(int i=0;i<8;i++) scl[i]=srow[r0+i];
            #pragma unroll
            for(int i=0;i<8;i++){
                #pragma unroll
                for(int c=0;c<8;c++) O[i*8+c] *= scl[i];
            }
            #pragma unroll 2
            for(int j=0;j<64;j++){
                float4 p0 = *(float4*)&Pt[j*132 + r0];
                float4 p1 = *(float4*)&Pt[j*132 + r0 + 4];
                float4 v0 = *(float4*)&Vs[j*132 + c0v];
                float4 v1 = *(float4*)&Vs[j*132 + c0v + 4];
                O[ 0]+=p0.x*v0.x; O[ 1]+=p0.x*v0.y; O[ 2]+=p0.x*v0.z; O[ 3]+=p0.x*v0.w;
                O[ 4]+=p0.x*v1.x; O[ 5]+=p0.x*v1.y; O[ 6]+=p0.x*v1.z; O[ 7]+=p0.x*v1.w;
                O[ 8]+=p0.y*v0.x; O[ 9]+=p0.y*v0.y; O[10]+=p0.y*v0.z; O[11]+=p0.y*v0.w;
                O[12]+=p0.y*v1.x; O[13]+=p0.y*v1.y; O[14]+=p0.y*v1.z; O[15]+=p0.y*v1.w;
                O[16]+=p0.z*v0.x; O[17]+=p0.z*v0.y; O[18]+=p0.z*v0.z; O[19]+=p0.z*v0.w;
                O[20]+=p0.z*v1.x; O[21]+=p0.z*v1.y; O[22]+=p0.z*v1.z; O[23]+=p0.z*v1.w;
                O[24]+=p0.w*v0.x; O[25]+=p0.w*v0.y; O[26]+=p0.w*v0.z; O[27]+=p0.w*v0.w;
                O[28]+=p0.w*v1.x; O[29]+=p0.w*v1.y; O[30]+=p0.w*v1.z; O[31]+=p0.w*v1.w;
                O[32]+=p1.x*v0.x; O[33]+=p1.x*v0.y; O[34]+=p1.x*v0.z; O[35]+=p1.x*v0.w;
                O[36]+=p1.x*v1.x; O[37]+=p1.x*v1.y; O[38]+=p1.x*v1.z; O[39]+=p1.x*v1.w;
                O[40]+=p1.y*v0.x; O[41]+=p1.y*v0.y; O[42]+=p1.y*v0.z; O[43]+=p1.y*v0.w;
                O[44]+=p1.y*v1.x; O[45]+=p1.y*v1.y; O[46]+=p1.y*v1.z; O[47]+=p1.y*v1.w;
                O[48]+=p1.z*v0.x; O[49]+=p1.z*v0.y; O[50]+=p1.z*v0.z; O[51]+=p1.z*v0.w;
                O[52]+=p1.z*v1.x; O[53]+=p1.z*v1.y; O[54]+=p1.z*v1.z; O[55]+=p1.z*v1.w;
                O[56]+=p1.w*v0.x; O[57]+=p1.w*v0.y; O[58]+=p1.w*v0.z; O[59]+=p1.w*v0.w;
                O[60]+=p1.w*v1.x; O[61]+=p1.w*v1.y; O[62]+=p1.w*v1.z; O[63]+=p1.w*v1.w;
            }
        }
        __syncthreads();
    }

    // finalize: divide by lsum, write out
    size_t ob = (size_t)(b*LL + i0 + r0)*1024 + h*128 + c0v;
    #pragma unroll
    for(int i=0;i<8;i++){
        float inv = 1.f/lrow[r0+i];
        float4 w0, w1;
        w0.x=O[i*8+0]*inv; w0.y=O[i*8+1]*inv; w0.z=O[i*8+2]*inv; w0.w=O[i*8+3]*inv;
        w1.x=O[i*8+4]*inv; w1.y=O[i*8+5]*inv; w1.z=O[i*8+6]*inv; w1.w=O[i*8+7]*inv;
        *(float4*)(g_o + ob + (size_t)i*1024)     = w0;
        *(float4*)(g_o + ob + (size_t)i*1024 + 4) = w1;
    }
}

// ---------------- K6: o@fc + residual + attn LN -> tokens ---------------------
__global__ void k_attnout(const float* __restrict__ enc, const float* __restrict__ fc,
                          const float* __restrict__ lnw, const float* __restrict__ lnb){
    __shared__ float os[1024];
    __shared__ float part[4][64];
    __shared__ float vbuf[64];
    __shared__ float r1[64], r2[64];
    int b=blockIdx.y, l=blockIdx.x, tid=threadIdx.x;
    const float* op = g_o + (size_t)(b*LL+l)*1024;
    for(int i=tid;i<1024;i+=256) os[i]=op[i];
    __syncthreads();
    int c=tid&63, q=tid>>6;
    float acc=0.f;
    int m0=q*256;
    #pragma unroll 8
    for(int mm=0;mm<256;mm++) acc += os[m0+mm]*fc[(size_t)(m0+mm)*64+c];
    part[q][c]=acc;
    __syncthreads();
    if(tid<64){
        float v = part[0][tid]+part[1][tid]+part[2][tid]+part[3][tid]
                + enc[(size_t)(b*CC+tid)*LL + l];
        vbuf[tid]=v; r1[tid]=v; r2[tid]=v*v;
    }
    __syncthreads();
    for(int s=32;s>0;s>>=1){ if(tid<s){ r1[tid]+=r1[tid+s]; r2[tid]+=r2[tid+s]; } __syncthreads(); }
    if(tid<64){
        float mean=r1[0]*(1.f/64.f);
        float var =r2[0]*(1.f/64.f)-mean*mean;
        float v=vbuf[tid];
        g_tok[(size_t)(b*LL+l)*64+tid] = (v-mean)*rsqrtf(var+1e-5f)*lnw[tid]+lnb[tid];
    }
}

// ---------------- K7: tok @ ss_in_w -> x1pre (B,DN,L) & z (B,L,DN) -------------
__global__ void k_xz(const float* __restrict__ win){
    __shared__ float Xs[64][65];
    __shared__ float Ws[64][65];
    int b=blockIdx.z, j0=blockIdx.y*64, l0=blockIdx.x*64, tid=threadIdx.x;
    for(int i=tid;i<4096;i+=256){
        int ll=i>>6, c=i&63;
        Xs[c][ll] = g_tok[(size_t)(b*LL+l0+ll)*64 + c];
    }
    for(int i=tid;i<4096;i+=256){
        int c=i>>6, jj=i&63;
        Ws[c][jj] = win[(size_t)c*256 + j0 + jj];
    }
    __syncthreads();
    int rg=tid>>4, cg=tid&15; int r0=rg*4, c0=cg*4;
    float acc[4][4]={};
    #pragma unroll 8
    for(int c=0;c<64;c++){
        float a0=Xs[c][r0],a1=Xs[c][r0+1],a2=Xs[c][r0+2],a3=Xs[c][r0+3];
        float b0=Ws[c][c0],b1=Ws[c][c0+1],b2=Ws[c][c0+2],b3=Ws[c][c0+3];
        acc[0][0]+=a0*b0; acc[0][1]+=a0*b1; acc[0][2]+=a0*b2; acc[0][3]+=a0*b3;
        acc[1][0]+=a1*b0; acc[1][1]+=a1*b1; acc[1][2]+=a1*b2; acc[1][3]+=a1*b3;
        acc[2][0]+=a2*b0; acc[2][1]+=a2*b1; acc[2][2]+=a2*b2; acc[2][3]+=a2*b3;
        acc[3][0]+=a3*b0; acc[3][1]+=a3*b1; acc[3][2]+=a3*b2; acc[3][3]+=a3*b3;
    }
    #pragma unroll
    for(int m=0;m<4;m++){
        int l=l0+r0+m;
        #pragma unroll
        for(int n=0;n<4;n++){
            int j=j0+c0+n; float v=acc[m][n];
            if(j<128) g_x1pre[((size_t)b*128+j)*LL + l] = v;
            else      g_z[(size_t)(b*LL+l)*128 + (j-128)] = v;
        }
    }
}

// ---------------- K8: depthwise 3x3 + bias + silu ------------------------------
__global__ void k_dwconv(const float* __restrict__ wconv, const float* __restrict__ bias){
    __shared__ float pl[HHH*WWW];
    int b=blockIdx.y, d=blockIdx.x, tid=threadIdx.x;
    const float* ip = g_x1pre + (size_t)(b*DNN+d)*LL;
    for(int i=tid;i<LL;i+=256) pl[i]=ip[i];
    __syncthreads();
    float w[9];
    #pragma unroll
    for(int i=0;i<9;i++) w[i]=wconv[d*9+i];
    float bb = bias[d];
    float* op = g_x1 + (size_t)(b*DNN+d)*LL;
    for(int p=tid;p<LL;p+=256){
        int h=p/WWW, x=p%WWW;
        float s=bb;
        #pragma unroll
        for(int kh=0;kh<3;kh++){
            int ih=h+kh-1;
            if(ih<0||ih>=HHH) continue;
            #pragma unroll
            for(int kw=0;kw<3;kw++){
                int iw=x+kw-1;
                if(iw<0||iw>=WWW) continue;
                s += w[kh*3+kw]*pl[ih*WWW+iw];
            }
        }
        op[p] = silu_f(s);
    }
}

// ---------------- K9: x_dbl + dts/B/C extraction -------------------------------
__global__ void k_xdbl(const float* __restrict__ xproj, const float* __restrict__ dtw,
                       const float* __restrict__ dtb){
    __shared__ float xs_s[128][32];
    __shared__ float pj_s[36*128];
    __shared__ float xd_s[36][33];
    int b=blockIdx.z, k=blockIdx.y, l0=blockIdx.x*32;
    int bk=b*4+k, tid=threadIdx.x;
    for(int i=tid;i<36*128;i+=256) pj_s[i]=xproj[(size_t)k*36*128+i];
    const float* x1p = g_x1 + (size_t)b*128*LL;
    for(int i=tid;i<128*32;i+=256){
        int d=i>>5, ll=i&31;
        int lp=l0+ll, src;
        if(k==0) src=lp;
        else if(k==1) src=(lp%48)*48 + lp/48;
        else if(k==2) src=LL-1-lp;
        else { int t2=LL-1-lp; src=(t2%48)*48 + t2/48; }
        xs_s[d][ll]=x1p[(size_t)d*LL+src];
    }
    __syncthreads();
    {
        int ll=tid&31, g=tid>>5;
        for(int c=g;c<36;c+=8){
            float s=0.f;
            #pragma unroll 8
            for(int d=0;d<128;d++) s += pj_s[c*128+d]*xs_s[d][ll];
            xd_s[c][ll]=s;
        }
    }
    __syncthreads();
    {
        int ll=tid&31, g=tid>>5;
        float r0v=xd_s[0][ll],r1v=xd_s[1][ll],r2v=xd_s[2][ll],r3v=xd_s[3][ll];
        for(int i=0;i<16;i++){
            int d=g*16+i;
            const float* w=dtw+((size_t)k*128+d)*4;
            float dv=r0v*w[0]+r1v*w[1]+r2v*w[2]+r3v*w[3]+dtb[k*128+d];
            float sp=softplus_f(dv);
            size_t o=((size_t)bk*128+d)*LL + l0+ll;
            g_dt[o]=sp;
            g_u[o]=sp*xs_s[d][ll];
        }
    }
    for(int idx=tid;idx<32*16;idx+=256){
        int ll=idx>>4, n=idx&15;
        size_t o=((size_t)bk*LL + l0+ll)*16 + n;
        g_Bsc[o]=xd_s[4+n][ll];
        g_Csc[o]=xd_s[20+n][ll];
    }
}

// ---------------- K10: selective scan ------------------------------------------
__global__ void k_scan(const float* __restrict__ Alog){
    int lane=threadIdx.x;
    int half=lane>>4, n=lane&15;
    int ci = blockIdx.x*2 + half;
    int bk = ci>>7, d = ci&127, k = bk&3;
    const float* dtp = g_dt + (size_t)ci*LL;
    const float* up  = g_u  + (size_t)ci*LL;
    const float* Bp  = g_Bsc + (size_t)bk*LL*16;
    const float* Cp  = g_Csc + (size_t)bk*LL*16;
    float* yp = g_ys + (size_t)ci*LL;
    float A = -__expf(Alog[((size_t)k*128+d)*16 + n]);
    float h = 0.f;
    #pragma unroll 4
    for(int l=0;l<LL;l++){
        float dt = dtp[l];
        float u  = up[l];
        float Bn = Bp[l*16+n];
        float Cn = Cp[l*16+n];
        float dA = __expf(dt*A);
        h = h*dA + u*Bn;
        float y = h*Cn;
        y += __shfl_xor_sync(0xffffffffu, y, 8);
        y += __shfl_xor_sync(0xffffffffu, y, 4);
        y += __shfl_xor_sync(0xffffffffu, y, 2);
        y += __shfl_xor_sync(0xffffffffu, y, 1);
        if(n==0) yp[l]=y;
    }
}

// ---------------- K11: direction merge + ss LN + gating + out proj + ffn LN ----
__global__ void k_combine(const float* __restrict__ enc, const float* __restrict__ snr,
                          const float* __restrict__ Dw,  const float* __restrict__ nw,
                          const float* __restrict__ nb,  const float* __restrict__ outw,
                          const float* __restrict__ fw,  const float* __restrict__ fb){
    __shared__ float yv[128];
    __shared__ float ra[128], rb[128];
    __shared__ float pbuf[128];
    __shared__ float x2s[64];
    __shared__ float rc[64], rd[64];
    int b=blockIdx.y, l=blockIdx.x, tid=threadIdx.x;
    int hh=l/48, ww=l%48;
    int m = ww*48 + hh;
    int fl = LL-1-l, fm = LL-1-m;
    int d = tid;
    size_t base = (size_t)b*4*128*LL;
    float y = g_ys[base + ((size_t)(0*128+d))*LL + l]
            + g_ys[base + ((size_t)(2*128+d))*LL + fl]
            + g_ys[base + ((size_t)(1*128+d))*LL + m]
            + g_ys[base + ((size_t)(3*128+d))*LL + fm];
    float sD = Dw[0*128+d]+Dw[1*128+d]+Dw[2*128+d]+Dw[3*128+d];
    y += sD * g_x1[(size_t)(b*128+d)*LL + l];
    ra[tid]=y; rb[tid]=y*y; __syncthreads();
    for(int s=64;s>0;s>>=1){ if(tid<s){ ra[tid]+=ra[tid+s]; rb[tid]+=rb[tid+s]; } __syncthreads(); }
    float mean = ra[0]*(1.f/128.f);
    float var  = rb[0]*(1.f/128.f)-mean*mean;
    float ln = (y-mean)*rsqrtf(var+1e-5f)*nw[d]+nb[d];
    float z  = g_z[(size_t)(b*LL+l)*128+d];
    yv[d] = ln * silu_f(z) * snr[b*LL+l];
    __syncthreads();
    int c=tid&63, hf=tid>>6;
    float acc=0.f;
    #pragma unroll 8
    for(int dd=hf*64; dd<hf*64+64; dd++) acc += yv[dd]*outw[(size_t)dd*64+c];
    pbuf[tid]=acc; __syncthreads();
    if(tid<64){
        float x2 = pbuf[tid]+pbuf[tid+64] + enc[(size_t)(b*CC+tid)*LL + l];
        x2s[tid]=x2;
        g_x2[(size_t)(b*LL+l)*64+tid]=x2;
        rc[tid]=x2; rd[tid]=x2*x2;
    }
    __syncthreads();
    for(int s=32;s>0;s>>=1){ if(tid<s){ rc[tid]+=rc[tid+s]; rd[tid]+=rd[tid+s]; } __syncthreads(); }
    if(tid<64){
        float mn=rc[0]*(1.f/64.f);
        float vr=rd[0]*(1.f/64.f)-mn*mn;
        g_xn[(size_t)(b*LL+l)*64+tid] = (x2s[tid]-mn)*rsqrtf(vr+1e-5f)*fw[tid]+fb[tid];
    }
}

// ---------------- K12: ffn1 = gelu(xn @ w1^T) -> (B,256,L) ---------------------
__global__ void k_ffn1(const float* __restrict__ w1){
    __shared__ float Xs[64][65];
    __shared__ float Ws[64][65];
    int b=blockIdx.z, o0=blockIdx.y*64, l0=blockIdx.x*64, tid=threadIdx.x;
    for(int i=tid;i<4096;i+=256){
        int ll=i>>6, c=i&63;
        Xs[c][ll]=g_xn[(size_t)(b*LL+l0+ll)*64+c];
    }
    for(int i=tid;i<4096;i+=256){
        int oo=i>>6, c=i&63;
        Ws[c][oo]=w1[(size_t)(o0+oo)*64+c];
    }
    __syncthreads();
    int rg=tid>>4, cg=tid&15; int r0=rg*4, c0=cg*4;
    float acc[4][4]={};
    #pragma unroll 8
    for(int c=0;c<64;c++){
        float a0=Xs[c][r0],a1=Xs[c][r0+1],a2=Xs[c][r0+2],a3=Xs[c][r0+3];
        float b0=Ws[c][c0],b1=Ws[c][c0+1],b2=Ws[c][c0+2],b3=Ws[c][c0+3];
        acc[0][0]+=a0*b0; acc[0][1]+=a0*b1; acc[0][2]+=a0*b2; acc[0][3]+=a0*b3;
        acc[1][0]+=a1*b0; acc[1][1]+=a1*b1; acc[1][2]+=a1*b2; acc[1][3]+=a1*b3;
        acc[2][0]+=a2*b0; acc[2][1]+=a2*b1; acc[2][2]+=a2*b2; acc[2][3]+=a2*b3;
        acc[3][0]+=a3*b0; acc[3][1]+=a3*b1; acc[3][2]+=a3*b2; acc[3][3]+=a3*b3;
    }
    #pragma unroll
    for(int m=0;m<4;m++)
        #pragma unroll
        for(int n=0;n<4;n++)
            g_h1[(size_t)(b*256+o0+c0+n)*LL + l0+r0+m] = gelu_f(acc[m][n]);
}

// ---------------- K13: depthwise 3x3 + gelu (256 ch) ---------------------------
__global__ void k_dwgelu(const float* __restrict__ wconv){
    __shared__ float pl[HHH*WWW];
    int b=blockIdx.y, d=blockIdx.x, tid=threadIdx.x;
    const float* ip = g_h1 + (size_t)(b*CM+d)*LL;
    for(int i=tid;i<LL;i+=256) pl[i]=ip[i];
    __syncthreads();
    float w[9];
    #pragma unroll
    for(int i=0;i<9;i++) w[i]=wconv[d*9+i];
    float* op = g_h2 + (size_t)(b*CM+d)*LL;
    for(int p=tid;p<LL;p+=256){
        int h=p/WWW, x=p%WWW;
        float s=0.f;
        #pragma unroll
        for(int kh=0;kh<3;kh++){
            int ih=h+kh-1;
            if(ih<0||ih>=HHH) continue;
            #pragma unroll
            for(int kw=0;kw<3;kw++){
                int iw=x+kw-1;
                if(iw<0||iw>=WWW) continue;
                s += w[kh*3+kw]*pl[ih*WWW+iw];
            }
        }
        op[p] = gelu_f(s);
    }
}

// ---------------- K14: ffn2 + residual + NCHW output ---------------------------
__global__ void k_ffn2(const float* __restrict__ w2, float* __restrict__ out){
    __shared__ float Hs[64][65];
    __shared__ float Ws[64][65];
    int b=blockIdx.y, l0=blockIdx.x*64, tid=threadIdx.x;
    int rg=tid>>4, cg=tid&15; int r0=rg*4, c0=cg*4;
    float acc[4][4]={};
    for(int m0=0;m0<256;m0+=64){
        __syncthreads();
        for(int i=tid;i<4096;i+=256){
            int mm=i>>6, ll=i&63;
            Hs[mm][ll]=g_h2[(size_t)(b*256+m0+mm)*LL + l0+ll];
        }
        for(int i=tid;i<4096;i+=256){
            int c=i>>6, mm=i&63;
            Ws[mm][c]=w2[(size_t)c*256 + m0+mm];
        }
        __syncthreads();
        #pragma unroll 8
        for(int mm=0;mm<64;mm++){
            float a0=Hs[mm][r0],a1=Hs[mm][r0+1],a2=Hs[mm][r0+2],a3=Hs[mm][r0+3];
            float b0=Ws[mm][c0],b1=Ws[mm][c0+1],b2=Ws[mm][c0+2],b3=Ws[mm][c0+3];
            acc[0][0]+=a0*b0; acc[0][1]+=a0*b1; acc[0][2]+=a0*b2; acc[0][3]+=a0*b3;
            acc[1][0]+=a1*b0; acc[1][1]+=a1*b1; acc[1][2]+=a1*b2; acc[1][3]+=a1*b3;
            acc[2][0]+=a2*b0; acc[2][1]+=a2*b1; acc[2][2]+=a2*b2; acc[2][3]+=a2*b3;
            acc[3][0]+=a3*b0; acc[3][1]+=a3*b1; acc[3][2]+=a3*b2; acc[3][3]+=a3*b3;
        }
    }
    #pragma unroll
    for(int m=0;m<4;m++){
        int l=l0+r0+m;
        #pragma unroll
        for(int n=0;n<4;n++){
            int c=c0+n;
            out[(size_t)(b*64+c)*LL + l] = acc[m][n] + g_x2[(size_t)(b*LL+l)*64+c];
        }
    }
}

// ---------------- launch --------------------------------------------------------
extern "C" void kernel_launch(void* const* d_in, const int* in_sizes, int n_in,
                              void* d_out, int out_size){
    (void)in_sizes; (void)n_in; (void)out_size;
    const float* enc       = (const float*)d_in[0];
    const float* snr       = (const float*)d_in[1];
    const float* attn_wq   = (const float*)d_in[2];
    const float* attn_wk   = (const float*)d_in[3];
    const float* attn_wv   = (const float*)d_in[4];
    const float* attn_fc   = (const float*)d_in[5];
    const float* attn_ln_w = (const float*)d_in[6];
    const float* attn_ln_b = (const float*)d_in[7];
    const float* ss_in_w   = (const float*)d_in[8];
    const float* ss_conv_w = (const float*)d_in[9];
    const float* ss_conv_b = (const float*)d_in[10];
    const float* ss_xproj  = (const float*)d_in[11];
    const float* ss_dt_w   = (const float*)d_in[12];
    const float* ss_dt_b   = (const float*)d_in[13];
    const float* ss_Alog   = (const float*)d_in[14];
    const float* ss_D      = (const float*)d_in[15];
    const float* ss_norm_w = (const float*)d_in[16];
    const float* ss_norm_b = (const float*)d_in[17];
    const float* ss_out_w  = (const float*)d_in[18];
    const float* ffn_ln_w  = (const float*)d_in[19];
    const float* ffn_ln_b  = (const float*)d_in[20];
    const float* ffn_w1    = (const float*)d_in[21];
    const float* ffn_dw    = (const float*)d_in[22];
    const float* ffn_w2    = (const float*)d_in[23];
    float* out = (float*)d_out;

    // dynamic smem for flash kernel (152 KB > 48 KB static limit)
    const int flash_smem = (64*132 + 64*68 + 64*132 + 128*68 + 64*132 + 64 + 3*128) * 4;
    cudaFuncSetAttribute(k_flash, cudaFuncAttributeMaxDynamicSharedMemorySize, flash_smem);

    k_logsnr<<<(BB*LL+255)/256, 256>>>(snr);
    k_qkv   <<<dim3(LL/64, 32, BB), 256>>>(enc, attn_wq, attn_wk, attn_wv);
    k_flash <<<dim3(LL/128, BHN), 256, flash_smem>>>();
    k_attnout<<<dim3(LL, BB), 256>>>(enc, attn_fc, attn_ln_w, attn_ln_b);
    k_xz    <<<dim3(LL/64, 4, BB), 256>>>(ss_in_w);
    k_dwconv<<<dim3(DNN, BB), 256>>>(ss_conv_w, ss_conv_b);
    k_xdbl  <<<dim3(LL/32, 4, BB), 256>>>(ss_xproj, ss_dt_w, ss_dt_b);
    k_scan  <<<BB*4*DNN/2, 32>>>(ss_Alog);
    k_combine<<<dim3(LL, BB), 128>>>(enc, snr, ss_D, ss_norm_w, ss_norm_b,
                                     ss_out_w, ffn_ln_w, ffn_ln_b);
    k_ffn1  <<<dim3(LL/64, CM/64, BB), 256>>>(ffn_w1);
    k_dwgelu<<<dim3(CM, BB), 256>>>(ffn_dw);
    k_ffn2  <<<dim3(LL/64, BB), 256>>>(ffn_w2, out);
}

// round 4
// speedup vs baseline: 2.3615x; 1.0204x over previous
#include <cuda_runtime.h>
#include <math.h>

#define BB 2
#define CC 64
#define HHH 48
#define WWW 48
#define LL 2304
#define NHH 8
#define DKK 64
#define DVV 128
#define DNN 128
#define NSS 16
#define CM 256
#define BHN (BB*NHH)

typedef unsigned long long u64;

// ---------------- packed fp32 helpers (Blackwell f32x2) ----------------------
__device__ __forceinline__ u64 pk2(float x, float y){
    u64 r; asm("mov.b64 %0, {%1,%2};" : "=l"(r) : "f"(x), "f"(y)); return r;
}
__device__ __forceinline__ u64 fma2(u64 a, u64 b, u64 c){
    u64 d; asm("fma.rn.f32x2 %0, %1, %2, %3;" : "=l"(d) : "l"(a), "l"(b), "l"(c)); return d;
}
__device__ __forceinline__ u64 mul2(u64 a, u64 b){
    u64 d; asm("mul.rn.f32x2 %0, %1, %2;" : "=l"(d) : "l"(a), "l"(b)); return d;
}
__device__ __forceinline__ float2 up2(u64 a){
    float2 f; asm("mov.b64 {%0,%1}, %2;" : "=f"(f.x), "=f"(f.y) : "l"(a)); return f;
}

// ---------------- scratch (static device globals; no runtime alloc) ----------
__device__ float g_q[BHN*LL*DKK];
__device__ float g_k[BHN*LL*DKK];
__device__ float g_v[BHN*LL*DVV];
__device__ float g_logsnr[BB*LL];
__device__ float g_o[BB*LL*NHH*DVV];
__device__ float g_tok[BB*LL*CC];
__device__ float g_z[BB*LL*DNN];
__device__ float g_x1pre[BB*DNN*LL];
__device__ float g_x1[BB*DNN*LL];
__device__ float g_dt[BB*4*DNN*LL];
__device__ float g_u[BB*4*DNN*LL];
__device__ float g_Bsc[BB*4*LL*NSS];
__device__ float g_Csc[BB*4*LL*NSS];
__device__ float g_ys[BB*4*DNN*LL];
__device__ float g_x2[BB*LL*CC];
__device__ float g_xn[BB*LL*CC];
__device__ float g_h1[BB*CM*LL];
__device__ float g_h2[BB*CM*LL];

// ---------------- helpers ----------------------------------------------------
__device__ __forceinline__ float silu_f(float x){ return x/(1.f+__expf(-x)); }
__device__ __forceinline__ float gelu_f(float x){ return 0.5f*x*(1.f+erff(x*0.70710678118654752440f)); }
__device__ __forceinline__ float softplus_f(float x){ return fmaxf(x,0.f)+log1pf(__expf(-fabsf(x))); }

// ---------------- K1: log(snr+1e-4) ------------------------------------------
__global__ void k_logsnr(const float* __restrict__ snr){
    int i = blockIdx.x*256 + threadIdx.x;
    if(i < BB*LL) g_logsnr[i] = logf(snr[i] + 1e-4f);
}

// ---------------- K2: QKV projections (f32x2 pair microkernel) ----------------
__global__ void k_qkv(const float* __restrict__ enc, const float* __restrict__ wq,
                      const float* __restrict__ wk, const float* __restrict__ wv){
    __shared__ float Xs[64][68];  // [c][l]
    __shared__ float Ws[64][68];  // [c][j]
    int b = blockIdx.z;
    int l0 = blockIdx.x*64;
    int t  = blockIdx.y;
    const float* wptr; int j0, wwid, which;
    if(t < 8){ wptr=wq; j0=t*64; wwid=512; which=0; }
    else if(t < 16){ wptr=wk; j0=(t-8)*64; wwid=512; which=1; }
    else { wptr=wv; j0=(t-16)*64; wwid=1024; which=2; }
    int tid = threadIdx.x;
    for(int i=tid;i<4096;i+=256){
        int c=i>>6, ll=i&63;
        Xs[c][ll] = enc[(size_t)(b*CC+c)*LL + l0 + ll];
    }
    for(int i=tid;i<4096;i+=256){
        int c=i>>6, jj=i&63;
        Ws[c][jj] = wptr[(size_t)c*wwid + j0 + jj];
    }
    __syncthreads();
    int rg=tid>>4, cg=tid&15; int r0=rg*4, c0=cg*4;
    u64 acc[2][4] = {};
    #pragma unroll 4
    for(int c=0;c<64;c++){
        u64 a0=*(const u64*)&Xs[c][r0], a1=*(const u64*)&Xs[c][r0+2];
        float4 bv=*(const float4*)&Ws[c][c0];
        u64 b0=pk2(bv.x,bv.x), b1=pk2(bv.y,bv.y), b2=pk2(bv.z,bv.z), b3=pk2(bv.w,bv.w);
        acc[0][0]=fma2(a0,b0,acc[0][0]); acc[0][1]=fma2(a0,b1,acc[0][1]);
        acc[0][2]=fma2(a0,b2,acc[0][2]); acc[0][3]=fma2(a0,b3,acc[0][3]);
        acc[1][0]=fma2(a1,b0,acc[1][0]); acc[1][1]=fma2(a1,b1,acc[1][1]);
        acc[1][2]=fma2(a1,b2,acc[1][2]); acc[1][3]=fma2(a1,b3,acc[1][3]);
    }
    #pragma unroll
    for(int p=0;p<2;p++){
        #pragma unroll
        for(int n=0;n<4;n++){
            float2 e = up2(acc[p][n]);
            int j = j0+c0+n;
            int la = l0+r0+2*p, lb = la+1;
            if(which==0){ int h=j>>6, dk=j&63;
                g_q[((size_t)(b*8+h)*LL+la)*64+dk]=e.x;
                g_q[((size_t)(b*8+h)*LL+lb)*64+dk]=e.y; }
            else if(which==1){ int h=j>>6, dk=j&63;
                g_k[((size_t)(b*8+h)*LL+la)*64+dk]=e.x;
                g_k[((size_t)(b*8+h)*LL+lb)*64+dk]=e.y; }
            else { int h=j>>7, dv=j&127;
                g_v[((size_t)(b*8+h)*LL+la)*128+dv]=e.x;
                g_v[((size_t)(b*8+h)*LL+lb)*128+dv]=e.y; }
        }
    }
}

// ---------------- K3: fused flash attention with f32x2 -------------------------
__global__ void __launch_bounds__(256,1) k_flash(){
    extern __shared__ float sm[];
    float* Qt   = sm;                 // [64][132] transposed Q (k-major)
    float* Kt   = Qt + 64*132;        // [64][68]  transposed K
    float* Vs   = Kt + 64*68;         // [64][132] V direct
    float* Ss   = Vs + 64*132;        // [128][68] raw scores
    float* Pt   = Ss + 128*68;        // [64][132] transposed probs
    float* lssh = Pt + 64*132;        // [64] logsnr tile
    float* mrow = lssh + 64;          // [128]
    float* lrow = mrow + 128;         // [128]
    float* srow = lrow + 128;         // [128]

    int bh = blockIdx.y; int b = bh>>3, h = bh&7;
    int i0 = blockIdx.x*128;
    int tid = threadIdx.x;
    const float* qp = g_q + (size_t)bh*LL*64;
    const float* kp = g_k + (size_t)bh*LL*64;
    const float* vp = g_v + (size_t)bh*LL*128;

    for(int idx=tid*4; idx<128*64; idx+=1024){
        int r=idx>>6, k=idx&63;
        float4 v = *(const float4*)(qp + (size_t)(i0+r)*64 + k);
        Qt[(k  )*132 + r] = v.x;
        Qt[(k+1)*132 + r] = v.y;
        Qt[(k+2)*132 + r] = v.z;
        Qt[(k+3)*132 + r] = v.w;
    }
    if(tid<128){ mrow[tid] = -1e30f; lrow[tid] = 0.f; }

    u64 Op[4][8];   // row-pairs (r0+2i, r0+2i+1) x 8 cols
    #pragma unroll
    for(int i=0;i<4;i++)
        #pragma unroll
        for(int c=0;c<8;c++) Op[i][c]=0ull;

    int rg=tid>>4, cg=tid&15;
    int r0=rg*8, c0=cg*4, c0v=cg*8;
    int rsm=tid>>1, half=tid&1;

    __syncthreads();

    for(int j0=0;j0<LL;j0+=64){
        for(int idx=tid*4; idx<64*64; idx+=1024){
            int r=idx>>6, k=idx&63;
            float4 v = *(const float4*)(kp + (size_t)(j0+r)*64 + k);
            Kt[(k  )*68 + r] = v.x;
            Kt[(k+1)*68 + r] = v.y;
            Kt[(k+2)*68 + r] = v.z;
            Kt[(k+3)*68 + r] = v.w;
        }
        for(int idx=tid*4; idx<64*128; idx+=1024){
            int r=idx>>7, c=idx&127;
            *(float4*)&Vs[r*132+c] = *(const float4*)(vp + (size_t)(j0+r)*128 + c);
        }
        if(tid<64) lssh[tid] = g_logsnr[b*LL + j0 + tid];
        __syncthreads();

        // --- S = Q K^T : 4 row-pairs x 4 cols in f32x2 ---
        {
            u64 accp[4][4];
            #pragma unroll
            for(int i=0;i<4;i++){ accp[i][0]=0ull; accp[i][1]=0ull; accp[i][2]=0ull; accp[i][3]=0ull; }
            #pragma unroll 4
            for(int k=0;k<64;k++){
                const float* qrow = &Qt[k*132 + r0];
                u64 qa0=*(const u64*)(qrow  );
                u64 qa1=*(const u64*)(qrow+2);
                u64 qa2=*(const u64*)(qrow+4);
                u64 qa3=*(const u64*)(qrow+6);
                float4 kv = *(const float4*)&Kt[k*68 + c0];
                u64 b0=pk2(kv.x,kv.x), b1=pk2(kv.y,kv.y), b2=pk2(kv.z,kv.z), b3=pk2(kv.w,kv.w);
                accp[0][0]=fma2(qa0,b0,accp[0][0]); accp[0][1]=fma2(qa0,b1,accp[0][1]);
                accp[0][2]=fma2(qa0,b2,accp[0][2]); accp[0][3]=fma2(qa0,b3,accp[0][3]);
                accp[1][0]=fma2(qa1,b0,accp[1][0]); accp[1][1]=fma2(qa1,b1,accp[1][1]);
                accp[1][2]=fma2(qa1,b2,accp[1][2]); accp[1][3]=fma2(qa1,b3,accp[1][3]);
                accp[2][0]=fma2(qa2,b0,accp[2][0]); accp[2][1]=fma2(qa2,b1,accp[2][1]);
                accp[2][2]=fma2(qa2,b2,accp[2][2]); accp[2][3]=fma2(qa2,b3,accp[2][3]);
                accp[3][0]=fma2(qa3,b0,accp[3][0]); accp[3][1]=fma2(qa3,b1,accp[3][1]);
                accp[3][2]=fma2(qa3,b2,accp[3][2]); accp[3][3]=fma2(qa3,b3,accp[3][3]);
            }
            #pragma unroll
            for(int i=0;i<4;i++){
                float2 e0=up2(accp[i][0]), e1=up2(accp[i][1]), e2=up2(accp[i][2]), e3=up2(accp[i][3]);
                float4 wA; wA.x=e0.x; wA.y=e1.x; wA.z=e2.x; wA.w=e3.x;
                float4 wB; wB.x=e0.y; wB.y=e1.y; wB.z=e2.y; wB.w=e3.y;
                *(float4*)&Ss[(r0+2*i  )*68 + c0] = wA;
                *(float4*)&Ss[(r0+2*i+1)*68 + c0] = wB;
            }
        }
        __syncthreads();

        // --- online softmax: 2 threads per row, 32 cols each ---
        {
            float mold = mrow[rsm];
            float tmax = -1e30f;
            int jb = half*32;
            #pragma unroll 8
            for(int jj=0;jj<32;jj++){
                float s = Ss[rsm*68 + jb + jj]*0.125f + lssh[jb+jj];
                tmax = fmaxf(tmax, s);
            }
            tmax = fmaxf(tmax, __shfl_xor_sync(0xffffffffu, tmax, 1));
            float mnew = fmaxf(mold, tmax);
            float sc = __expf(mold - mnew);
            float psum = 0.f;
            #pragma unroll 8
            for(int jj=0;jj<32;jj++){
                int j = jb + jj;
                float p = __expf(Ss[rsm*68 + j]*0.125f + lssh[j] - mnew);
                Pt[j*132 + rsm] = p;
                psum += p;
            }
            psum += __shfl_xor_sync(0xffffffffu, psum, 1);
            if(half==0){
                srow[rsm] = sc;
                mrow[rsm] = mnew;
                lrow[rsm] = lrow[rsm]*sc + psum;
            }
        }
        __syncthreads();

        // --- rescale O, accumulate P @ V in f32x2 ---
        {
            #pragma unroll
            for(int i=0;i<4;i++){
                u64 s2 = pk2(srow[r0+2*i], srow[r0+2*i+1]);
                #pragma unroll
                for(int c=0;c<8;c++) Op[i][c] = mul2(Op[i][c], s2);
            }
            #pragma unroll 2
            for(int j=0;j<64;j++){
                const float* pr = &Pt[j*132 + r0];
                u64 pa0=*(const u64*)(pr  );
                u64 pa1=*(const u64*)(pr+2);
                u64 pa2=*(const u64*)(pr+4);
                u64 pa3=*(const u64*)(pr+6);
                float4 v0 = *(const float4*)&Vs[j*132 + c0v];
                float4 v1 = *(const float4*)&Vs[j*132 + c0v + 4];
                u64 vb0=pk2(v0.x,v0.x), vb1=pk2(v0.y,v0.y), vb2=pk2(v0.z,v0.z), vb3=pk2(v0.w,v0.w);
                u64 vb4=pk2(v1.x,v1.x), vb5=pk2(v1.y,v1.y), vb6=pk2(v1.z,v1.z), vb7=pk2(v1.w,v1.w);
                Op[0][0]=fma2(pa0,vb0,Op[0][0]); Op[0][1]=fma2(pa0,vb1,Op[0][1]);
                Op[0][2]=fma2(pa0,vb2,Op[0][2]); Op[0][3]=fma2(pa0,vb3,Op[0][3]);
                Op[0][4]=fma2(pa0,vb4,Op[0][4]); Op[0][5]=fma2(pa0,vb5,Op[0][5]);
                Op[0][6]=fma2(pa0,vb6,Op[0][6]); Op[0][7]=fma2(pa0,vb7,Op[0][7]);
                Op[1][0]=fma2(pa1,vb0,Op[1][0]); Op[1][1]=fma2(pa1,vb1,Op[1][1]);
                Op[1][2]=fma2(pa1,vb2,Op[1][2]); Op[1][3]=fma2(pa1,vb3,Op[1][3]);
                Op[1][4]=fma2(pa1,vb4,Op[1][4]); Op[1][5]=fma2(pa1,vb5,Op[1][5]);
                Op[1][6]=fma2(pa1,vb6,Op[1][6]); Op[1][7]=fma2(pa1,vb7,Op[1][7]);
                Op[2][0]=fma2(pa2,vb0,Op[2][0]); Op[2][1]=fma2(pa2,vb1,Op[2][1]);
                Op[2][2]=fma2(pa2,vb2,Op[2][2]); Op[2][3]=fma2(pa2,vb3,Op[2][3]);
                Op[2][4]=fma2(pa2,vb4,Op[2][4]); Op[2][5]=fma2(pa2,vb5,Op[2][5]);
                Op[2][6]=fma2(pa2,vb6,Op[2][6]); Op[2][7]=fma2(pa2,vb7,Op[2][7]);
                Op[3][0]=fma2(pa3,vb0,Op[3][0]); Op[3][1]=fma2(pa3,vb1,Op[3][1]);
                Op[3][2]=fma2(pa3,vb2,Op[3][2]); Op[3][3]=fma2(pa3,vb3,Op[3][3]);
                Op[3][4]=fma2(pa3,vb4,Op[3][4]); Op[3][5]=fma2(pa3,vb5,Op[3][5]);
                Op[3][6]=fma2(pa3,vb6,Op[3][6]); Op[3][7]=fma2(pa3,vb7,Op[3][7]);
            }
        }
        __syncthreads();
    }

    // finalize: divide by lsum, write out
    #pragma unroll
    for(int i=0;i<4;i++){
        int ra = r0+2*i, rb = ra+1;
        float inva = 1.f/lrow[ra];
        float invb = 1.f/lrow[rb];
        float2 e[8];
        #pragma unroll
        for(int c=0;c<8;c++) e[c]=up2(Op[i][c]);
        float4 a0; a0.x=e[0].x*inva; a0.y=e[1].x*inva; a0.z=e[2].x*inva; a0.w=e[3].x*inva;
        float4 a1; a1.x=e[4].x*inva; a1.y=e[5].x*inva; a1.z=e[6].x*inva; a1.w=e[7].x*inva;
        float4 b0; b0.x=e[0].y*invb; b0.y=e[1].y*invb; b0.z=e[2].y*invb; b0.w=e[3].y*invb;
        float4 b1; b1.x=e[4].y*invb; b1.y=e[5].y*invb; b1.z=e[6].y*invb; b1.w=e[7].y*invb;
        size_t oa = (size_t)(b*LL + i0 + ra)*1024 + h*128 + c0v;
        size_t ob = (size_t)(b*LL + i0 + rb)*1024 + h*128 + c0v;
        *(float4*)(g_o + oa)     = a0;
        *(float4*)(g_o + oa + 4) = a1;
        *(float4*)(g_o + ob)     = b0;
        *(float4*)(g_o + ob + 4) = b1;
    }
}

// ---------------- K6: o@fc + residual + attn LN as tiled GEMM ------------------
__global__ void k_attnout(const float* __restrict__ enc, const float* __restrict__ fc,
                          const float* __restrict__ lnw, const float* __restrict__ lnb){
    __shared__ float Hs[64][68];  // [m][l], reused as Ts[l][c] after GEMM
    __shared__ float Ws[64][68];  // [m][c]
    int b=blockIdx.y, l0=blockIdx.x*64, tid=threadIdx.x;
    int rg=tid>>4, cg=tid&15; int r0=rg*4, c0=cg*4;
    u64 acc[2][4]={};
    for(int m0=0;m0<1024;m0+=64){
        __syncthreads();
        for(int i=tid;i<4096;i+=256){
            int mm=i&63, ll=i>>6;
            Hs[mm][ll]=g_o[(size_t)(b*LL+l0+ll)*1024 + m0+mm];
        }
        for(int i=tid;i<4096;i+=256){
            int c=i&63, mm=i>>6;
            Ws[mm][c]=fc[(size_t)(m0+mm)*64+c];
        }
        __syncthreads();
        #pragma unroll 4
        for(int mm=0;mm<64;mm++){
            u64 a0=*(const u64*)&Hs[mm][r0], a1=*(const u64*)&Hs[mm][r0+2];
            float4 bv=*(const float4*)&Ws[mm][c0];
            u64 b0=pk2(bv.x,bv.x), b1=pk2(bv.y,bv.y), b2=pk2(bv.z,bv.z), b3=pk2(bv.w,bv.w);
            acc[0][0]=fma2(a0,b0,acc[0][0]); acc[0][1]=fma2(a0,b1,acc[0][1]);
            acc[0][2]=fma2(a0,b2,acc[0][2]); acc[0][3]=fma2(a0,b3,acc[0][3]);
            acc[1][0]=fma2(a1,b0,acc[1][0]); acc[1][1]=fma2(a1,b1,acc[1][1]);
            acc[1][2]=fma2(a1,b2,acc[1][2]); acc[1][3]=fma2(a1,b3,acc[1][3]);
        }
    }
    __syncthreads();
    // residual + stash into Hs as Ts[l][c]
    #pragma unroll
    for(int p=0;p<2;p++){
        #pragma unroll
        for(int n=0;n<4;n++){
            float2 e = up2(acc[p][n]);
            int r = r0+2*p, c = c0+n;
            Hs[r  ][c] = e.x + enc[(size_t)(b*CC+c)*LL + l0+r];
            Hs[r+1][c] = e.y + enc[(size_t)(b*CC+c)*LL + l0+r+1];
        }
    }
    __syncthreads();
    // LN per row: 4 threads/row
    int row=tid>>2, qq=tid&3;
    float s1=0.f, s2=0.f;
    #pragma unroll
    for(int c=qq*16;c<qq*16+16;c++){ float v=Hs[row][c]; s1+=v; s2+=v*v; }
    s1 += __shfl_xor_sync(0xffffffffu, s1, 1);
    s2 += __shfl_xor_sync(0xffffffffu, s2, 1);
    s1 += __shfl_xor_sync(0xffffffffu, s1, 2);
    s2 += __shfl_xor_sync(0xffffffffu, s2, 2);
    float mean = s1*(1.f/64.f);
    float var  = s2*(1.f/64.f) - mean*mean;
    float iv = rsqrtf(var+1e-5f);
    #pragma unroll
    for(int c=qq*16;c<qq*16+16;c++){
        g_tok[(size_t)(b*LL+l0+row)*64+c] = (Hs[row][c]-mean)*iv*lnw[c]+lnb[c];
    }
}

// ---------------- K7: tok @ ss_in_w -> x1pre (B,DN,L) & z (B,L,DN) -------------
__global__ void k_xz(const float* __restrict__ win){
    __shared__ float Xs[64][68];
    __shared__ float Ws[64][68];
    int b=blockIdx.z, j0=blockIdx.y*64, l0=blockIdx.x*64, tid=threadIdx.x;
    for(int i=tid;i<4096;i+=256){
        int ll=i>>6, c=i&63;
        Xs[c][ll] = g_tok[(size_t)(b*LL+l0+ll)*64 + c];
    }
    for(int i=tid;i<4096;i+=256){
        int c=i>>6, jj=i&63;
        Ws[c][jj] = win[(size_t)c*256 + j0 + jj];
    }
    __syncthreads();
    int rg=tid>>4, cg=tid&15; int r0=rg*4, c0=cg*4;
    u64 acc[2][4]={};
    #pragma unroll 4
    for(int c=0;c<64;c++){
        u64 a0=*(const u64*)&Xs[c][r0], a1=*(const u64*)&Xs[c][r0+2];
        float4 bv=*(const float4*)&Ws[c][c0];
        u64 b0=pk2(bv.x,bv.x), b1=pk2(bv.y,bv.y), b2=pk2(bv.z,bv.z), b3=pk2(bv.w,bv.w);
        acc[0][0]=fma2(a0,b0,acc[0][0]); acc[0][1]=fma2(a0,b1,acc[0][1]);
        acc[0][2]=fma2(a0,b2,acc[0][2]); acc[0][3]=fma2(a0,b3,acc[0][3]);
        acc[1][0]=fma2(a1,b0,acc[1][0]); acc[1][1]=fma2(a1,b1,acc[1][1]);
        acc[1][2]=fma2(a1,b2,acc[1][2]); acc[1][3]=fma2(a1,b3,acc[1][3]);
    }
    #pragma unroll
    for(int p=0;p<2;p++){
        #pragma unroll
        for(int n=0;n<4;n++){
            float2 e = up2(acc[p][n]);
            int j=j0+c0+n;
            int la=l0+r0+2*p, lb=la+1;
            if(j<128){
                g_x1pre[((size_t)b*128+j)*LL + la] = e.x;
                g_x1pre[((size_t)b*128+j)*LL + lb] = e.y;
            } else {
                g_z[(size_t)(b*LL+la)*128 + (j-128)] = e.x;
                g_z[(size_t)(b*LL+lb)*128 + (j-128)] = e.y;
            }
        }
    }
}

// ---------------- K8: depthwise 3x3 + bias + silu ------------------------------
__global__ void k_dwconv(const float* __restrict__ wconv, const float* __restrict__ bias){
    __shared__ float pl[HHH*WWW];
    int b=blockIdx.y, d=blockIdx.x, tid=threadIdx.x;
    const float* ip = g_x1pre + (size_t)(b*DNN+d)*LL;
    for(int i=tid;i<LL;i+=256) pl[i]=ip[i];
    __syncthreads();
    float w[9];
    #pragma unroll
    for(int i=0;i<9;i++) w[i]=wconv[d*9+i];
    float bb = bias[d];
    float* op = g_x1 + (size_t)(b*DNN+d)*LL;
    for(int p=tid;p<LL;p+=256){
        int h=p/WWW, x=p%WWW;
        float s=bb;
        #pragma unroll
        for(int kh=0;kh<3;kh++){
            int ih=h+kh-1;
            if(ih<0||ih>=HHH) continue;
            #pragma unroll
            for(int kw=0;kw<3;kw++){
                int iw=x+kw-1;
                if(iw<0||iw>=WWW) continue;
                s += w[kh*3+kw]*pl[ih*WWW+iw];
            }
        }
        op[p] = silu_f(s);
    }
}

// ---------------- K9: x_dbl + dts/B/C extraction -------------------------------
__global__ void k_xdbl(const float* __restrict__ xproj, const float* __restrict__ dtw,
                       const float* __restrict__ dtb){
    __shared__ float xs_s[128][32];
    __shared__ float pj_s[36*128];
    __shared__ float xd_s[36][33];
    int b=blockIdx.z, k=blockIdx.y, l0=blockIdx.x*32;
    int bk=b*4+k, tid=threadIdx.x;
    for(int i=tid;i<36*128;i+=256) pj_s[i]=xproj[(size_t)k*36*128+i];
    const float* x1p = g_x1 + (size_t)b*128*LL;
    for(int i=tid;i<128*32;i+=256){
        int d=i>>5, ll=i&31;
        int lp=l0+ll, src;
        if(k==0) src=lp;
        else if(k==1) src=(lp%48)*48 + lp/48;
        else if(k==2) src=LL-1-lp;
        else { int t2=LL-1-lp; src=(t2%48)*48 + t2/48; }
        xs_s[d][ll]=x1p[(size_t)d*LL+src];
    }
    __syncthreads();
    {
        int ll=tid&31, g=tid>>5;
        for(int c=g;c<36;c+=8){
            float s=0.f;
            #pragma unroll 8
            for(int d=0;d<128;d++) s += pj_s[c*128+d]*xs_s[d][ll];
            xd_s[c][ll]=s;
        }
    }
    __syncthreads();
    {
        int ll=tid&31, g=tid>>5;
        float r0v=xd_s[0][ll],r1v=xd_s[1][ll],r2v=xd_s[2][ll],r3v=xd_s[3][ll];
        for(int i=0;i<16;i++){
            int d=g*16+i;
            const float* w=dtw+((size_t)k*128+d)*4;
            float dv=r0v*w[0]+r1v*w[1]+r2v*w[2]+r3v*w[3]+dtb[k*128+d];
            float sp=softplus_f(dv);
            size_t o=((size_t)bk*128+d)*LL + l0+ll;
            g_dt[o]=sp;
            g_u[o]=sp*xs_s[d][ll];
        }
    }
    for(int idx=tid;idx<32*16;idx+=256){
        int ll=idx>>4, n=idx&15;
        size_t o=((size_t)bk*LL + l0+ll)*16 + n;
        g_Bsc[o]=xd_s[4+n][ll];
        g_Csc[o]=xd_s[20+n][ll];
    }
}

// ---------------- K10: selective scan ------------------------------------------
__global__ void k_scan(const float* __restrict__ Alog){
    int lane=threadIdx.x;
    int half=lane>>4, n=lane&15;
    int ci = blockIdx.x*2 + half;
    int bk = ci>>7, d = ci&127, k = bk&3;
    const float* dtp = g_dt + (size_t)ci*LL;
    const float* up  = g_u  + (size_t)ci*LL;
    const float* Bp  = g_Bsc + (size_t)bk*LL*16;
    const float* Cp  = g_Csc + (size_t)bk*LL*16;
    float* yp = g_ys + (size_t)ci*LL;
    float A = -__expf(Alog[((size_t)k*128+d)*16 + n]);
    float h = 0.f;
    #pragma unroll 4
    for(int l=0;l<LL;l++){
        float dt = dtp[l];
        float u  = up[l];
        float Bn = Bp[l*16+n];
        float Cn = Cp[l*16+n];
        float dA = __expf(dt*A);
        h = h*dA + u*Bn;
        float y = h*Cn;
        y += __shfl_xor_sync(0xffffffffu, y, 8);
        y += __shfl_xor_sync(0xffffffffu, y, 4);
        y += __shfl_xor_sync(0xffffffffu, y, 2);
        y += __shfl_xor_sync(0xffffffffu, y, 1);
        if(n==0) yp[l]=y;
    }
}

// ---------------- K11: direction merge + ss LN + gating + out proj + ffn LN ----
__global__ void k_combine(const float* __restrict__ enc, const float* __restrict__ snr,
                          const float* __restrict__ Dw,  const float* __restrict__ nw,
                          const float* __restrict__ nb,  const float* __restrict__ outw,
                          const float* __restrict__ fw,  const float* __restrict__ fb){
    __shared__ float yv[128];
    __shared__ float ra[128], rb[128];
    __shared__ float pbuf[128];
    __shared__ float x2s[64];
    __shared__ float rc[64], rd[64];
    int b=blockIdx.y, l=blockIdx.x, tid=threadIdx.x;
    int hh=l/48, ww=l%48;
    int m = ww*48 + hh;
    int fl = LL-1-l, fm = LL-1-m;
    int d = tid;
    size_t base = (size_t)b*4*128*LL;
    float y = g_ys[base + ((size_t)(0*128+d))*LL + l]
            + g_ys[base + ((size_t)(2*128+d))*LL + fl]
            + g_ys[base + ((size_t)(1*128+d))*LL + m]
            + g_ys[base + ((size_t)(3*128+d))*LL + fm];
    float sD = Dw[0*128+d]+Dw[1*128+d]+Dw[2*128+d]+Dw[3*128+d];
    y += sD * g_x1[(size_t)(b*128+d)*LL + l];
    ra[tid]=y; rb[tid]=y*y; __syncthreads();
    for(int s=64;s>0;s>>=1){ if(tid<s){ ra[tid]+=ra[tid+s]; rb[tid]+=rb[tid+s]; } __syncthreads(); }
    float mean = ra[0]*(1.f/128.f);
    float var  = rb[0]*(1.f/128.f)-mean*mean;
    float ln = (y-mean)*rsqrtf(var+1e-5f)*nw[d]+nb[d];
    float z  = g_z[(size_t)(b*LL+l)*128+d];
    yv[d] = ln * silu_f(z) * snr[b*LL+l];
    __syncthreads();
    int c=tid&63, hf=tid>>6;
    float acc=0.f;
    #pragma unroll 8
    for(int dd=hf*64; dd<hf*64+64; dd++) acc += yv[dd]*outw[(size_t)dd*64+c];
    pbuf[tid]=acc; __syncthreads();
    if(tid<64){
        float x2 = pbuf[tid]+pbuf[tid+64] + enc[(size_t)(b*CC+tid)*LL + l];
        x2s[tid]=x2;
        g_x2[(size_t)(b*LL+l)*64+tid]=x2;
        rc[tid]=x2; rd[tid]=x2*x2;
    }
    __syncthreads();
    for(int s=32;s>0;s>>=1){ if(tid<s){ rc[tid]+=rc[tid+s]; rd[tid]+=rd[tid+s]; } __syncthreads(); }
    if(tid<64){
        float mn=rc[0]*(1.f/64.f);
        float vr=rd[0]*(1.f/64.f)-mn*mn;
        g_xn[(size_t)(b*LL+l)*64+tid] = (x2s[tid]-mn)*rsqrtf(vr+1e-5f)*fw[tid]+fb[tid];
    }
}

// ---------------- K12: ffn1 = gelu(xn @ w1^T) -> (B,256,L) ---------------------
__global__ void k_ffn1(const float* __restrict__ w1){
    __shared__ float Xs[64][68];
    __shared__ float Ws[64][68];
    int b=blockIdx.z, o0=blockIdx.y*64, l0=blockIdx.x*64, tid=threadIdx.x;
    for(int i=tid;i<4096;i+=256){
        int ll=i>>6, c=i&63;
        Xs[c][ll]=g_xn[(size_t)(b*LL+l0+ll)*64+c];
    }
    for(int i=tid;i<4096;i+=256){
        int oo=i>>6, c=i&63;
        Ws[c][oo]=w1[(size_t)(o0+oo)*64+c];
    }
    __syncthreads();
    int rg=tid>>4, cg=tid&15; int r0=rg*4, c0=cg*4;
    u64 acc[2][4]={};
    #pragma unroll 4
    for(int c=0;c<64;c++){
        u64 a0=*(const u64*)&Xs[c][r0], a1=*(const u64*)&Xs[c][r0+2];
        float4 bv=*(const float4*)&Ws[c][c0];
        u64 b0=pk2(bv.x,bv.x), b1=pk2(bv.y,bv.y), b2=pk2(bv.z,bv.z), b3=pk2(bv.w,bv.w);
        acc[0][0]=fma2(a0,b0,acc[0][0]); acc[0][1]=fma2(a0,b1,acc[0][1]);
        acc[0][2]=fma2(a0,b2,acc[0][2]); acc[0][3]=fma2(a0,b3,acc[0][3]);
        acc[1][0]=fma2(a1,b0,acc[1][0]); acc[1][1]=fma2(a1,b1,acc[1][1]);
        acc[1][2]=fma2(a1,b2,acc[1][2]); acc[1][3]=fma2(a1,b3,acc[1][3]);
    }
    #pragma unroll
    for(int p=0;p<2;p++){
        #pragma unroll
        for(int n=0;n<4;n++){
            float2 e = up2(acc[p][n]);
            int la=l0+r0+2*p;
            g_h1[(size_t)(b*256+o0+c0+n)*LL + la  ] = gelu_f(e.x);
            g_h1[(size_t)(b*256+o0+c0+n)*LL + la+1] = gelu_f(e.y);
        }
    }
}

// ---------------- K13: depthwise 3x3 + gelu (256 ch) ---------------------------
__global__ void k_dwgelu(const float* __restrict__ wconv){
    __shared__ float pl[HHH*WWW];
    int b=blockIdx.y, d=blockIdx.x, tid=threadIdx.x;
    const float* ip = g_h1 + (size_t)(b*CM+d)*LL;
    for(int i=tid;i<LL;i+=256) pl[i]=ip[i];
    __syncthreads();
    float w[9];
    #pragma unroll
    for(int i=0;i<9;i++) w[i]=wconv[d*9+i];
    float* op = g_h2 + (size_t)(b*CM+d)*LL;
    for(int p=tid;p<LL;p+=256){
        int h=p/WWW, x=p%WWW;
        float s=0.f;
        #pragma unroll
        for(int kh=0;kh<3;kh++){
            int ih=h+kh-1;
            if(ih<0||ih>=HHH) continue;
            #pragma unroll
            for(int kw=0;kw<3;kw++){
                int iw=x+kw-1;
                if(iw<0||iw>=WWW) continue;
                s += w[kh*3+kw]*pl[ih*WWW+iw];
            }
        }
        op[p] = gelu_f(s);
    }
}

// ---------------- K14: ffn2 + residual + NCHW output ---------------------------
__global__ void k_ffn2(const float* __restrict__ w2, float* __restrict__ out){
    __shared__ float Hs[64][68];
    __shared__ float Ws[64][68];
    int b=blockIdx.y, l0=blockIdx.x*64, tid=threadIdx.x;
    int rg=tid>>4, cg=tid&15; int r0=rg*4, c0=cg*4;
    u64 acc[2][4]={};
    for(int m0=0;m0<256;m0+=64){
        __syncthreads();
        for(int i=tid;i<4096;i+=256){
            int mm=i>>6, ll=i&63;
            Hs[mm][ll]=g_h2[(size_t)(b*256+m0+mm)*LL + l0+ll];
        }
        for(int i=tid;i<4096;i+=256){
            int c=i&63, mm=i>>6;
            Ws[mm][c]=w2[(size_t)c*256 + m0+mm];
        }
        __syncthreads();
        #pragma unroll 4
        for(int mm=0;mm<64;mm++){
            u64 a0=*(const u64*)&Hs[mm][r0], a1=*(const u64*)&Hs[mm][r0+2];
            float4 bv; bv.x=Ws[mm][c0]; bv.y=Ws[mm][c0+1]; bv.z=Ws[mm][c0+2]; bv.w=Ws[mm][c0+3];
            u64 b0=pk2(bv.x,bv.x), b1=pk2(bv.y,bv.y), b2=pk2(bv.z,bv.z), b3=pk2(bv.w,bv.w);
            acc[0][0]=fma2(a0,b0,acc[0][0]); acc[0][1]=fma2(a0,b1,acc[0][1]);
            acc[0][2]=fma2(a0,b2,acc[0][2]); acc[0][3]=fma2(a0,b3,acc[0][3]);
            acc[1][0]=fma2(a1,b0,acc[1][0]); acc[1][1]=fma2(a1,b1,acc[1][1]);
            acc[1][2]=fma2(a1,b2,acc[1][2]); acc[1][3]=fma2(a1,b3,acc[1][3]);
        }
    }
    #pragma unroll
    for(int p=0;p<2;p++){
        #pragma unroll
        for(int n=0;n<4;n++){
            float2 e = up2(acc[p][n]);
            int la=l0+r0+2*p, c=c0+n;
            out[(size_t)(b*64+c)*LL + la  ] = e.x + g_x2[(size_t)(b*LL+la  )*64+c];
            out[(size_t)(b*64+c)*LL + la+1] = e.y + g_x2[(size_t)(b*LL+la+1)*64+c];
        }
    }
}

// ---------------- launch --------------------------------------------------------
extern "C" void kernel_launch(void* const* d_in, const int* in_sizes, int n_in,
                              void* d_out, int out_size){
    (void)in_sizes; (void)n_in; (void)out_size;
    const float* enc       = (const float*)d_in[0];
    const float* snr       = (const float*)d_in[1];
    const float* attn_wq   = (const float*)d_in[2];
    const float* attn_wk   = (const float*)d_in[3];
    const float* attn_wv   = (const float*)d_in[4];
    const float* attn_fc   = (const float*)d_in[5];
    const float* attn_ln_w = (const float*)d_in[6];
    const float* attn_ln_b = (const float*)d_in[7];
    const float* ss_in_w   = (const float*)d_in[8];
    const float* ss_conv_w = (const float*)d_in[9];
    const float* ss_conv_b = (const float*)d_in[10];
    const float* ss_xproj  = (const float*)d_in[11];
    const float* ss_dt_w   = (const float*)d_in[12];
    const float* ss_dt_b   = (const float*)d_in[13];
    const float* ss_Alog   = (const float*)d_in[14];
    const float* ss_D      = (const float*)d_in[15];
    const float* ss_norm_w = (const float*)d_in[16];
    const float* ss_norm_b = (const float*)d_in[17];
    const float* ss_out_w  = (const float*)d_in[18];
    const float* ffn_ln_w  = (const float*)d_in[19];
    const float* ffn_ln_b  = (const float*)d_in[20];
    const float* ffn_w1    = (const float*)d_in[21];
    const float* ffn_dw    = (const float*)d_in[22];
    const float* ffn_w2    = (const float*)d_in[23];
    float* out = (float*)d_out;

    const int flash_smem = (64*132 + 64*68 + 64*132 + 128*68 + 64*132 + 64 + 3*128) * 4;
    cudaFuncSetAttribute(k_flash, cudaFuncAttributeMaxDynamicSharedMemorySize, flash_smem);

    k_logsnr<<<(BB*LL+255)/256, 256>>>(snr);
    k_qkv   <<<dim3(LL/64, 32, BB), 256>>>(enc, attn_wq, attn_wk, attn_wv);
    k_flash <<<dim3(LL/128, BHN), 256, flash_smem>>>();
    k_attnout<<<dim3(LL/64, BB), 256>>>(enc, attn_fc, attn_ln_w, attn_ln_b);
    k_xz    <<<dim3(LL/64, 4, BB), 256>>>(ss_in_w);
    k_dwconv<<<dim3(DNN, BB), 256>>>(ss_conv_w, ss_conv_b);
    k_xdbl  <<<dim3(LL/32, 4, BB), 256>>>(ss_xproj, ss_dt_w, ss_dt_b);
    k_scan  <<<BB*4*DNN/2, 32>>>(ss_Alog);
    k_combine<<<dim3(LL, BB), 128>>>(enc, snr, ss_D, ss_norm_w, ss_norm_b,
                                     ss_out_w, ffn_ln_w, ffn_ln_b);
    k_ffn1  <<<dim3(LL/64, CM/64, BB), 256>>>(ffn_w1);
    k_dwgelu<<<dim3(CM, BB), 256>>>(ffn_dw);
    k_ffn2  <<<dim3(LL/64, BB), 256>>>(ffn_w2, out);
}

// round 5
// speedup vs baseline: 3.3861x; 1.4339x over previous
#include <cuda_runtime.h>
#include <math.h>

#define BB 2
#define CC 64
#define HHH 48
#define WWW 48
#define LL 2304
#define NHH 8
#define DKK 64
#define DVV 128
#define DNN 128
#define NSS 16
#define CM 256
#define BHN (BB*NHH)

typedef unsigned long long u64;

// ---------------- packed fp32 helpers (Blackwell f32x2) ----------------------
__device__ __forceinline__ u64 pk2(float x, float y){
    u64 r; asm("mov.b64 %0, {%1,%2};" : "=l"(r) : "f"(x), "f"(y)); return r;
}
__device__ __forceinline__ u64 fma2(u64 a, u64 b, u64 c){
    u64 d; asm("fma.rn.f32x2 %0, %1, %2, %3;" : "=l"(d) : "l"(a), "l"(b), "l"(c)); return d;
}
__device__ __forceinline__ float2 up2(u64 a){
    float2 f; asm("mov.b64 {%0,%1}, %2;" : "=f"(f.x), "=f"(f.y) : "l"(a)); return f;
}

// ---------------- tf32 mma helpers -------------------------------------------
__device__ __forceinline__ float tf32r(float x){
    unsigned u; asm("cvt.rna.tf32.f32 %0, %1;" : "=r"(u) : "f"(x));
    return __uint_as_float(u);
}
__device__ __forceinline__ void mma_tf32(float& d0, float& d1, float& d2, float& d3,
    unsigned a0, unsigned a1, unsigned a2, unsigned a3, unsigned b0, unsigned b1){
    asm volatile("mma.sync.aligned.m16n8k8.row.col.f32.tf32.tf32.f32 "
        "{%0,%1,%2,%3}, {%4,%5,%6,%7}, {%8,%9}, {%0,%1,%2,%3};"
        : "+f"(d0), "+f"(d1), "+f"(d2), "+f"(d3)
        : "r"(a0), "r"(a1), "r"(a2), "r"(a3), "r"(b0), "r"(b1));
}

// ---------------- scratch (static device globals; no runtime alloc) ----------
__device__ float g_q[BHN*LL*DKK];
__device__ float g_k[BHN*LL*DKK];
__device__ float g_v[BHN*LL*DVV];
__device__ float g_logsnr[BB*LL];
__device__ float g_o[BB*LL*NHH*DVV];
__device__ float g_opart[4*BB*LL*CC];
__device__ float g_tok[BB*LL*CC];
__device__ float g_z[BB*LL*DNN];
__device__ float g_x1pre[BB*DNN*LL];
__device__ float g_x1[BB*DNN*LL];
__device__ float g_dt[BB*4*DNN*LL];
__device__ float g_u[BB*4*DNN*LL];
__device__ float g_Bsc[BB*4*LL*NSS];
__device__ float g_Csc[BB*4*LL*NSS];
__device__ float g_ys[BB*4*DNN*LL];
__device__ float g_x2[BB*LL*CC];
__device__ float g_xn[BB*LL*CC];
__device__ float g_h1[BB*CM*LL];
__device__ float g_h2[BB*CM*LL];

// ---------------- helpers ----------------------------------------------------
__device__ __forceinline__ float silu_f(float x){ return x/(1.f+__expf(-x)); }
__device__ __forceinline__ float gelu_f(float x){ return 0.5f*x*(1.f+erff(x*0.70710678118654752440f)); }
__device__ __forceinline__ float softplus_f(float x){ return fmaxf(x,0.f)+log1pf(__expf(-fabsf(x))); }

// ---------------- K1: log(snr+1e-4) ------------------------------------------
__global__ void k_logsnr(const float* __restrict__ snr){
    int i = blockIdx.x*256 + threadIdx.x;
    if(i < BB*LL) g_logsnr[i] = logf(snr[i] + 1e-4f);
}

// ---------------- K2: QKV projections (f32x2 pair microkernel) ----------------
__global__ void k_qkv(const float* __restrict__ enc, const float* __restrict__ wq,
                      const float* __restrict__ wk, const float* __restrict__ wv){
    __shared__ float Xs[64][68];  // [c][l]
    __shared__ float Ws[64][68];  // [c][j]
    int b = blockIdx.z;
    int l0 = blockIdx.x*64;
    int t  = blockIdx.y;
    const float* wptr; int j0, wwid, which;
    if(t < 8){ wptr=wq; j0=t*64; wwid=512; which=0; }
    else if(t < 16){ wptr=wk; j0=(t-8)*64; wwid=512; which=1; }
    else { wptr=wv; j0=(t-16)*64; wwid=1024; which=2; }
    int tid = threadIdx.x;
    for(int i=tid;i<4096;i+=256){
        int c=i>>6, ll=i&63;
        Xs[c][ll] = enc[(size_t)(b*CC+c)*LL + l0 + ll];
    }
    for(int i=tid;i<4096;i+=256){
        int c=i>>6, jj=i&63;
        Ws[c][jj] = wptr[(size_t)c*wwid + j0 + jj];
    }
    __syncthreads();
    int rg=tid>>4, cg=tid&15; int r0=rg*4, c0=cg*4;
    u64 acc[2][4] = {};
    #pragma unroll 4
    for(int c=0;c<64;c++){
        u64 a0=*(const u64*)&Xs[c][r0], a1=*(const u64*)&Xs[c][r0+2];
        float4 bv=*(const float4*)&Ws[c][c0];
        u64 b0=pk2(bv.x,bv.x), b1=pk2(bv.y,bv.y), b2=pk2(bv.z,bv.z), b3=pk2(bv.w,bv.w);
        acc[0][0]=fma2(a0,b0,acc[0][0]); acc[0][1]=fma2(a0,b1,acc[0][1]);
        acc[0][2]=fma2(a0,b2,acc[0][2]); acc[0][3]=fma2(a0,b3,acc[0][3]);
        acc[1][0]=fma2(a1,b0,acc[1][0]); acc[1][1]=fma2(a1,b1,acc[1][1]);
        acc[1][2]=fma2(a1,b2,acc[1][2]); acc[1][3]=fma2(a1,b3,acc[1][3]);
    }
    #pragma unroll
    for(int p=0;p<2;p++){
        #pragma unroll
        for(int n=0;n<4;n++){
            float2 e = up2(acc[p][n]);
            int j = j0+c0+n;
            int la = l0+r0+2*p, lb = la+1;
            if(which==0){ int h=j>>6, dk=j&63;
                g_q[((size_t)(b*8+h)*LL+la)*64+dk]=e.x;
                g_q[((size_t)(b*8+h)*LL+lb)*64+dk]=e.y; }
            else if(which==1){ int h=j>>6, dk=j&63;
                g_k[((size_t)(b*8+h)*LL+la)*64+dk]=e.x;
                g_k[((size_t)(b*8+h)*LL+lb)*64+dk]=e.y; }
            else { int h=j>>7, dv=j&127;
                g_v[((size_t)(b*8+h)*LL+la)*128+dv]=e.x;
                g_v[((size_t)(b*8+h)*LL+lb)*128+dv]=e.y; }
        }
    }
}

// ---------------- K3: flash attention via tf32 mma.sync ------------------------
// i-tile 128, j-tile 64. 256 threads = 8 warps; warp w owns rows [16w,16w+16).
// No running max: scores = qk/8 + log(snr+1e-4) are bounded (~[-9.3, 1]), so
// exp never overflows; accumulate unnormalized O + row-sums, divide at end.
__global__ void __launch_bounds__(256,1) k_flash(){
    extern __shared__ float sm[];
    float* Qs   = sm;             // [128][68] tf32-rounded, row-major [m][k]
    float* Ks   = Qs + 128*68;    // [64][68]  [n][k]
    float* Vs   = Ks + 64*68;     // [64][136] [j][dv]
    float* Ps   = Vs + 64*136;    // [128][68] probs [m][j]
    float* lssh = Ps + 128*68;    // [64]
    float* lrow = lssh + 64;      // [128] running sum of probs

    int bh = blockIdx.y; int b = bh>>3, h = bh&7;
    int i0 = blockIdx.x*128;
    int tid = threadIdx.x;
    int w = tid>>5, lane = tid&31;
    int qg = lane>>2, tg = lane&3;   // groupID (t/4), threadID-in-group (t%4)
    int m0 = w*16;
    const float* qp = g_q + (size_t)bh*LL*64;
    const float* kp = g_k + (size_t)bh*LL*64;
    const float* vp = g_v + (size_t)bh*LL*128;

    // load Q tile (tf32 rounding at staging)
    for(int idx=tid*4; idx<128*64; idx+=1024){
        int r=idx>>6, k=idx&63;
        float4 v = *(const float4*)(qp + (size_t)(i0+r)*64 + k);
        Qs[r*68+k  ]=tf32r(v.x); Qs[r*68+k+1]=tf32r(v.y);
        Qs[r*68+k+2]=tf32r(v.z); Qs[r*68+k+3]=tf32r(v.w);
    }
    if(tid<128) lrow[tid]=0.f;

    float O[16][4];  // 16 dv n-tiles × 4 d-regs
    #pragma unroll
    for(int i=0;i<16;i++){ O[i][0]=0.f; O[i][1]=0.f; O[i][2]=0.f; O[i][3]=0.f; }

    __syncthreads();

    // preload A(Q) fragments once: a[k-step][4]
    unsigned aq[8][4];
    #pragma unroll
    for(int ks=0;ks<8;ks++){
        int k0=ks*8;
        aq[ks][0]=__float_as_uint(Qs[(m0+qg  )*68 + k0+tg  ]);
        aq[ks][1]=__float_as_uint(Qs[(m0+8+qg)*68 + k0+tg  ]);
        aq[ks][2]=__float_as_uint(Qs[(m0+qg  )*68 + k0+4+tg]);
        aq[ks][3]=__float_as_uint(Qs[(m0+8+qg)*68 + k0+4+tg]);
    }

    for(int j0=0;j0<LL;j0+=64){
        // stage K, V, logsnr tiles (tf32)
        for(int idx=tid*4; idx<64*64; idx+=1024){
            int r=idx>>6, k=idx&63;
            float4 v = *(const float4*)(kp + (size_t)(j0+r)*64 + k);
            Ks[r*68+k  ]=tf32r(v.x); Ks[r*68+k+1]=tf32r(v.y);
            Ks[r*68+k+2]=tf32r(v.z); Ks[r*68+k+3]=tf32r(v.w);
        }
        for(int idx=tid*4; idx<64*128; idx+=1024){
            int r=idx>>7, c=idx&127;
            float4 v = *(const float4*)(vp + (size_t)(j0+r)*128 + c);
            Vs[r*136+c  ]=tf32r(v.x); Vs[r*136+c+1]=tf32r(v.y);
            Vs[r*136+c+2]=tf32r(v.z); Vs[r*136+c+3]=tf32r(v.w);
        }
        if(tid<64) lssh[tid]=g_logsnr[b*LL + j0 + tid];
        __syncthreads();

        // --- S = Q K^T, then P = exp(S/8 + logsnr) ---
        float psLo=0.f, psHi=0.f;
        #pragma unroll
        for(int nt=0;nt<8;nt++){
            int n0=nt*8;
            float d0=0.f,d1=0.f,d2=0.f,d3=0.f;
            #pragma unroll
            for(int ks=0;ks<8;ks++){
                int k0=ks*8;
                unsigned b0=__float_as_uint(Ks[(n0+qg)*68 + k0+tg  ]);
                unsigned b1=__float_as_uint(Ks[(n0+qg)*68 + k0+4+tg]);
                mma_tf32(d0,d1,d2,d3, aq[ks][0],aq[ks][1],aq[ks][2],aq[ks][3], b0,b1);
            }
            // d0: (row m0+qg, col n0+2tg), d1: col+1, d2/d3: row+8
            int c0=n0+2*tg;
            float ls0=lssh[c0], ls1=lssh[c0+1];
            float p0=__expf(d0*0.125f + ls0);
            float p1=__expf(d1*0.125f + ls1);
            float p2=__expf(d2*0.125f + ls0);
            float p3=__expf(d3*0.125f + ls1);
            psLo += p0+p1; psHi += p2+p3;
            float2 wlo; wlo.x=tf32r(p0); wlo.y=tf32r(p1);
            float2 whi; whi.x=tf32r(p2); whi.y=tf32r(p3);
            *(float2*)&Ps[(m0+qg  )*68 + c0] = wlo;
            *(float2*)&Ps[(m0+8+qg)*68 + c0] = whi;
        }
        psLo += __shfl_xor_sync(0xffffffffu, psLo, 1);
        psLo += __shfl_xor_sync(0xffffffffu, psLo, 2);
        psHi += __shfl_xor_sync(0xffffffffu, psHi, 1);
        psHi += __shfl_xor_sync(0xffffffffu, psHi, 2);
        if(tg==0){ lrow[m0+qg] += psLo; lrow[m0+8+qg] += psHi; }
        __syncthreads();

        // --- O += P @ V ---
        unsigned ap[8][4];
        #pragma unroll
        for(int ks=0;ks<8;ks++){
            int k0=ks*8;
            ap[ks][0]=__float_as_uint(Ps[(m0+qg  )*68 + k0+tg  ]);
            ap[ks][1]=__float_as_uint(Ps[(m0+8+qg)*68 + k0+tg  ]);
            ap[ks][2]=__float_as_uint(Ps[(m0+qg  )*68 + k0+4+tg]);
            ap[ks][3]=__float_as_uint(Ps[(m0+8+qg)*68 + k0+4+tg]);
        }
        #pragma unroll
        for(int nt=0;nt<16;nt++){
            int n0=nt*8;
            #pragma unroll
            for(int ks=0;ks<8;ks++){
                int k0=ks*8;
                unsigned b0=__float_as_uint(Vs[(k0+tg  )*136 + n0+qg]);
                unsigned b1=__float_as_uint(Vs[(k0+4+tg)*136 + n0+qg]);
                mma_tf32(O[nt][0],O[nt][1],O[nt][2],O[nt][3],
                         ap[ks][0],ap[ks][1],ap[ks][2],ap[ks][3], b0,b1);
            }
        }
        __syncthreads();
    }

    // epilogue: divide by row sums, write out
    float invLo = 1.f/lrow[m0+qg];
    float invHi = 1.f/lrow[m0+8+qg];
    size_t oa = (size_t)(b*LL + i0 + m0 + qg  )*1024 + h*128;
    size_t ob = (size_t)(b*LL + i0 + m0 + 8+qg)*1024 + h*128;
    #pragma unroll
    for(int nt=0;nt<16;nt++){
        int dv = nt*8 + 2*tg;
        float2 wa; wa.x=O[nt][0]*invLo; wa.y=O[nt][1]*invLo;
        float2 wb; wb.x=O[nt][2]*invHi; wb.y=O[nt][3]*invHi;
        *(float2*)(g_o + oa + dv) = wa;
        *(float2*)(g_o + ob + dv) = wb;
    }
}

// ---------------- K6a: o@fc split-K partial GEMM -------------------------------
__global__ void k_attnout_part(const float* __restrict__ fc){
    __shared__ float Hs[64][68];  // [m][l]
    __shared__ float Ws[64][68];  // [m][c]
    int b=blockIdx.z, ky=blockIdx.y, l0=blockIdx.x*64, tid=threadIdx.x;
    int rg=tid>>4, cg=tid&15; int r0=rg*4, c0=cg*4;
    u64 acc[2][4]={};
    for(int m0=ky*256; m0<ky*256+256; m0+=64){
        __syncthreads();
        for(int i=tid;i<4096;i+=256){
            int mm=i&63, ll=i>>6;
            Hs[mm][ll]=g_o[(size_t)(b*LL+l0+ll)*1024 + m0+mm];
        }
        for(int i=tid;i<4096;i+=256){
            int c=i&63, mm=i>>6;
            Ws[mm][c]=fc[(size_t)(m0+mm)*64+c];
        }
        __syncthreads();
        #pragma unroll 4
        for(int mm=0;mm<64;mm++){
            u64 a0=*(const u64*)&Hs[mm][r0], a1=*(const u64*)&Hs[mm][r0+2];
            float4 bv=*(const float4*)&Ws[mm][c0];
            u64 b0=pk2(bv.x,bv.x), b1=pk2(bv.y,bv.y), b2=pk2(bv.z,bv.z), b3=pk2(bv.w,bv.w);
            acc[0][0]=fma2(a0,b0,acc[0][0]); acc[0][1]=fma2(a0,b1,acc[0][1]);
            acc[0][2]=fma2(a0,b2,acc[0][2]); acc[0][3]=fma2(a0,b3,acc[0][3]);
            acc[1][0]=fma2(a1,b0,acc[1][0]); acc[1][1]=fma2(a1,b1,acc[1][1]);
            acc[1][2]=fma2(a1,b2,acc[1][2]); acc[1][3]=fma2(a1,b3,acc[1][3]);
        }
    }
    size_t pb = ((size_t)(ky*BB + b)*LL + l0)*64;
    #pragma unroll
    for(int p=0;p<2;p++){
        #pragma unroll
        for(int n=0;n<4;n++){
            float2 e = up2(acc[p][n]);
            int r = r0+2*p, c = c0+n;
            g_opart[pb + (size_t)r*64 + c]     = e.x;
            g_opart[pb + (size_t)(r+1)*64 + c] = e.y;
        }
    }
}

// ---------------- K6b: sum partials + residual + attn LN -----------------------
__global__ void k_attnout_fin(const float* __restrict__ enc, const float* __restrict__ lnw,
                              const float* __restrict__ lnb){
    __shared__ float Hs[64][68];
    int b=blockIdx.y, l0=blockIdx.x*64, tid=threadIdx.x;
    for(int i=tid;i<4096;i+=256){
        int l=i>>6, c=i&63;
        size_t off = ((size_t)(b)*LL + l0+l)*64 + c;
        size_t stp = (size_t)BB*LL*64;
        float s = g_opart[off] + g_opart[off+stp] + g_opart[off+2*stp] + g_opart[off+3*stp]
                + enc[(size_t)(b*CC+c)*LL + l0+l];
        Hs[l][c]=s;
    }
    __syncthreads();
    int row=tid>>2, qq=tid&3;
    float s1=0.f, s2=0.f;
    #pragma unroll
    for(int c=qq*16;c<qq*16+16;c++){ float v=Hs[row][c]; s1+=v; s2+=v*v; }
    s1 += __shfl_xor_sync(0xffffffffu, s1, 1);
    s2 += __shfl_xor_sync(0xffffffffu, s2, 1);
    s1 += __shfl_xor_sync(0xffffffffu, s1, 2);
    s2 += __shfl_xor_sync(0xffffffffu, s2, 2);
    float mean = s1*(1.f/64.f);
    float var  = s2*(1.f/64.f) - mean*mean;
    float iv = rsqrtf(var+1e-5f);
    #pragma unroll
    for(int c=qq*16;c<qq*16+16;c++){
        g_tok[(size_t)(b*LL+l0+row)*64+c] = (Hs[row][c]-mean)*iv*lnw[c]+lnb[c];
    }
}

// ---------------- K7: tok @ ss_in_w -> x1pre (B,DN,L) & z (B,L,DN) -------------
__global__ void k_xz(const float* __restrict__ win){
    __shared__ float Xs[64][68];
    __shared__ float Ws[64][68];
    int b=blockIdx.z, j0=blockIdx.y*64, l0=blockIdx.x*64, tid=threadIdx.x;
    for(int i=tid;i<4096;i+=256){
        int ll=i>>6, c=i&63;
        Xs[c][ll] = g_tok[(size_t)(b*LL+l0+ll)*64 + c];
    }
    for(int i=tid;i<4096;i+=256){
        int c=i>>6, jj=i&63;
        Ws[c][jj] = win[(size_t)c*256 + j0 + jj];
    }
    __syncthreads();
    int rg=tid>>4, cg=tid&15; int r0=rg*4, c0=cg*4;
    u64 acc[2][4]={};
    #pragma unroll 4
    for(int c=0;c<64;c++){
        u64 a0=*(const u64*)&Xs[c][r0], a1=*(const u64*)&Xs[c][r0+2];
        float4 bv=*(const float4*)&Ws[c][c0];
        u64 b0=pk2(bv.x,bv.x), b1=pk2(bv.y,bv.y), b2=pk2(bv.z,bv.z), b3=pk2(bv.w,bv.w);
        acc[0][0]=fma2(a0,b0,acc[0][0]); acc[0][1]=fma2(a0,b1,acc[0][1]);
        acc[0][2]=fma2(a0,b2,acc[0][2]); acc[0][3]=fma2(a0,b3,acc[0][3]);
        acc[1][0]=fma2(a1,b0,acc[1][0]); acc[1][1]=fma2(a1,b1,acc[1][1]);
        acc[1][2]=fma2(a1,b2,acc[1][2]); acc[1][3]=fma2(a1,b3,acc[1][3]);
    }
    #pragma unroll
    for(int p=0;p<2;p++){
        #pragma unroll
        for(int n=0;n<4;n++){
            float2 e = up2(acc[p][n]);
            int j=j0+c0+n;
            int la=l0+r0+2*p, lb=la+1;
            if(j<128){
                g_x1pre[((size_t)b*128+j)*LL + la] = e.x;
                g_x1pre[((size_t)b*128+j)*LL + lb] = e.y;
            } else {
                g_z[(size_t)(b*LL+la)*128 + (j-128)] = e.x;
                g_z[(size_t)(b*LL+lb)*128 + (j-128)] = e.y;
            }
        }
    }
}

// ---------------- K8: depthwise 3x3 + bias + silu ------------------------------
__global__ void k_dwconv(const float* __restrict__ wconv, const float* __restrict__ bias){
    __shared__ float pl[HHH*WWW];
    int b=blockIdx.y, d=blockIdx.x, tid=threadIdx.x;
    const float* ip = g_x1pre + (size_t)(b*DNN+d)*LL;
    for(int i=tid;i<LL;i+=256) pl[i]=ip[i];
    __syncthreads();
    float w[9];
    #pragma unroll
    for(int i=0;i<9;i++) w[i]=wconv[d*9+i];
    float bb = bias[d];
    float* op = g_x1 + (size_t)(b*DNN+d)*LL;
    for(int p=tid;p<LL;p+=256){
        int h=p/WWW, x=p%WWW;
        float s=bb;
        #pragma unroll
        for(int kh=0;kh<3;kh++){
            int ih=h+kh-1;
            if(ih<0||ih>=HHH) continue;
            #pragma unroll
            for(int kw=0;kw<3;kw++){
                int iw=x+kw-1;
                if(iw<0||iw>=WWW) continue;
                s += w[kh*3+kw]*pl[ih*WWW+iw];
            }
        }
        op[p] = silu_f(s);
    }
}

// ---------------- K9: x_dbl + dts/B/C extraction -------------------------------
__global__ void k_xdbl(const float* __restrict__ xproj, const float* __restrict__ dtw,
                       const float* __restrict__ dtb){
    __shared__ float xs_s[128][32];
    __shared__ float pj_s[36*128];
    __shared__ float xd_s[36][33];
    int b=blockIdx.z, k=blockIdx.y, l0=blockIdx.x*32;
    int bk=b*4+k, tid=threadIdx.x;
    for(int i=tid;i<36*128;i+=256) pj_s[i]=xproj[(size_t)k*36*128+i];
    const float* x1p = g_x1 + (size_t)b*128*LL;
    for(int i=tid;i<128*32;i+=256){
        int d=i>>5, ll=i&31;
        int lp=l0+ll, src;
        if(k==0) src=lp;
        else if(k==1) src=(lp%48)*48 + lp/48;
        else if(k==2) src=LL-1-lp;
        else { int t2=LL-1-lp; src=(t2%48)*48 + t2/48; }
        xs_s[d][ll]=x1p[(size_t)d*LL+src];
    }
    __syncthreads();
    {
        int ll=tid&31, g=tid>>5;
        for(int c=g;c<36;c+=8){
            float s=0.f;
            #pragma unroll 8
            for(int d=0;d<128;d++) s += pj_s[c*128+d]*xs_s[d][ll];
            xd_s[c][ll]=s;
        }
    }
    __syncthreads();
    {
        int ll=tid&31, g=tid>>5;
        float r0v=xd_s[0][ll],r1v=xd_s[1][ll],r2v=xd_s[2][ll],r3v=xd_s[3][ll];
        for(int i=0;i<16;i++){
            int d=g*16+i;
            const float* w=dtw+((size_t)k*128+d)*4;
            float dv=r0v*w[0]+r1v*w[1]+r2v*w[2]+r3v*w[3]+dtb[k*128+d];
            float sp=softplus_f(dv);
            size_t o=((size_t)bk*128+d)*LL + l0+ll;
            g_dt[o]=sp;
            g_u[o]=sp*xs_s[d][ll];
        }
    }
    for(int idx=tid;idx<32*16;idx+=256){
        int ll=idx>>4, n=idx&15;
        size_t o=((size_t)bk*LL + l0+ll)*16 + n;
        g_Bsc[o]=xd_s[4+n][ll];
        g_Csc[o]=xd_s[20+n][ll];
    }
}

// ---------------- K10: selective scan ------------------------------------------
__global__ void k_scan(const float* __restrict__ Alog){
    int lane=threadIdx.x;
    int half=lane>>4, n=lane&15;
    int ci = blockIdx.x*2 + half;
    int bk = ci>>7, d = ci&127, k = bk&3;
    const float* dtp = g_dt + (size_t)ci*LL;
    const float* up  = g_u  + (size_t)ci*LL;
    const float* Bp  = g_Bsc + (size_t)bk*LL*16;
    const float* Cp  = g_Csc + (size_t)bk*LL*16;
    float* yp = g_ys + (size_t)ci*LL;
    float A = -__expf(Alog[((size_t)k*128+d)*16 + n]);
    float h = 0.f;
    #pragma unroll 4
    for(int l=0;l<LL;l++){
        float dt = dtp[l];
        float u  = up[l];
        float Bn = Bp[l*16+n];
        float Cn = Cp[l*16+n];
        float dA = __expf(dt*A);
        h = h*dA + u*Bn;
        float y = h*Cn;
        y += __shfl_xor_sync(0xffffffffu, y, 8);
        y += __shfl_xor_sync(0xffffffffu, y, 4);
        y += __shfl_xor_sync(0xffffffffu, y, 2);
        y += __shfl_xor_sync(0xffffffffu, y, 1);
        if(n==0) yp[l]=y;
    }
}

// ---------------- K11: direction merge + ss LN + gating + out proj + ffn LN ----
__global__ void k_combine(const float* __restrict__ enc, const float* __restrict__ snr,
                          const float* __restrict__ Dw,  const float* __restrict__ nw,
                          const float* __restrict__ nb,  const float* __restrict__ outw,
                          const float* __restrict__ fw,  const float* __restrict__ fb){
    __shared__ float yv[128];
    __shared__ float ra[128], rb[128];
    __shared__ float pbuf[128];
    __shared__ float x2s[64];
    __shared__ float rc[64], rd[64];
    int b=blockIdx.y, l=blockIdx.x, tid=threadIdx.x;
    int hh=l/48, ww=l%48;
    int m = ww*48 + hh;
    int fl = LL-1-l, fm = LL-1-m;
    int d = tid;
    size_t base = (size_t)b*4*128*LL;
    float y = g_ys[base + ((size_t)(0*128+d))*LL + l]
            + g_ys[base + ((size_t)(2*128+d))*LL + fl]
            + g_ys[base + ((size_t)(1*128+d))*LL + m]
            + g_ys[base + ((size_t)(3*128+d))*LL + fm];
    float sD = Dw[0*128+d]+Dw[1*128+d]+Dw[2*128+d]+Dw[3*128+d];
    y += sD * g_x1[(size_t)(b*128+d)*LL + l];
    ra[tid]=y; rb[tid]=y*y; __syncthreads();
    for(int s=64;s>0;s>>=1){ if(tid<s){ ra[tid]+=ra[tid+s]; rb[tid]+=rb[tid+s]; } __syncthreads(); }
    float mean = ra[0]*(1.f/128.f);
    float var  = rb[0]*(1.f/128.f)-mean*mean;
    float ln = (y-mean)*rsqrtf(var+1e-5f)*nw[d]+nb[d];
    float z  = g_z[(size_t)(b*LL+l)*128+d];
    yv[d] = ln * silu_f(z) * snr[b*LL+l];
    __syncthreads();
    int c=tid&63, hf=tid>>6;
    float acc=0.f;
    #pragma unroll 8
    for(int dd=hf*64; dd<hf*64+64; dd++) acc += yv[dd]*outw[(size_t)dd*64+c];
    pbuf[tid]=acc; __syncthreads();
    if(tid<64){
        float x2 = pbuf[tid]+pbuf[tid+64] + enc[(size_t)(b*CC+tid)*LL + l];
        x2s[tid]=x2;
        g_x2[(size_t)(b*LL+l)*64+tid]=x2;
        rc[tid]=x2; rd[tid]=x2*x2;
    }
    __syncthreads();
    for(int s=32;s>0;s>>=1){ if(tid<s){ rc[tid]+=rc[tid+s]; rd[tid]+=rd[tid+s]; } __syncthreads(); }
    if(tid<64){
        float mn=rc[0]*(1.f/64.f);
        float vr=rd[0]*(1.f/64.f)-mn*mn;
        g_xn[(size_t)(b*LL+l)*64+tid] = (x2s[tid]-mn)*rsqrtf(vr+1e-5f)*fw[tid]+fb[tid];
    }
}

// ---------------- K12: ffn1 = gelu(xn @ w1^T) -> (B,256,L) ---------------------
__global__ void k_ffn1(const float* __restrict__ w1){
    __shared__ float Xs[64][68];
    __shared__ float Ws[64][68];
    int b=blockIdx.z, o0=blockIdx.y*64, l0=blockIdx.x*64, tid=threadIdx.x;
    for(int i=tid;i<4096;i+=256){
        int ll=i>>6, c=i&63;
        Xs[c][ll]=g_xn[(size_t)(b*LL+l0+ll)*64+c];
    }
    for(int i=tid;i<4096;i+=256){
        int oo=i>>6, c=i&63;
        Ws[c][oo]=w1[(size_t)(o0+oo)*64+c];
    }
    __syncthreads();
    int rg=tid>>4, cg=tid&15; int r0=rg*4, c0=cg*4;
    u64 acc[2][4]={};
    #pragma unroll 4
    for(int c=0;c<64;c++){
        u64 a0=*(const u64*)&Xs[c][r0], a1=*(const u64*)&Xs[c][r0+2];
        float4 bv=*(const float4*)&Ws[c][c0];
        u64 b0=pk2(bv.x,bv.x), b1=pk2(bv.y,bv.y), b2=pk2(bv.z,bv.z), b3=pk2(bv.w,bv.w);
        acc[0][0]=fma2(a0,b0,acc[0][0]); acc[0][1]=fma2(a0,b1,acc[0][1]);
        acc[0][2]=fma2(a0,b2,acc[0][2]); acc[0][3]=fma2(a0,b3,acc[0][3]);
        acc[1][0]=fma2(a1,b0,acc[1][0]); acc[1][1]=fma2(a1,b1,acc[1][1]);
        acc[1][2]=fma2(a1,b2,acc[1][2]); acc[1][3]=fma2(a1,b3,acc[1][3]);
    }
    #pragma unroll
    for(int p=0;p<2;p++){
        #pragma unroll
        for(int n=0;n<4;n++){
            float2 e = up2(acc[p][n]);
            int la=l0+r0+2*p;
            g_h1[(size_t)(b*256+o0+c0+n)*LL + la  ] = gelu_f(e.x);
            g_h1[(size_t)(b*256+o0+c0+n)*LL + la+1] = gelu_f(e.y);
        }
    }
}

// ---------------- K13: depthwise 3x3 + gelu (256 ch) ---------------------------
__global__ void k_dwgelu(const float* __restrict__ wconv){
    __shared__ float pl[HHH*WWW];
    int b=blockIdx.y, d=blockIdx.x, tid=threadIdx.x;
    const float* ip = g_h1 + (size_t)(b*CM+d)*LL;
    for(int i=tid;i<LL;i+=256) pl[i]=ip[i];
    __syncthreads();
    float w[9];
    #pragma unroll
    for(int i=0;i<9;i++) w[i]=wconv[d*9+i];
    float* op = g_h2 + (size_t)(b*CM+d)*LL;
    for(int p=tid;p<LL;p+=256){
        int h=p/WWW, x=p%WWW;
        float s=0.f;
        #pragma unroll
        for(int kh=0;kh<3;kh++){
            int ih=h+kh-1;
            if(ih<0||ih>=HHH) continue;
            #pragma unroll
            for(int kw=0;kw<3;kw++){
                int iw=x+kw-1;
                if(iw<0||iw>=WWW) continue;
                s += w[kh*3+kw]*pl[ih*WWW+iw];
            }
        }
        op[p] = gelu_f(s);
    }
}

// ---------------- K14: ffn2 + residual + NCHW output ---------------------------
__global__ void k_ffn2(const float* __restrict__ w2, float* __restrict__ out){
    __shared__ float Hs[64][68];
    __shared__ float Ws[64][68];
    int b=blockIdx.y, l0=blockIdx.x*64, tid=threadIdx.x;
    int rg=tid>>4, cg=tid&15; int r0=rg*4, c0=cg*4;
    u64 acc[2][4]={};
    for(int m0=0;m0<256;m0+=64){
        __syncthreads();
        for(int i=tid;i<4096;i+=256){
            int mm=i>>6, ll=i&63;
            Hs[mm][ll]=g_h2[(size_t)(b*256+m0+mm)*LL + l0+ll];
        }
        for(int i=tid;i<4096;i+=256){
            int c=i&63, mm=i>>6;
            Ws[mm][c]=w2[(size_t)c*256 + m0+mm];
        }
        __syncthreads();
        #pragma unroll 4
        for(int mm=0;mm<64;mm++){
            u64 a0=*(const u64*)&Hs[mm][r0], a1=*(const u64*)&Hs[mm][r0+2];
            float4 bv; bv.x=Ws[mm][c0]; bv.y=Ws[mm][c0+1]; bv.z=Ws[mm][c0+2]; bv.w=Ws[mm][c0+3];
            u64 b0=pk2(bv.x,bv.x), b1=pk2(bv.y,bv.y), b2=pk2(bv.z,bv.z), b3=pk2(bv.w,bv.w);
            acc[0][0]=fma2(a0,b0,acc[0][0]); acc[0][1]=fma2(a0,b1,acc[0][1]);
            acc[0][2]=fma2(a0,b2,acc[0][2]); acc[0][3]=fma2(a0,b3,acc[0][3]);
            acc[1][0]=fma2(a1,b0,acc[1][0]); acc[1][1]=fma2(a1,b1,acc[1][1]);
            acc[1][2]=fma2(a1,b2,acc[1][2]); acc[1][3]=fma2(a1,b3,acc[1][3]);
        }
    }
    #pragma unroll
    for(int p=0;p<2;p++){
        #pragma unroll
        for(int n=0;n<4;n++){
            float2 e = up2(acc[p][n]);
            int la=l0+r0+2*p, c=c0+n;
            out[(size_t)(b*64+c)*LL + la  ] = e.x + g_x2[(size_t)(b*LL+la  )*64+c];
            out[(size_t)(b*64+c)*LL + la+1] = e.y + g_x2[(size_t)(b*LL+la+1)*64+c];
        }
    }
}

// ---------------- launch --------------------------------------------------------
extern "C" void kernel_launch(void* const* d_in, const int* in_sizes, int n_in,
                              void* d_out, int out_size){
    (void)in_sizes; (void)n_in; (void)out_size;
    const float* enc       = (const float*)d_in[0];
    const float* snr       = (const float*)d_in[1];
    const float* attn_wq   = (const float*)d_in[2];
    const float* attn_wk   = (const float*)d_in[3];
    const float* attn_wv   = (const float*)d_in[4];
    const float* attn_fc   = (const float*)d_in[5];
    const float* attn_ln_w = (const float*)d_in[6];
    const float* attn_ln_b = (const float*)d_in[7];
    const float* ss_in_w   = (const float*)d_in[8];
    const float* ss_conv_w = (const float*)d_in[9];
    const float* ss_conv_b = (const float*)d_in[10];
    const float* ss_xproj  = (const float*)d_in[11];
    const float* ss_dt_w   = (const float*)d_in[12];
    const float* ss_dt_b   = (const float*)d_in[13];
    const float* ss_Alog   = (const float*)d_in[14];
    const float* ss_D      = (const float*)d_in[15];
    const float* ss_norm_w = (const float*)d_in[16];
    const float* ss_norm_b = (const float*)d_in[17];
    const float* ss_out_w  = (const float*)d_in[18];
    const float* ffn_ln_w  = (const float*)d_in[19];
    const float* ffn_ln_b  = (const float*)d_in[20];
    const float* ffn_w1    = (const float*)d_in[21];
    const float* ffn_dw    = (const float*)d_in[22];
    const float* ffn_w2    = (const float*)d_in[23];
    float* out = (float*)d_out;

    const int flash_smem = (128*68 + 64*68 + 64*136 + 128*68 + 64 + 128) * 4;
    cudaFuncSetAttribute(k_flash, cudaFuncAttributeMaxDynamicSharedMemorySize, flash_smem);

    k_logsnr<<<(BB*LL+255)/256, 256>>>(snr);
    k_qkv   <<<dim3(LL/64, 32, BB), 256>>>(enc, attn_wq, attn_wk, attn_wv);
    k_flash <<<dim3(LL/128, BHN), 256, flash_smem>>>();
    k_attnout_part<<<dim3(LL/64, 4, BB), 256>>>(attn_fc);
    k_attnout_fin <<<dim3(LL/64, BB), 256>>>(enc, attn_ln_w, attn_ln_b);
    k_xz    <<<dim3(LL/64, 4, BB), 256>>>(ss_in_w);
    k_dwconv<<<dim3(DNN, BB), 256>>>(ss_conv_w, ss_conv_b);
    k_xdbl  <<<dim3(LL/32, 4, BB), 256>>>(ss_xproj, ss_dt_w, ss_dt_b);
    k_scan  <<<BB*4*DNN/2, 32>>>(ss_Alog);
    k_combine<<<dim3(LL, BB), 128>>>(enc, snr, ss_D, ss_norm_w, ss_norm_b,
                                     ss_out_w, ffn_ln_w, ffn_ln_b);
    k_ffn1  <<<dim3(LL/64, CM/64, BB), 256>>>(ffn_w1);
    k_dwgelu<<<dim3(CM, BB), 256>>>(ffn_dw);
    k_ffn2  <<<dim3(LL/64, BB), 256>>>(ffn_w2, out);
}

// round 6
// speedup vs baseline: 3.9487x; 1.1662x over previous
#include <cuda_runtime.h>
#include <cuda_bf16.h>
#include <math.h>

#define BB 2
#define CC 64
#define HHH 48
#define WWW 48
#define LL 2304
#define NHH 8
#define DKK 64
#define DVV 128
#define DNN 128
#define NSS 16
#define CM 256
#define BHN (BB*NHH)

typedef unsigned long long u64;

// ---------------- packed fp32 helpers (Blackwell f32x2) ----------------------
__device__ __forceinline__ u64 pk2(float x, float y){
    u64 r; asm("mov.b64 %0, {%1,%2};" : "=l"(r) : "f"(x), "f"(y)); return r;
}
__device__ __forceinline__ u64 fma2(u64 a, u64 b, u64 c){
    u64 d; asm("fma.rn.f32x2 %0, %1, %2, %3;" : "=l"(d) : "l"(a), "l"(b), "l"(c)); return d;
}
__device__ __forceinline__ float2 up2(u64 a){
    float2 f; asm("mov.b64 {%0,%1}, %2;" : "=f"(f.x), "=f"(f.y) : "l"(a)); return f;
}

// ---------------- bf16 mma helpers -------------------------------------------
// pack two fp32 into bf16x2: lo half = first arg, hi half = second
__device__ __forceinline__ unsigned pkbf(float lo, float hi){
    unsigned r; asm("cvt.rn.bf16x2.f32 %0, %1, %2;" : "=r"(r) : "f"(hi), "f"(lo)); return r;
}
__device__ __forceinline__ void ldsm_x2(unsigned& r0, unsigned& r1, unsigned addr){
    asm volatile("ldmatrix.sync.aligned.m8n8.x2.shared.b16 {%0,%1}, [%2];"
        : "=r"(r0), "=r"(r1) : "r"(addr));
}
__device__ __forceinline__ void ldsm_x2t(unsigned& r0, unsigned& r1, unsigned addr){
    asm volatile("ldmatrix.sync.aligned.m8n8.x2.trans.shared.b16 {%0,%1}, [%2];"
        : "=r"(r0), "=r"(r1) : "r"(addr));
}
__device__ __forceinline__ void ldsm_x4(unsigned* r, unsigned addr){
    asm volatile("ldmatrix.sync.aligned.m8n8.x4.shared.b16 {%0,%1,%2,%3}, [%4];"
        : "=r"(r[0]), "=r"(r[1]), "=r"(r[2]), "=r"(r[3]) : "r"(addr));
}
__device__ __forceinline__ void mma_bf16(float& d0, float& d1, float& d2, float& d3,
    unsigned a0, unsigned a1, unsigned a2, unsigned a3, unsigned b0, unsigned b1){
    asm volatile("mma.sync.aligned.m16n8k16.row.col.f32.bf16.bf16.f32 "
        "{%0,%1,%2,%3}, {%4,%5,%6,%7}, {%8,%9}, {%0,%1,%2,%3};"
        : "+f"(d0), "+f"(d1), "+f"(d2), "+f"(d3)
        : "r"(a0), "r"(a1), "r"(a2), "r"(a3), "r"(b0), "r"(b1));
}

// ---------------- scratch (static device globals; no runtime alloc) ----------
__device__ float g_q[BHN*LL*DKK];
__device__ float g_k[BHN*LL*DKK];
__device__ float g_v[BHN*LL*DVV];
__device__ float g_logsnr[BB*LL];
__device__ float g_o[BB*LL*NHH*DVV];
__device__ float g_opart[4*BB*LL*CC];
__device__ float g_tok[BB*LL*CC];
__device__ float g_z[BB*LL*DNN];
__device__ float g_x1pre[BB*DNN*LL];
__device__ float g_x1[BB*DNN*LL];
__device__ float g_dt[BB*4*DNN*LL];
__device__ float g_u[BB*4*DNN*LL];
__device__ float g_Bsc[BB*4*LL*NSS];
__device__ float g_Csc[BB*4*LL*NSS];
__device__ float g_ys[BB*4*DNN*LL];
__device__ float g_x2[BB*LL*CC];
__device__ float g_xn[BB*LL*CC];
__device__ float g_h1[BB*CM*LL];
__device__ float g_h2[BB*CM*LL];

// ---------------- helpers ----------------------------------------------------
__device__ __forceinline__ float silu_f(float x){ return x/(1.f+__expf(-x)); }
__device__ __forceinline__ float gelu_f(float x){ return 0.5f*x*(1.f+erff(x*0.70710678118654752440f)); }
__device__ __forceinline__ float softplus_f(float x){ return fmaxf(x,0.f)+log1pf(__expf(-fabsf(x))); }

// ---------------- K1: log(snr+1e-4) ------------------------------------------
__global__ void k_logsnr(const float* __restrict__ snr){
    int i = blockIdx.x*256 + threadIdx.x;
    if(i < BB*LL) g_logsnr[i] = logf(snr[i] + 1e-4f);
}

// ---------------- K2: QKV projections (f32x2 pair microkernel) ----------------
__global__ void k_qkv(const float* __restrict__ enc, const float* __restrict__ wq,
                      const float* __restrict__ wk, const float* __restrict__ wv){
    __shared__ float Xs[64][68];  // [c][l]
    __shared__ float Ws[64][68];  // [c][j]
    int b = blockIdx.z;
    int l0 = blockIdx.x*64;
    int t  = blockIdx.y;
    const float* wptr; int j0, wwid, which;
    if(t < 8){ wptr=wq; j0=t*64; wwid=512; which=0; }
    else if(t < 16){ wptr=wk; j0=(t-8)*64; wwid=512; which=1; }
    else { wptr=wv; j0=(t-16)*64; wwid=1024; which=2; }
    int tid = threadIdx.x;
    for(int i=tid;i<4096;i+=256){
        int c=i>>6, ll=i&63;
        Xs[c][ll] = enc[(size_t)(b*CC+c)*LL + l0 + ll];
    }
    for(int i=tid;i<4096;i+=256){
        int c=i>>6, jj=i&63;
        Ws[c][jj] = wptr[(size_t)c*wwid + j0 + jj];
    }
    __syncthreads();
    int rg=tid>>4, cg=tid&15; int r0=rg*4, c0=cg*4;
    u64 acc[2][4] = {};
    #pragma unroll 4
    for(int c=0;c<64;c++){
        u64 a0=*(const u64*)&Xs[c][r0], a1=*(const u64*)&Xs[c][r0+2];
        float4 bv=*(const float4*)&Ws[c][c0];
        u64 b0=pk2(bv.x,bv.x), b1=pk2(bv.y,bv.y), b2=pk2(bv.z,bv.z), b3=pk2(bv.w,bv.w);
        acc[0][0]=fma2(a0,b0,acc[0][0]); acc[0][1]=fma2(a0,b1,acc[0][1]);
        acc[0][2]=fma2(a0,b2,acc[0][2]); acc[0][3]=fma2(a0,b3,acc[0][3]);
        acc[1][0]=fma2(a1,b0,acc[1][0]); acc[1][1]=fma2(a1,b1,acc[1][1]);
        acc[1][2]=fma2(a1,b2,acc[1][2]); acc[1][3]=fma2(a1,b3,acc[1][3]);
    }
    #pragma unroll
    for(int p=0;p<2;p++){
        #pragma unroll
        for(int n=0;n<4;n++){
            float2 e = up2(acc[p][n]);
            int j = j0+c0+n;
            int la = l0+r0+2*p, lb = la+1;
            if(which==0){ int h=j>>6, dk=j&63;
                g_q[((size_t)(b*8+h)*LL+la)*64+dk]=e.x;
                g_q[((size_t)(b*8+h)*LL+lb)*64+dk]=e.y; }
            else if(which==1){ int h=j>>6, dk=j&63;
                g_k[((size_t)(b*8+h)*LL+la)*64+dk]=e.x;
                g_k[((size_t)(b*8+h)*LL+lb)*64+dk]=e.y; }
            else { int h=j>>7, dv=j&127;
                g_v[((size_t)(b*8+h)*LL+la)*128+dv]=e.x;
                g_v[((size_t)(b*8+h)*LL+lb)*128+dv]=e.y; }
        }
    }
}

// ---------------- K3: flash attention via bf16 m16n8k16 mma + ldmatrix --------
// i-tile 128, j-tile 64. 256 thr = 8 warps; warp w owns rows [16w, 16w+16).
// No running max (scores bounded); O accumulates unnormalized, divide at end.
// smem: PQ buffer aliases Q staging (used once) and P probs (per j-tile).
__global__ void __launch_bounds__(256) k_flash(){
    __shared__ __nv_bfloat16 PQ[128*72];   // Q staging, then P probs [m][k/j]
    __shared__ __nv_bfloat16 Ksm[64*72];   // K tile [n][k]
    __shared__ __nv_bfloat16 Vsm[64*136];  // V tile [j][dv]
    __shared__ float lssh[64];
    __shared__ float lrow[128];

    int bh = blockIdx.y; int b = bh>>3, h = bh&7;
    int i0 = blockIdx.x*128;
    int tid = threadIdx.x;
    int w = tid>>5, lane = tid&31;
    int qg = lane>>2, tg = lane&3;
    int m0 = w*16;
    const float* qp = g_q + (size_t)bh*LL*64;
    const float* kp = g_k + (size_t)bh*LL*64;
    const float* vp = g_v + (size_t)bh*LL*128;

    unsigned pqU = (unsigned)__cvta_generic_to_shared(PQ);
    unsigned ksU = (unsigned)__cvta_generic_to_shared(Ksm);
    unsigned vsU = (unsigned)__cvta_generic_to_shared(Vsm);

    // stage Q tile as bf16 into PQ
    for(int idx=tid*4; idx<128*64; idx+=1024){
        int r=idx>>6, c=idx&63;
        float4 v = *(const float4*)(qp + (size_t)(i0+r)*64 + c);
        uint2 u; u.x = pkbf(v.x,v.y); u.y = pkbf(v.z,v.w);
        *(uint2*)&PQ[r*72 + c] = u;
    }
    if(tid<128) lrow[tid]=0.f;
    __syncthreads();

    // preload Q A-fragments (4 k-steps x 4 regs) straight from smem
    unsigned aq[4][4];
    #pragma unroll
    for(int ks=0;ks<4;ks++){
        int colb = ks*16 + 2*tg;
        aq[ks][0] = *(const unsigned*)&PQ[(m0+qg  )*72 + colb    ];
        aq[ks][1] = *(const unsigned*)&PQ[(m0+8+qg)*72 + colb    ];
        aq[ks][2] = *(const unsigned*)&PQ[(m0+qg  )*72 + colb + 8];
        aq[ks][3] = *(const unsigned*)&PQ[(m0+8+qg)*72 + colb + 8];
    }

    float O[16][4];
    #pragma unroll
    for(int i=0;i<16;i++){ O[i][0]=0.f; O[i][1]=0.f; O[i][2]=0.f; O[i][3]=0.f; }

    // per-lane ldmatrix base addresses
    int srow = lane&7, smat = (lane>>3)&1;
    // S-phase B (Ks, non-trans): lane addr row = n0+srow, col = ks*16 + smat*8
    unsigned kB = ksU + (unsigned)((srow*72 + smat*8)*2);
    // PV B (Vsm, trans): lane addr row = ks*16 + srow + 8*smat, col = n0
    unsigned vB = vsU + (unsigned)(((srow + 8*smat)*136)*2);
    // PV A (PQ as P, x4): mat = lane>>3: row = m0 + srow + 8*(mat&1), colb = 8*(mat>>1)
    int amat = lane>>3;
    unsigned pA = pqU + (unsigned)((((m0 + srow + 8*(amat&1))*72) + 8*(amat>>1))*2);

    for(int j0=0;j0<LL;j0+=64){
        // stage K, V (bf16), logsnr
        for(int idx=tid*4; idx<64*64; idx+=1024){
            int r=idx>>6, c=idx&63;
            float4 v = *(const float4*)(kp + (size_t)(j0+r)*64 + c);
            uint2 u; u.x = pkbf(v.x,v.y); u.y = pkbf(v.z,v.w);
            *(uint2*)&Ksm[r*72 + c] = u;
        }
        for(int idx=tid*4; idx<64*128; idx+=1024){
            int r=idx>>7, c=idx&127;
            float4 v = *(const float4*)(vp + (size_t)(j0+r)*128 + c);
            uint2 u; u.x = pkbf(v.x,v.y); u.y = pkbf(v.z,v.w);
            *(uint2*)&Vsm[r*136 + c] = u;
        }
        if(tid<64) lssh[tid]=g_logsnr[b*LL + j0 + tid];
        __syncthreads();

        // --- S = Q K^T, P = exp(S/8 + logsnr), stash P (bf16) in PQ ---
        float psLo=0.f, psHi=0.f;
        #pragma unroll
        for(int nt=0;nt<8;nt++){
            int n0=nt*8;
            float d0=0.f,d1=0.f,d2=0.f,d3=0.f;
            #pragma unroll
            for(int ks=0;ks<4;ks++){
                unsigned b0,b1;
                ldsm_x2(b0,b1, kB + (unsigned)((n0*72 + ks*16)*2));
                mma_bf16(d0,d1,d2,d3, aq[ks][0],aq[ks][1],aq[ks][2],aq[ks][3], b0,b1);
            }
            int c0=n0+2*tg;
            float ls0=lssh[c0], ls1=lssh[c0+1];
            float p0=__expf(d0*0.125f + ls0);
            float p1=__expf(d1*0.125f + ls1);
            float p2=__expf(d2*0.125f + ls0);
            float p3=__expf(d3*0.125f + ls1);
            psLo += p0+p1; psHi += p2+p3;
            *(unsigned*)&PQ[(m0+qg  )*72 + c0] = pkbf(p0,p1);
            *(unsigned*)&PQ[(m0+8+qg)*72 + c0] = pkbf(p2,p3);
        }
        psLo += __shfl_xor_sync(0xffffffffu, psLo, 1);
        psLo += __shfl_xor_sync(0xffffffffu, psLo, 2);
        psHi += __shfl_xor_sync(0xffffffffu, psHi, 1);
        psHi += __shfl_xor_sync(0xffffffffu, psHi, 2);
        if(tg==0){ lrow[m0+qg] += psLo; lrow[m0+8+qg] += psHi; }
        __syncwarp();   // P rows are warp-private; warp-level ordering suffices

        // --- O += P @ V ---
        unsigned ap[4][4];
        #pragma unroll
        for(int ks=0;ks<4;ks++)
            ldsm_x4(ap[ks], pA + (unsigned)(ks*16*2));
        #pragma unroll
        for(int nt=0;nt<16;nt++){
            int n0=nt*8;
            #pragma unroll
            for(int ks=0;ks<4;ks++){
                unsigned b0,b1;
                ldsm_x2t(b0,b1, vB + (unsigned)((ks*16*136 + n0)*2));
                mma_bf16(O[nt][0],O[nt][1],O[nt][2],O[nt][3],
                         ap[ks][0],ap[ks][1],ap[ks][2],ap[ks][3], b0,b1);
            }
        }
        __syncthreads();   // protect Ksm/Vsm (+PQ) before next staging
    }

    // epilogue: divide by row sums, write out
    float invLo = 1.f/lrow[m0+qg];
    float invHi = 1.f/lrow[m0+8+qg];
    size_t oa = (size_t)(b*LL + i0 + m0 + qg  )*1024 + h*128;
    size_t ob = (size_t)(b*LL + i0 + m0 + 8+qg)*1024 + h*128;
    #pragma unroll
    for(int nt=0;nt<16;nt++){
        int dv = nt*8 + 2*tg;
        float2 wa; wa.x=O[nt][0]*invLo; wa.y=O[nt][1]*invLo;
        float2 wb; wb.x=O[nt][2]*invHi; wb.y=O[nt][3]*invHi;
        *(float2*)(g_o + oa + dv) = wa;
        *(float2*)(g_o + ob + dv) = wb;
    }
}

// ---------------- K6a: o@fc split-K partial GEMM -------------------------------
__global__ void k_attnout_part(const float* __restrict__ fc){
    __shared__ float Hs[64][68];  // [m][l]
    __shared__ float Ws[64][68];  // [m][c]
    int b=blockIdx.z, ky=blockIdx.y, l0=blockIdx.x*64, tid=threadIdx.x;
    int rg=tid>>4, cg=tid&15; int r0=rg*4, c0=cg*4;
    u64 acc[2][4]={};
    for(int m0=ky*256; m0<ky*256+256; m0+=64){
        __syncthreads();
        for(int i=tid;i<4096;i+=256){
            int mm=i&63, ll=i>>6;
            Hs[mm][ll]=g_o[(size_t)(b*LL+l0+ll)*1024 + m0+mm];
        }
        for(int i=tid;i<4096;i+=256){
            int c=i&63, mm=i>>6;
            Ws[mm][c]=fc[(size_t)(m0+mm)*64+c];
        }
        __syncthreads();
        #pragma unroll 4
        for(int mm=0;mm<64;mm++){
            u64 a0=*(const u64*)&Hs[mm][r0], a1=*(const u64*)&Hs[mm][r0+2];
            float4 bv=*(const float4*)&Ws[mm][c0];
            u64 b0=pk2(bv.x,bv.x), b1=pk2(bv.y,bv.y), b2=pk2(bv.z,bv.z), b3=pk2(bv.w,bv.w);
            acc[0][0]=fma2(a0,b0,acc[0][0]); acc[0][1]=fma2(a0,b1,acc[0][1]);
            acc[0][2]=fma2(a0,b2,acc[0][2]); acc[0][3]=fma2(a0,b3,acc[0][3]);
            acc[1][0]=fma2(a1,b0,acc[1][0]); acc[1][1]=fma2(a1,b1,acc[1][1]);
            acc[1][2]=fma2(a1,b2,acc[1][2]); acc[1][3]=fma2(a1,b3,acc[1][3]);
        }
    }
    size_t pb = ((size_t)(ky*BB + b)*LL + l0)*64;
    #pragma unroll
    for(int p=0;p<2;p++){
        #pragma unroll
        for(int n=0;n<4;n++){
            float2 e = up2(acc[p][n]);
            int r = r0+2*p, c = c0+n;
            g_opart[pb + (size_t)r*64 + c]     = e.x;
            g_opart[pb + (size_t)(r+1)*64 + c] = e.y;
        }
    }
}

// ---------------- K6b: sum partials + residual + attn LN -----------------------
__global__ void k_attnout_fin(const float* __restrict__ enc, const float* __restrict__ lnw,
                              const float* __restrict__ lnb){
    __shared__ float Hs[64][68];
    int b=blockIdx.y, l0=blockIdx.x*64, tid=threadIdx.x;
    for(int i=tid;i<4096;i+=256){
        int l=i>>6, c=i&63;
        size_t off = ((size_t)(b)*LL + l0+l)*64 + c;
        size_t stp = (size_t)BB*LL*64;
        float s = g_opart[off] + g_opart[off+stp] + g_opart[off+2*stp] + g_opart[off+3*stp]
                + enc[(size_t)(b*CC+c)*LL + l0+l];
        Hs[l][c]=s;
    }
    __syncthreads();
    int row=tid>>2, qq=tid&3;
    float s1=0.f, s2=0.f;
    #pragma unroll
    for(int c=qq*16;c<qq*16+16;c++){ float v=Hs[row][c]; s1+=v; s2+=v*v; }
    s1 += __shfl_xor_sync(0xffffffffu, s1, 1);
    s2 += __shfl_xor_sync(0xffffffffu, s2, 1);
    s1 += __shfl_xor_sync(0xffffffffu, s1, 2);
    s2 += __shfl_xor_sync(0xffffffffu, s2, 2);
    float mean = s1*(1.f/64.f);
    float var  = s2*(1.f/64.f) - mean*mean;
    float iv = rsqrtf(var+1e-5f);
    #pragma unroll
    for(int c=qq*16;c<qq*16+16;c++){
        g_tok[(size_t)(b*LL+l0+row)*64+c] = (Hs[row][c]-mean)*iv*lnw[c]+lnb[c];
    }
}

// ---------------- K7: tok @ ss_in_w -> x1pre (B,DN,L) & z (B,L,DN) -------------
__global__ void k_xz(const float* __restrict__ win){
    __shared__ float Xs[64][68];
    __shared__ float Ws[64][68];
    int b=blockIdx.z, j0=blockIdx.y*64, l0=blockIdx.x*64, tid=threadIdx.x;
    for(int i=tid;i<4096;i+=256){
        int ll=i>>6, c=i&63;
        Xs[c][ll] = g_tok[(size_t)(b*LL+l0+ll)*64 + c];
    }
    for(int i=tid;i<4096;i+=256){
        int c=i>>6, jj=i&63;
        Ws[c][jj] = win[(size_t)c*256 + j0 + jj];
    }
    __syncthreads();
    int rg=tid>>4, cg=tid&15; int r0=rg*4, c0=cg*4;
    u64 acc[2][4]={};
    #pragma unroll 4
    for(int c=0;c<64;c++){
        u64 a0=*(const u64*)&Xs[c][r0], a1=*(const u64*)&Xs[c][r0+2];
        float4 bv=*(const float4*)&Ws[c][c0];
        u64 b0=pk2(bv.x,bv.x), b1=pk2(bv.y,bv.y), b2=pk2(bv.z,bv.z), b3=pk2(bv.w,bv.w);
        acc[0][0]=fma2(a0,b0,acc[0][0]); acc[0][1]=fma2(a0,b1,acc[0][1]);
        acc[0][2]=fma2(a0,b2,acc[0][2]); acc[0][3]=fma2(a0,b3,acc[0][3]);
        acc[1][0]=fma2(a1,b0,acc[1][0]); acc[1][1]=fma2(a1,b1,acc[1][1]);
        acc[1][2]=fma2(a1,b2,acc[1][2]); acc[1][3]=fma2(a1,b3,acc[1][3]);
    }
    #pragma unroll
    for(int p=0;p<2;p++){
        #pragma unroll
        for(int n=0;n<4;n++){
            float2 e = up2(acc[p][n]);
            int j=j0+c0+n;
            int la=l0+r0+2*p, lb=la+1;
            if(j<128){
                g_x1pre[((size_t)b*128+j)*LL + la] = e.x;
                g_x1pre[((size_t)b*128+j)*LL + lb] = e.y;
            } else {
                g_z[(size_t)(b*LL+la)*128 + (j-128)] = e.x;
                g_z[(size_t)(b*LL+lb)*128 + (j-128)] = e.y;
            }
        }
    }
}

// ---------------- K8: depthwise 3x3 + bias + silu ------------------------------
__global__ void k_dwconv(const float* __restrict__ wconv, const float* __restrict__ bias){
    __shared__ float pl[HHH*WWW];
    int b=blockIdx.y, d=blockIdx.x, tid=threadIdx.x;
    const float* ip = g_x1pre + (size_t)(b*DNN+d)*LL;
    for(int i=tid;i<LL;i+=256) pl[i]=ip[i];
    __syncthreads();
    float w[9];
    #pragma unroll
    for(int i=0;i<9;i++) w[i]=wconv[d*9+i];
    float bb = bias[d];
    float* op = g_x1 + (size_t)(b*DNN+d)*LL;
    for(int p=tid;p<LL;p+=256){
        int h=p/WWW, x=p%WWW;
        float s=bb;
        #pragma unroll
        for(int kh=0;kh<3;kh++){
            int ih=h+kh-1;
            if(ih<0||ih>=HHH) continue;
            #pragma unroll
            for(int kw=0;kw<3;kw++){
                int iw=x+kw-1;
                if(iw<0||iw>=WWW) continue;
                s += w[kh*3+kw]*pl[ih*WWW+iw];
            }
        }
        op[p] = silu_f(s);
    }
}

// ---------------- K9: x_dbl + dts/B/C extraction -------------------------------
__global__ void k_xdbl(const float* __restrict__ xproj, const float* __restrict__ dtw,
                       const float* __restrict__ dtb){
    __shared__ float xs_s[128][32];
    __shared__ float pj_s[36*128];
    __shared__ float xd_s[36][33];
    int b=blockIdx.z, k=blockIdx.y, l0=blockIdx.x*32;
    int bk=b*4+k, tid=threadIdx.x;
    for(int i=tid;i<36*128;i+=256) pj_s[i]=xproj[(size_t)k*36*128+i];
    const float* x1p = g_x1 + (size_t)b*128*LL;
    for(int i=tid;i<128*32;i+=256){
        int d=i>>5, ll=i&31;
        int lp=l0+ll, src;
        if(k==0) src=lp;
        else if(k==1) src=(lp%48)*48 + lp/48;
        else if(k==2) src=LL-1-lp;
        else { int t2=LL-1-lp; src=(t2%48)*48 + t2/48; }
        xs_s[d][ll]=x1p[(size_t)d*LL+src];
    }
    __syncthreads();
    {
        int ll=tid&31, g=tid>>5;
        for(int c=g;c<36;c+=8){
            float s=0.f;
            #pragma unroll 8
            for(int d=0;d<128;d++) s += pj_s[c*128+d]*xs_s[d][ll];
            xd_s[c][ll]=s;
        }
    }
    __syncthreads();
    {
        int ll=tid&31, g=tid>>5;
        float r0v=xd_s[0][ll],r1v=xd_s[1][ll],r2v=xd_s[2][ll],r3v=xd_s[3][ll];
        for(int i=0;i<16;i++){
            int d=g*16+i;
            const float* w=dtw+((size_t)k*128+d)*4;
            float dv=r0v*w[0]+r1v*w[1]+r2v*w[2]+r3v*w[3]+dtb[k*128+d];
            float sp=softplus_f(dv);
            size_t o=((size_t)bk*128+d)*LL + l0+ll;
            g_dt[o]=sp;
            g_u[o]=sp*xs_s[d][ll];
        }
    }
    for(int idx=tid;idx<32*16;idx+=256){
        int ll=idx>>4, n=idx&15;
        size_t o=((size_t)bk*LL + l0+ll)*16 + n;
        g_Bsc[o]=xd_s[4+n][ll];
        g_Csc[o]=xd_s[20+n][ll];
    }
}

// ---------------- K10: selective scan ------------------------------------------
__global__ void k_scan(const float* __restrict__ Alog){
    int lane=threadIdx.x;
    int half=lane>>4, n=lane&15;
    int ci = blockIdx.x*2 + half;
    int bk = ci>>7, d = ci&127, k = bk&3;
    const float* dtp = g_dt + (size_t)ci*LL;
    const float* up  = g_u  + (size_t)ci*LL;
    const float* Bp  = g_Bsc + (size_t)bk*LL*16;
    const float* Cp  = g_Csc + (size_t)bk*LL*16;
    float* yp = g_ys + (size_t)ci*LL;
    float A = -__expf(Alog[((size_t)k*128+d)*16 + n]);
    float h = 0.f;
    #pragma unroll 4
    for(int l=0;l<LL;l++){
        float dt = dtp[l];
        float u  = up[l];
        float Bn = Bp[l*16+n];
        float Cn = Cp[l*16+n];
        float dA = __expf(dt*A);
        h = h*dA + u*Bn;
        float y = h*Cn;
        y += __shfl_xor_sync(0xffffffffu, y, 8);
        y += __shfl_xor_sync(0xffffffffu, y, 4);
        y += __shfl_xor_sync(0xffffffffu, y, 2);
        y += __shfl_xor_sync(0xffffffffu, y, 1);
        if(n==0) yp[l]=y;
    }
}

// ---------------- K11: direction merge + ss LN + gating + out proj + ffn LN ----
__global__ void k_combine(const float* __restrict__ enc, const float* __restrict__ snr,
                          const float* __restrict__ Dw,  const float* __restrict__ nw,
                          const float* __restrict__ nb,  const float* __restrict__ outw,
                          const float* __restrict__ fw,  const float* __restrict__ fb){
    __shared__ float yv[128];
    __shared__ float ra[128], rb[128];
    __shared__ float pbuf[128];
    __shared__ float x2s[64];
    __shared__ float rc[64], rd[64];
    int b=blockIdx.y, l=blockIdx.x, tid=threadIdx.x;
    int hh=l/48, ww=l%48;
    int m = ww*48 + hh;
    int fl = LL-1-l, fm = LL-1-m;
    int d = tid;
    size_t base = (size_t)b*4*128*LL;
    float y = g_ys[base + ((size_t)(0*128+d))*LL + l]
            + g_ys[base + ((size_t)(2*128+d))*LL + fl]
            + g_ys[base + ((size_t)(1*128+d))*LL + m]
            + g_ys[base + ((size_t)(3*128+d))*LL + fm];
    float sD = Dw[0*128+d]+Dw[1*128+d]+Dw[2*128+d]+Dw[3*128+d];
    y += sD * g_x1[(size_t)(b*128+d)*LL + l];
    ra[tid]=y; rb[tid]=y*y; __syncthreads();
    for(int s=64;s>0;s>>=1){ if(tid<s){ ra[tid]+=ra[tid+s]; rb[tid]+=rb[tid+s]; } __syncthreads(); }
    float mean = ra[0]*(1.f/128.f);
    float var  = rb[0]*(1.f/128.f)-mean*mean;
    float ln = (y-mean)*rsqrtf(var+1e-5f)*nw[d]+nb[d];
    float z  = g_z[(size_t)(b*LL+l)*128+d];
    yv[d] = ln * silu_f(z) * snr[b*LL+l];
    __syncthreads();
    int c=tid&63, hf=tid>>6;
    float acc=0.f;
    #pragma unroll 8
    for(int dd=hf*64; dd<hf*64+64; dd++) acc += yv[dd]*outw[(size_t)dd*64+c];
    pbuf[tid]=acc; __syncthreads();
    if(tid<64){
        float x2 = pbuf[tid]+pbuf[tid+64] + enc[(size_t)(b*CC+tid)*LL + l];
        x2s[tid]=x2;
        g_x2[(size_t)(b*LL+l)*64+tid]=x2;
        rc[tid]=x2; rd[tid]=x2*x2;
    }
    __syncthreads();
    for(int s=32;s>0;s>>=1){ if(tid<s){ rc[tid]+=rc[tid+s]; rd[tid]+=rd[tid+s]; } __syncthreads(); }
    if(tid<64){
        float mn=rc[0]*(1.f/64.f);
        float vr=rd[0]*(1.f/64.f)-mn*mn;
        g_xn[(size_t)(b*LL+l)*64+tid] = (x2s[tid]-mn)*rsqrtf(vr+1e-5f)*fw[tid]+fb[tid];
    }
}

// ---------------- K12: ffn1 = gelu(xn @ w1^T) -> (B,256,L) ---------------------
__global__ void k_ffn1(const float* __restrict__ w1){
    __shared__ float Xs[64][68];
    __shared__ float Ws[64][68];
    int b=blockIdx.z, o0=blockIdx.y*64, l0=blockIdx.x*64, tid=threadIdx.x;
    for(int i=tid;i<4096;i+=256){
        int ll=i>>6, c=i&63;
        Xs[c][ll]=g_xn[(size_t)(b*LL+l0+ll)*64+c];
    }
    for(int i=tid;i<4096;i+=256){
        int oo=i>>6, c=i&63;
        Ws[c][oo]=w1[(size_t)(o0+oo)*64+c];
    }
    __syncthreads();
    int rg=tid>>4, cg=tid&15; int r0=rg*4, c0=cg*4;
    u64 acc[2][4]={};
    #pragma unroll 4
    for(int c=0;c<64;c++){
        u64 a0=*(const u64*)&Xs[c][r0], a1=*(const u64*)&Xs[c][r0+2];
        float4 bv=*(const float4*)&Ws[c][c0];
        u64 b0=pk2(bv.x,bv.x), b1=pk2(bv.y,bv.y), b2=pk2(bv.z,bv.z), b3=pk2(bv.w,bv.w);
        acc[0][0]=fma2(a0,b0,acc[0][0]); acc[0][1]=fma2(a0,b1,acc[0][1]);
        acc[0][2]=fma2(a0,b2,acc[0][2]); acc[0][3]=fma2(a0,b3,acc[0][3]);
        acc[1][0]=fma2(a1,b0,acc[1][0]); acc[1][1]=fma2(a1,b1,acc[1][1]);
        acc[1][2]=fma2(a1,b2,acc[1][2]); acc[1][3]=fma2(a1,b3,acc[1][3]);
    }
    #pragma unroll
    for(int p=0;p<2;p++){
        #pragma unroll
        for(int n=0;n<4;n++){
            float2 e = up2(acc[p][n]);
            int la=l0+r0+2*p;
            g_h1[(size_t)(b*256+o0+c0+n)*LL + la  ] = gelu_f(e.x);
            g_h1[(size_t)(b*256+o0+c0+n)*LL + la+1] = gelu_f(e.y);
        }
    }
}

// ---------------- K13: depthwise 3x3 + gelu (256 ch) ---------------------------
__global__ void k_dwgelu(const float* __restrict__ wconv){
    __shared__ float pl[HHH*WWW];
    int b=blockIdx.y, d=blockIdx.x, tid=threadIdx.x;
    const float* ip = g_h1 + (size_t)(b*CM+d)*LL;
    for(int i=tid;i<LL;i+=256) pl[i]=ip[i];
    __syncthreads();
    float w[9];
    #pragma unroll
    for(int i=0;i<9;i++) w[i]=wconv[d*9+i];
    float* op = g_h2 + (size_t)(b*CM+d)*LL;
    for(int p=tid;p<LL;p+=256){
        int h=p/WWW, x=p%WWW;
        float s=0.f;
        #pragma unroll
        for(int kh=0;kh<3;kh++){
            int ih=h+kh-1;
            if(ih<0||ih>=HHH) continue;
            #pragma unroll
            for(int kw=0;kw<3;kw++){
                int iw=x+kw-1;
                if(iw<0||iw>=WWW) continue;
                s += w[kh*3+kw]*pl[ih*WWW+iw];
            }
        }
        op[p] = gelu_f(s);
    }
}

// ---------------- K14: ffn2 + residual + NCHW output ---------------------------
__global__ void k_ffn2(const float* __restrict__ w2, float* __restrict__ out){
    __shared__ float Hs[64][68];
    __shared__ float Ws[64][68];
    int b=blockIdx.y, l0=blockIdx.x*64, tid=threadIdx.x;
    int rg=tid>>4, cg=tid&15; int r0=rg*4, c0=cg*4;
    u64 acc[2][4]={};
    for(int m0=0;m0<256;m0+=64){
        __syncthreads();
        for(int i=tid;i<4096;i+=256){
            int mm=i>>6, ll=i&63;
            Hs[mm][ll]=g_h2[(size_t)(b*256+m0+mm)*LL + l0+ll];
        }
        for(int i=tid;i<4096;i+=256){
            int c=i&63, mm=i>>6;
            Ws[mm][c]=w2[(size_t)c*256 + m0+mm];
        }
        __syncthreads();
        #pragma unroll 4
        for(int mm=0;mm<64;mm++){
            u64 a0=*(const u64*)&Hs[mm][r0], a1=*(const u64*)&Hs[mm][r0+2];
            float4 bv; bv.x=Ws[mm][c0]; bv.y=Ws[mm][c0+1]; bv.z=Ws[mm][c0+2]; bv.w=Ws[mm][c0+3];
            u64 b0=pk2(bv.x,bv.x), b1=pk2(bv.y,bv.y), b2=pk2(bv.z,bv.z), b3=pk2(bv.w,bv.w);
            acc[0][0]=fma2(a0,b0,acc[0][0]); acc[0][1]=fma2(a0,b1,acc[0][1]);
            acc[0][2]=fma2(a0,b2,acc[0][2]); acc[0][3]=fma2(a0,b3,acc[0][3]);
            acc[1][0]=fma2(a1,b0,acc[1][0]); acc[1][1]=fma2(a1,b1,acc[1][1]);
            acc[1][2]=fma2(a1,b2,acc[1][2]); acc[1][3]=fma2(a1,b3,acc[1][3]);
        }
    }
    #pragma unroll
    for(int p=0;p<2;p++){
        #pragma unroll
        for(int n=0;n<4;n++){
            float2 e = up2(acc[p][n]);
            int la=l0+r0+2*p, c=c0+n;
            out[(size_t)(b*64+c)*LL + la  ] = e.x + g_x2[(size_t)(b*LL+la  )*64+c];
            out[(size_t)(b*64+c)*LL + la+1] = e.y + g_x2[(size_t)(b*LL+la+1)*64+c];
        }
    }
}

// ---------------- launch --------------------------------------------------------
extern "C" void kernel_launch(void* const* d_in, const int* in_sizes, int n_in,
                              void* d_out, int out_size){
    (void)in_sizes; (void)n_in; (void)out_size;
    const float* enc       = (const float*)d_in[0];
    const float* snr       = (const float*)d_in[1];
    const float* attn_wq   = (const float*)d_in[2];
    const float* attn_wk   = (const float*)d_in[3];
    const float* attn_wv   = (const float*)d_in[4];
    const float* attn_fc   = (const float*)d_in[5];
    const float* attn_ln_w = (const float*)d_in[6];
    const float* attn_ln_b = (const float*)d_in[7];
    const float* ss_in_w   = (const float*)d_in[8];
    const float* ss_conv_w = (const float*)d_in[9];
    const float* ss_conv_b = (const float*)d_in[10];
    const float* ss_xproj  = (const float*)d_in[11];
    const float* ss_dt_w   = (const float*)d_in[12];
    const float* ss_dt_b   = (const float*)d_in[13];
    const float* ss_Alog   = (const float*)d_in[14];
    const float* ss_D      = (const float*)d_in[15];
    const float* ss_norm_w = (const float*)d_in[16];
    const float* ss_norm_b = (const float*)d_in[17];
    const float* ss_out_w  = (const float*)d_in[18];
    const float* ffn_ln_w  = (const float*)d_in[19];
    const float* ffn_ln_b  = (const float*)d_in[20];
    const float* ffn_w1    = (const float*)d_in[21];
    const float* ffn_dw    = (const float*)d_in[22];
    const float* ffn_w2    = (const float*)d_in[23];
    float* out = (float*)d_out;

    k_logsnr<<<(BB*LL+255)/256, 256>>>(snr);
    k_qkv   <<<dim3(LL/64, 32, BB), 256>>>(enc, attn_wq, attn_wk, attn_wv);
    k_flash <<<dim3(LL/128, BHN), 256>>>();
    k_attnout_part<<<dim3(LL/64, 4, BB), 256>>>(attn_fc);
    k_attnout_fin <<<dim3(LL/64, BB), 256>>>(enc, attn_ln_w, attn_ln_b);
    k_xz    <<<dim3(LL/64, 4, BB), 256>>>(ss_in_w);
    k_dwconv<<<dim3(DNN, BB), 256>>>(ss_conv_w, ss_conv_b);
    k_xdbl  <<<dim3(LL/32, 4, BB), 256>>>(ss_xproj, ss_dt_w, ss_dt_b);
    k_scan  <<<BB*4*DNN/2, 32>>>(ss_Alog);
    k_combine<<<dim3(LL, BB), 128>>>(enc, snr, ss_D, ss_norm_w, ss_norm_b,
                                     ss_out_w, ffn_ln_w, ffn_ln_b);
    k_ffn1  <<<dim3(LL/64, CM/64, BB), 256>>>(ffn_w1);
    k_dwgelu<<<dim3(CM, BB), 256>>>(ffn_dw);
    k_ffn2  <<<dim3(LL/64, BB), 256>>>(ffn_w2, out);
}

// round 8
// speedup vs baseline: 4.1923x; 1.0617x over previous
#include <cuda_runtime.h>
#include <cuda_bf16.h>
#include <math.h>

#define BB 2
#define CC 64
#define HHH 48
#define WWW 48
#define LL 2304
#define NHH 8
#define DKK 64
#define DVV 128
#define DNN 128
#define NSS 16
#define CM 256
#define BHN (BB*NHH)

typedef unsigned long long u64;

// ---------------- packed fp32 helpers (Blackwell f32x2) ----------------------
__device__ __forceinline__ u64 pk2(float x, float y){
    u64 r; asm("mov.b64 %0, {%1,%2};" : "=l"(r) : "f"(x), "f"(y)); return r;
}
__device__ __forceinline__ u64 fma2(u64 a, u64 b, u64 c){
    u64 d; asm("fma.rn.f32x2 %0, %1, %2, %3;" : "=l"(d) : "l"(a), "l"(b), "l"(c)); return d;
}
__device__ __forceinline__ float2 up2(u64 a){
    float2 f; asm("mov.b64 {%0,%1}, %2;" : "=f"(f.x), "=f"(f.y) : "l"(a)); return f;
}

// ---------------- bf16 mma helpers -------------------------------------------
__device__ __forceinline__ unsigned pkbf(float lo, float hi){
    unsigned r; asm("cvt.rn.bf16x2.f32 %0, %1, %2;" : "=r"(r) : "f"(hi), "f"(lo)); return r;
}
__device__ __forceinline__ void ldsm_x2(unsigned& r0, unsigned& r1, unsigned addr){
    asm volatile("ldmatrix.sync.aligned.m8n8.x2.shared.b16 {%0,%1}, [%2];"
        : "=r"(r0), "=r"(r1) : "r"(addr));
}
__device__ __forceinline__ void ldsm_x2t(unsigned& r0, unsigned& r1, unsigned addr){
    asm volatile("ldmatrix.sync.aligned.m8n8.x2.trans.shared.b16 {%0,%1}, [%2];"
        : "=r"(r0), "=r"(r1) : "r"(addr));
}
__device__ __forceinline__ void ldsm_x4(unsigned* r, unsigned addr){
    asm volatile("ldmatrix.sync.aligned.m8n8.x4.shared.b16 {%0,%1,%2,%3}, [%4];"
        : "=r"(r[0]), "=r"(r[1]), "=r"(r[2]), "=r"(r[3]) : "r"(addr));
}
__device__ __forceinline__ void mma_bf16(float& d0, float& d1, float& d2, float& d3,
    unsigned a0, unsigned a1, unsigned a2, unsigned a3, unsigned b0, unsigned b1){
    asm volatile("mma.sync.aligned.m16n8k16.row.col.f32.bf16.bf16.f32 "
        "{%0,%1,%2,%3}, {%4,%5,%6,%7}, {%8,%9}, {%0,%1,%2,%3};"
        : "+f"(d0), "+f"(d1), "+f"(d2), "+f"(d3)
        : "r"(a0), "r"(a1), "r"(a2), "r"(a3), "r"(b0), "r"(b1));
}

// ---------------- scratch (static device globals; no runtime alloc) ----------
__device__ __nv_bfloat16 g_qh[BHN*LL*DKK];
__device__ __nv_bfloat16 g_kh[BHN*LL*DKK];
__device__ __nv_bfloat16 g_vh[BHN*LL*DVV];
__device__ float g_logsnr[BB*LL];
__device__ float g_o[BB*LL*NHH*DVV];
__device__ float g_opart[4*BB*LL*CC];
__device__ float g_tok[BB*LL*CC];
__device__ float g_z[BB*LL*DNN];
__device__ float g_x1pre[BB*DNN*LL];
__device__ float g_x1[BB*DNN*LL];
__device__ float g_dt[BB*4*DNN*LL];
__device__ float g_u[BB*4*DNN*LL];
__device__ float g_Bsc[BB*4*LL*NSS];
__device__ float g_Csc[BB*4*LL*NSS];
__device__ float g_ys[BB*4*DNN*LL];
__device__ float g_x2[BB*LL*CC];
__device__ float g_xn[BB*LL*CC];
__device__ float g_h1[BB*CM*LL];
__device__ float g_h2[BB*CM*LL];

// ---------------- helpers ----------------------------------------------------
__device__ __forceinline__ float silu_f(float x){ return x/(1.f+__expf(-x)); }
__device__ __forceinline__ float gelu_f(float x){ return 0.5f*x*(1.f+erff(x*0.70710678118654752440f)); }
__device__ __forceinline__ float softplus_f(float x){ return fmaxf(x,0.f)+log1pf(__expf(-fabsf(x))); }

// ---------------- K1: log(snr+1e-4) ------------------------------------------
__global__ void k_logsnr(const float* __restrict__ snr){
    int i = blockIdx.x*256 + threadIdx.x;
    if(i < BB*LL) g_logsnr[i] = logf(snr[i] + 1e-4f);
}

// ---------------- K2: QKV projections -> bf16 outputs --------------------------
__global__ void k_qkv(const float* __restrict__ enc, const float* __restrict__ wq,
                      const float* __restrict__ wk, const float* __restrict__ wv){
    __shared__ float Xs[64][68];  // [c][l]
    __shared__ float Ws[64][68];  // [c][j]
    int b = blockIdx.z;
    int l0 = blockIdx.x*64;
    int t  = blockIdx.y;
    const float* wptr; int j0, wwid, which;
    if(t < 8){ wptr=wq; j0=t*64; wwid=512; which=0; }
    else if(t < 16){ wptr=wk; j0=(t-8)*64; wwid=512; which=1; }
    else { wptr=wv; j0=(t-16)*64; wwid=1024; which=2; }
    int tid = threadIdx.x;
    for(int i=tid;i<4096;i+=256){
        int c=i>>6, ll=i&63;
        Xs[c][ll] = enc[(size_t)(b*CC+c)*LL + l0 + ll];
    }
    for(int i=tid;i<4096;i+=256){
        int c=i>>6, jj=i&63;
        Ws[c][jj] = wptr[(size_t)c*wwid + j0 + jj];
    }
    __syncthreads();
    int rg=tid>>4, cg=tid&15; int r0=rg*4, c0=cg*4;
    u64 acc[2][4] = {};
    #pragma unroll 4
    for(int c=0;c<64;c++){
        u64 a0=*(const u64*)&Xs[c][r0], a1=*(const u64*)&Xs[c][r0+2];
        float4 bv=*(const float4*)&Ws[c][c0];
        u64 b0=pk2(bv.x,bv.x), b1=pk2(bv.y,bv.y), b2=pk2(bv.z,bv.z), b3=pk2(bv.w,bv.w);
        acc[0][0]=fma2(a0,b0,acc[0][0]); acc[0][1]=fma2(a0,b1,acc[0][1]);
        acc[0][2]=fma2(a0,b2,acc[0][2]); acc[0][3]=fma2(a0,b3,acc[0][3]);
        acc[1][0]=fma2(a1,b0,acc[1][0]); acc[1][1]=fma2(a1,b1,acc[1][1]);
        acc[1][2]=fma2(a1,b2,acc[1][2]); acc[1][3]=fma2(a1,b3,acc[1][3]);
    }
    #pragma unroll
    for(int p=0;p<2;p++){
        #pragma unroll
        for(int n=0;n<4;n++){
            float2 e = up2(acc[p][n]);
            int j = j0+c0+n;
            int la = l0+r0+2*p, lb = la+1;
            if(which==0){ int h=j>>6, dk=j&63;
                g_qh[((size_t)(b*8+h)*LL+la)*64+dk]=__float2bfloat16(e.x);
                g_qh[((size_t)(b*8+h)*LL+lb)*64+dk]=__float2bfloat16(e.y); }
            else if(which==1){ int h=j>>6, dk=j&63;
                g_kh[((size_t)(b*8+h)*LL+la)*64+dk]=__float2bfloat16(e.x);
                g_kh[((size_t)(b*8+h)*LL+lb)*64+dk]=__float2bfloat16(e.y); }
            else { int h=j>>7, dv=j&127;
                g_vh[((size_t)(b*8+h)*LL+la)*128+dv]=__float2bfloat16(e.x);
                g_vh[((size_t)(b*8+h)*LL+lb)*128+dv]=__float2bfloat16(e.y); }
        }
    }
}

// ---------------- K3: flash attention, bf16 mma, 2 CTAs/SM ---------------------
__global__ void __launch_bounds__(256,2) k_flash(){
    __shared__ __nv_bfloat16 PQ[128*72];   // Q staging, then P probs
    __shared__ __nv_bfloat16 Ksm[64*72];
    __shared__ __nv_bfloat16 Vsm[64*136];
    __shared__ float lssh[64];
    __shared__ float lrow[128];

    int bh = blockIdx.y; int b = bh>>3, h = bh&7;
    int i0 = blockIdx.x*128;
    int tid = threadIdx.x;
    int w = tid>>5, lane = tid&31;
    int qg = lane>>2, tg = lane&3;
    int m0 = w*16;
    const __nv_bfloat16* qp = g_qh + (size_t)bh*LL*64;
    const __nv_bfloat16* kp = g_kh + (size_t)bh*LL*64;
    const __nv_bfloat16* vp = g_vh + (size_t)bh*LL*128;

    unsigned pqU = (unsigned)__cvta_generic_to_shared(PQ);
    unsigned ksU = (unsigned)__cvta_generic_to_shared(Ksm);
    unsigned vsU = (unsigned)__cvta_generic_to_shared(Vsm);

    // stage Q tile (bf16 straight copy, uint4 = 8 elems)
    for(int idx=tid*8; idx<128*64; idx+=2048){
        int r=idx>>6, c=idx&63;
        *(uint4*)&PQ[r*72 + c] = *(const uint4*)(qp + (size_t)(i0+r)*64 + c);
    }
    if(tid<128) lrow[tid]=0.f;
    __syncthreads();

    unsigned aq[4][4];
    #pragma unroll
    for(int ks=0;ks<4;ks++){
        int colb = ks*16 + 2*tg;
        aq[ks][0] = *(const unsigned*)&PQ[(m0+qg  )*72 + colb    ];
        aq[ks][1] = *(const unsigned*)&PQ[(m0+8+qg)*72 + colb    ];
        aq[ks][2] = *(const unsigned*)&PQ[(m0+qg  )*72 + colb + 8];
        aq[ks][3] = *(const unsigned*)&PQ[(m0+8+qg)*72 + colb + 8];
    }

    float O[16][4];
    #pragma unroll
    for(int i=0;i<16;i++){ O[i][0]=0.f; O[i][1]=0.f; O[i][2]=0.f; O[i][3]=0.f; }

    int srow = lane&7, smat = (lane>>3)&1;
    unsigned kB = ksU + (unsigned)((srow*72 + smat*8)*2);
    unsigned vB = vsU + (unsigned)(((srow + 8*smat)*136)*2);
    int amat = lane>>3;
    unsigned pA = pqU + (unsigned)((((m0 + srow + 8*(amat&1))*72) + 8*(amat>>1))*2);

    for(int j0=0;j0<LL;j0+=64){
        // stage K, V (bf16 copies), logsnr
        for(int idx=tid*8; idx<64*64; idx+=2048){
            int r=idx>>6, c=idx&63;
            *(uint4*)&Ksm[r*72 + c] = *(const uint4*)(kp + (size_t)(j0+r)*64 + c);
        }
        for(int idx=tid*8; idx<64*128; idx+=2048){
            int r=idx>>7, c=idx&127;
            *(uint4*)&Vsm[r*136 + c] = *(const uint4*)(vp + (size_t)(j0+r)*128 + c);
        }
        if(tid<64) lssh[tid]=g_logsnr[b*LL + j0 + tid];
        __syncthreads();

        // --- S = Q K^T, P = exp(S/8 + logsnr) ---
        float psLo=0.f, psHi=0.f;
        #pragma unroll
        for(int nt=0;nt<8;nt++){
            int n0=nt*8;
            float d0=0.f,d1=0.f,d2=0.f,d3=0.f;
            #pragma unroll
            for(int ks=0;ks<4;ks++){
                unsigned b0,b1;
                ldsm_x2(b0,b1, kB + (unsigned)((n0*72 + ks*16)*2));
                mma_bf16(d0,d1,d2,d3, aq[ks][0],aq[ks][1],aq[ks][2],aq[ks][3], b0,b1);
            }
            int c0=n0+2*tg;
            float ls0=lssh[c0], ls1=lssh[c0+1];
            float p0=__expf(d0*0.125f + ls0);
            float p1=__expf(d1*0.125f + ls1);
            float p2=__expf(d2*0.125f + ls0);
            float p3=__expf(d3*0.125f + ls1);
            psLo += p0+p1; psHi += p2+p3;
            *(unsigned*)&PQ[(m0+qg  )*72 + c0] = pkbf(p0,p1);
            *(unsigned*)&PQ[(m0+8+qg)*72 + c0] = pkbf(p2,p3);
        }
        psLo += __shfl_xor_sync(0xffffffffu, psLo, 1);
        psLo += __shfl_xor_sync(0xffffffffu, psLo, 2);
        psHi += __shfl_xor_sync(0xffffffffu, psHi, 1);
        psHi += __shfl_xor_sync(0xffffffffu, psHi, 2);
        if(tg==0){ lrow[m0+qg] += psLo; lrow[m0+8+qg] += psHi; }
        __syncwarp();

        // --- O += P @ V ---
        unsigned ap[4][4];
        #pragma unroll
        for(int ks=0;ks<4;ks++)
            ldsm_x4(ap[ks], pA + (unsigned)(ks*16*2));
        #pragma unroll
        for(int nt=0;nt<16;nt++){
            int n0=nt*8;
            #pragma unroll
            for(int ks=0;ks<4;ks++){
                unsigned b0,b1;
                ldsm_x2t(b0,b1, vB + (unsigned)((ks*16*136 + n0)*2));
                mma_bf16(O[nt][0],O[nt][1],O[nt][2],O[nt][3],
                         ap[ks][0],ap[ks][1],ap[ks][2],ap[ks][3], b0,b1);
            }
        }
        __syncthreads();
    }

    float invLo = 1.f/lrow[m0+qg];
    float invHi = 1.f/lrow[m0+8+qg];
    size_t oa = (size_t)(b*LL + i0 + m0 + qg  )*1024 + h*128;
    size_t ob = (size_t)(b*LL + i0 + m0 + 8+qg)*1024 + h*128;
    #pragma unroll
    for(int nt=0;nt<16;nt++){
        int dv = nt*8 + 2*tg;
        float2 wa; wa.x=O[nt][0]*invLo; wa.y=O[nt][1]*invLo;
        float2 wb; wb.x=O[nt][2]*invHi; wb.y=O[nt][3]*invHi;
        *(float2*)(g_o + oa + dv) = wa;
        *(float2*)(g_o + ob + dv) = wb;
    }
}

// ---------------- K6a: o@fc split-K partial GEMM -------------------------------
__global__ void k_attnout_part(const float* __restrict__ fc){
    __shared__ float Hs[64][68];
    __shared__ float Ws[64][68];
    int b=blockIdx.z, ky=blockIdx.y, l0=blockIdx.x*64, tid=threadIdx.x;
    int rg=tid>>4, cg=tid&15; int r0=rg*4, c0=cg*4;
    u64 acc[2][4]={};
    for(int m0=ky*256; m0<ky*256+256; m0+=64){
        __syncthreads();
        for(int i=tid;i<4096;i+=256){
            int mm=i&63, ll=i>>6;
            Hs[mm][ll]=g_o[(size_t)(b*LL+l0+ll)*1024 + m0+mm];
        }
        for(int i=tid;i<4096;i+=256){
            int c=i&63, mm=i>>6;
            Ws[mm][c]=fc[(size_t)(m0+mm)*64+c];
        }
        __syncthreads();
        #pragma unroll 4
        for(int mm=0;mm<64;mm++){
            u64 a0=*(const u64*)&Hs[mm][r0], a1=*(const u64*)&Hs[mm][r0+2];
            float4 bv=*(const float4*)&Ws[mm][c0];
            u64 b0=pk2(bv.x,bv.x), b1=pk2(bv.y,bv.y), b2=pk2(bv.z,bv.z), b3=pk2(bv.w,bv.w);
            acc[0][0]=fma2(a0,b0,acc[0][0]); acc[0][1]=fma2(a0,b1,acc[0][1]);
            acc[0][2]=fma2(a0,b2,acc[0][2]); acc[0][3]=fma2(a0,b3,acc[0][3]);
            acc[1][0]=fma2(a1,b0,acc[1][0]); acc[1][1]=fma2(a1,b1,acc[1][1]);
            acc[1][2]=fma2(a1,b2,acc[1][2]); acc[1][3]=fma2(a1,b3,acc[1][3]);
        }
    }
    size_t pb = ((size_t)(ky*BB + b)*LL + l0)*64;
    #pragma unroll
    for(int p=0;p<2;p++){
        #pragma unroll
        for(int n=0;n<4;n++){
            float2 e = up2(acc[p][n]);
            int r = r0+2*p, c = c0+n;
            g_opart[pb + (size_t)r*64 + c]     = e.x;
            g_opart[pb + (size_t)(r+1)*64 + c] = e.y;
        }
    }
}

// ---------------- K6b: sum partials + residual + attn LN -----------------------
__global__ void k_attnout_fin(const float* __restrict__ enc, const float* __restrict__ lnw,
                              const float* __restrict__ lnb){
    __shared__ float Hs[64][68];
    int b=blockIdx.y, l0=blockIdx.x*64, tid=threadIdx.x;
    for(int i=tid;i<4096;i+=256){
        int l=i>>6, c=i&63;
        size_t off = ((size_t)(b)*LL + l0+l)*64 + c;
        size_t stp = (size_t)BB*LL*64;
        float s = g_opart[off] + g_opart[off+stp] + g_opart[off+2*stp] + g_opart[off+3*stp]
                + enc[(size_t)(b*CC+c)*LL + l0+l];
        Hs[l][c]=s;
    }
    __syncthreads();
    int row=tid>>2, qq=tid&3;
    float s1=0.f, s2=0.f;
    #pragma unroll
    for(int c=qq*16;c<qq*16+16;c++){ float v=Hs[row][c]; s1+=v; s2+=v*v; }
    s1 += __shfl_xor_sync(0xffffffffu, s1, 1);
    s2 += __shfl_xor_sync(0xffffffffu, s2, 1);
    s1 += __shfl_xor_sync(0xffffffffu, s1, 2);
    s2 += __shfl_xor_sync(0xffffffffu, s2, 2);
    float mean = s1*(1.f/64.f);
    float var  = s2*(1.f/64.f) - mean*mean;
    float iv = rsqrtf(var+1e-5f);
    #pragma unroll
    for(int c=qq*16;c<qq*16+16;c++){
        g_tok[(size_t)(b*LL+l0+row)*64+c] = (Hs[row][c]-mean)*iv*lnw[c]+lnb[c];
    }
}

// ---------------- K7: tok @ ss_in_w -> x1pre (B,DN,L) & z (B,L,DN) -------------
__global__ void k_xz(const float* __restrict__ win){
    __shared__ float Xs[64][68];
    __shared__ float Ws[64][68];
    int b=blockIdx.z, j0=blockIdx.y*64, l0=blockIdx.x*64, tid=threadIdx.x;
    for(int i=tid;i<4096;i+=256){
        int ll=i>>6, c=i&63;
        Xs[c][ll] = g_tok[(size_t)(b*LL+l0+ll)*64 + c];
    }
    for(int i=tid;i<4096;i+=256){
        int c=i>>6, jj=i&63;
        Ws[c][jj] = win[(size_t)c*256 + j0 + jj];
    }
    __syncthreads();
    int rg=tid>>4, cg=tid&15; int r0=rg*4, c0=cg*4;
    u64 acc[2][4]={};
    #pragma unroll 4
    for(int c=0;c<64;c++){
        u64 a0=*(const u64*)&Xs[c][r0], a1=*(const u64*)&Xs[c][r0+2];
        float4 bv=*(const float4*)&Ws[c][c0];
        u64 b0=pk2(bv.x,bv.x), b1=pk2(bv.y,bv.y), b2=pk2(bv.z,bv.z), b3=pk2(bv.w,bv.w);
        acc[0][0]=fma2(a0,b0,acc[0][0]); acc[0][1]=fma2(a0,b1,acc[0][1]);
        acc[0][2]=fma2(a0,b2,acc[0][2]); acc[0][3]=fma2(a0,b3,acc[0][3]);
        acc[1][0]=fma2(a1,b0,acc[1][0]); acc[1][1]=fma2(a1,b1,acc[1][1]);
        acc[1][2]=fma2(a1,b2,acc[1][2]); acc[1][3]=fma2(a1,b3,acc[1][3]);
    }
    #pragma unroll
    for(int p=0;p<2;p++){
        #pragma unroll
        for(int n=0;n<4;n++){
            float2 e = up2(acc[p][n]);
            int j=j0+c0+n;
            int la=l0+r0+2*p, lb=la+1;
            if(j<128){
                g_x1pre[((size_t)b*128+j)*LL + la] = e.x;
                g_x1pre[((size_t)b*128+j)*LL + lb] = e.y;
            } else {
                g_z[(size_t)(b*LL+la)*128 + (j-128)] = e.x;
                g_z[(size_t)(b*LL+lb)*128 + (j-128)] = e.y;
            }
        }
    }
}

// ---------------- K8: depthwise 3x3 + bias + silu ------------------------------
__global__ void k_dwconv(const float* __restrict__ wconv, const float* __restrict__ bias){
    __shared__ float pl[HHH*WWW];
    int b=blockIdx.y, d=blockIdx.x, tid=threadIdx.x;
    const float* ip = g_x1pre + (size_t)(b*DNN+d)*LL;
    for(int i=tid;i<LL;i+=256) pl[i]=ip[i];
    __syncthreads();
    float w[9];
    #pragma unroll
    for(int i=0;i<9;i++) w[i]=wconv[d*9+i];
    float bb = bias[d];
    float* op = g_x1 + (size_t)(b*DNN+d)*LL;
    for(int p=tid;p<LL;p+=256){
        int h=p/WWW, x=p%WWW;
        float s=bb;
        #pragma unroll
        for(int kh=0;kh<3;kh++){
            int ih=h+kh-1;
            if(ih<0||ih>=HHH) continue;
            #pragma unroll
            for(int kw=0;kw<3;kw++){
                int iw=x+kw-1;
                if(iw<0||iw>=WWW) continue;
                s += w[kh*3+kw]*pl[ih*WWW+iw];
            }
        }
        op[p] = silu_f(s);
    }
}

// ---------------- K9: x_dbl + dts/B/C extraction -------------------------------
__global__ void k_xdbl(const float* __restrict__ xproj, const float* __restrict__ dtw,
                       const float* __restrict__ dtb){
    __shared__ float xs_s[128][32];
    __shared__ float pj_s[36*128];
    __shared__ float xd_s[36][33];
    int b=blockIdx.z, k=blockIdx.y, l0=blockIdx.x*32;
    int bk=b*4+k, tid=threadIdx.x;
    for(int i=tid;i<36*128;i+=256) pj_s[i]=xproj[(size_t)k*36*128+i];
    const float* x1p = g_x1 + (size_t)b*128*LL;
    for(int i=tid;i<128*32;i+=256){
        int d=i>>5, ll=i&31;
        int lp=l0+ll, src;
        if(k==0) src=lp;
        else if(k==1) src=(lp%48)*48 + lp/48;
        else if(k==2) src=LL-1-lp;
        else { int t2=LL-1-lp; src=(t2%48)*48 + t2/48; }
        xs_s[d][ll]=x1p[(size_t)d*LL+src];
    }
    __syncthreads();
    {
        int ll=tid&31, g=tid>>5;
        for(int c=g;c<36;c+=8){
            float s=0.f;
            #pragma unroll 8
            for(int d=0;d<128;d++) s += pj_s[c*128+d]*xs_s[d][ll];
            xd_s[c][ll]=s;
        }
    }
    __syncthreads();
    {
        int ll=tid&31, g=tid>>5;
        float r0v=xd_s[0][ll],r1v=xd_s[1][ll],r2v=xd_s[2][ll],r3v=xd_s[3][ll];
        for(int i=0;i<16;i++){
            int d=g*16+i;
            const float* w=dtw+((size_t)k*128+d)*4;
            float dv=r0v*w[0]+r1v*w[1]+r2v*w[2]+r3v*w[3]+dtb[k*128+d];
            float sp=softplus_f(dv);
            size_t o=((size_t)bk*128+d)*LL + l0+ll;
            g_dt[o]=sp;
            g_u[o]=sp*xs_s[d][ll];
        }
    }
    for(int idx=tid;idx<32*16;idx+=256){
        int ll=idx>>4, n=idx&15;
        size_t o=((size_t)bk*LL + l0+ll)*16 + n;
        g_Bsc[o]=xd_s[4+n][ll];
        g_Csc[o]=xd_s[20+n][ll];
    }
}

// ---------------- K10: selective scan ------------------------------------------
__global__ void k_scan(const float* __restrict__ Alog){
    int lane=threadIdx.x;
    int half=lane>>4, n=lane&15;
    int ci = blockIdx.x*2 + half;
    int bk = ci>>7, d = ci&127, k = bk&3;
    const float* dtp = g_dt + (size_t)ci*LL;
    const float* up  = g_u  + (size_t)ci*LL;
    const float* Bp  = g_Bsc + (size_t)bk*LL*16;
    const float* Cp  = g_Csc + (size_t)bk*LL*16;
    float* yp = g_ys + (size_t)ci*LL;
    float A = -__expf(Alog[((size_t)k*128+d)*16 + n]);
    float h = 0.f;
    #pragma unroll 4
    for(int l=0;l<LL;l++){
        float dt = dtp[l];
        float u  = up[l];
        float Bn = Bp[l*16+n];
        float Cn = Cp[l*16+n];
        float dA = __expf(dt*A);
        h = h*dA + u*Bn;
        float y = h*Cn;
        y += __shfl_xor_sync(0xffffffffu, y, 8);
        y += __shfl_xor_sync(0xffffffffu, y, 4);
        y += __shfl_xor_sync(0xffffffffu, y, 2);
        y += __shfl_xor_sync(0xffffffffu, y, 1);
        if(n==0) yp[l]=y;
    }
}

// ---------------- K11: direction merge + ss LN + gating + out proj + ffn LN ----
__global__ void k_combine(const float* __restrict__ enc, const float* __restrict__ snr,
                          const float* __restrict__ Dw,  const float* __restrict__ nw,
                          const float* __restrict__ nb,  const float* __restrict__ outw,
                          const float* __restrict__ fw,  const float* __restrict__ fb){
    __shared__ float yv[128];
    __shared__ float ra[128], rb[128];
    __shared__ float pbuf[128];
    __shared__ float x2s[64];
    __shared__ float rc[64], rd[64];
    int b=blockIdx.y, l=blockIdx.x, tid=threadIdx.x;
    int hh=l/48, ww=l%48;
    int m = ww*48 + hh;
    int fl = LL-1-l, fm = LL-1-m;
    int d = tid;
    size_t base = (size_t)b*4*128*LL;
    float y = g_ys[base + ((size_t)(0*128+d))*LL + l]
            + g_ys[base + ((size_t)(2*128+d))*LL + fl]
            + g_ys[base + ((size_t)(1*128+d))*LL + m]
            + g_ys[base + ((size_t)(3*128+d))*LL + fm];
    float sD = Dw[0*128+d]+Dw[1*128+d]+Dw[2*128+d]+Dw[3*128+d];
    y += sD * g_x1[(size_t)(b*128+d)*LL + l];
    ra[tid]=y; rb[tid]=y*y; __syncthreads();
    for(int s=64;s>0;s>>=1){ if(tid<s){ ra[tid]+=ra[tid+s]; rb[tid]+=rb[tid+s]; } __syncthreads(); }
    float mean = ra[0]*(1.f/128.f);
    float var  = rb[0]*(1.f/128.f)-mean*mean;
    float ln = (y-mean)*rsqrtf(var+1e-5f)*nw[d]+nb[d];
    float z  = g_z[(size_t)(b*LL+l)*128+d];
    yv[d] = ln * silu_f(z) * snr[b*LL+l];
    __syncthreads();
    int c=tid&63, hf=tid>>6;
    float acc=0.f;
    #pragma unroll 8
    for(int dd=hf*64; dd<hf*64+64; dd++) acc += yv[dd]*outw[(size_t)dd*64+c];
    pbuf[tid]=acc; __syncthreads();
    if(tid<64){
        float x2 = pbuf[tid]+pbuf[tid+64] + enc[(size_t)(b*CC+tid)*LL + l];
        x2s[tid]=x2;
        g_x2[(size_t)(b*LL+l)*64+tid]=x2;
        rc[tid]=x2; rd[tid]=x2*x2;
    }
    __syncthreads();
    for(int s=32;s>0;s>>=1){ if(tid<s){ rc[tid]+=rc[tid+s]; rd[tid]+=rd[tid+s]; } __syncthreads(); }
    if(tid<64){
        float mn=rc[0]*(1.f/64.f);
        float vr=rd[0]*(1.f/64.f)-mn*mn;
        g_xn[(size_t)(b*LL+l)*64+tid] = (x2s[tid]-mn)*rsqrtf(vr+1e-5f)*fw[tid]+fb[tid];
    }
}

// ---------------- K12: ffn1 = gelu(xn @ w1^T) -> (B,256,L) ---------------------
__global__ void k_ffn1(const float* __restrict__ w1){
    __shared__ float Xs[64][68];
    __shared__ float Ws[64][68];
    int b=blockIdx.z, o0=blockIdx.y*64, l0=blockIdx.x*64, tid=threadIdx.x;
    for(int i=tid;i<4096;i+=256){
        int ll=i>>6, c=i&63;
        Xs[c][ll]=g_xn[(size_t)(b*LL+l0+ll)*64+c];
    }
    for(int i=tid;i<4096;i+=256){
        int oo=i>>6, c=i&63;
        Ws[c][oo]=w1[(size_t)(o0+oo)*64+c];
    }
    __syncthreads();
    int rg=tid>>4, cg=tid&15; int r0=rg*4, c0=cg*4;
    u64 acc[2][4]={};
    #pragma unroll 4
    for(int c=0;c<64;c++){
        u64 a0=*(const u64*)&Xs[c][r0], a1=*(const u64*)&Xs[c][r0+2];
        float4 bv=*(const float4*)&Ws[c][c0];
        u64 b0=pk2(bv.x,bv.x), b1=pk2(bv.y,bv.y), b2=pk2(bv.z,bv.z), b3=pk2(bv.w,bv.w);
        acc[0][0]=fma2(a0,b0,acc[0][0]); acc[0][1]=fma2(a0,b1,acc[0][1]);
        acc[0][2]=fma2(a0,b2,acc[0][2]); acc[0][3]=fma2(a0,b3,acc[0][3]);
        acc[1][0]=fma2(a1,b0,acc[1][0]); acc[1][1]=fma2(a1,b1,acc[1][1]);
        acc[1][2]=fma2(a1,b2,acc[1][2]); acc[1][3]=fma2(a1,b3,acc[1][3]);
    }
    #pragma unroll
    for(int p=0;p<2;p++){
        #pragma unroll
        for(int n=0;n<4;n++){
            float2 e = up2(acc[p][n]);
            int la=l0+r0+2*p;
            g_h1[(size_t)(b*256+o0+c0+n)*LL + la  ] = gelu_f(e.x);
            g_h1[(size_t)(b*256+o0+c0+n)*LL + la+1] = gelu_f(e.y);
        }
    }
}

// ---------------- K13: depthwise 3x3 + gelu (256 ch) ---------------------------
__global__ void k_dwgelu(const float* __restrict__ wconv){
    __shared__ float pl[HHH*WWW];
    int b=blockIdx.y, d=blockIdx.x, tid=threadIdx.x;
    const float* ip = g_h1 + (size_t)(b*CM+d)*LL;
    for(int i=tid;i<LL;i+=256) pl[i]=ip[i];
    __syncthreads();
    float w[9];
    #pragma unroll
    for(int i=0;i<9;i++) w[i]=wconv[d*9+i];
    float* op = g_h2 + (size_t)(b*CM+d)*LL;
    for(int p=tid;p<LL;p+=256){
        int h=p/WWW, x=p%WWW;
        float s=0.f;
        #pragma unroll
        for(int kh=0;kh<3;kh++){
            int ih=h+kh-1;
            if(ih<0||ih>=HHH) continue;
            #pragma unroll
            for(int kw=0;kw<3;kw++){
                int iw=x+kw-1;
                if(iw<0||iw>=WWW) continue;
                s += w[kh*3+kw]*pl[ih*WWW+iw];
            }
        }
        op[p] = gelu_f(s);
    }
}

// ---------------- K14: ffn2 + residual + NCHW output ---------------------------
__global__ void k_ffn2(const float* __restrict__ w2, float* __restrict__ out){
    __shared__ float Hs[64][68];
    __shared__ float Ws[64][68];
    int b=blockIdx.y, l0=blockIdx.x*64, tid=threadIdx.x;
    int rg=tid>>4, cg=tid&15; int r0=rg*4, c0=cg*4;
    u64 acc[2][4]={};
    for(int m0=0;m0<256;m0+=64){
        __syncthreads();
        for(int i=tid;i<4096;i+=256){
            int mm=i>>6, ll=i&63;
            Hs[mm][ll]=g_h2[(size_t)(b*256+m0+mm)*LL + l0+ll];
        }
        for(int i=tid;i<4096;i+=256){
            int c=i&63, mm=i>>6;
            Ws[mm][c]=w2[(size_t)c*256 + m0+mm];
        }
        __syncthreads();
        #pragma unroll 4
        for(int mm=0;mm<64;mm++){
            u64 a0=*(const u64*)&Hs[mm][r0], a1=*(const u64*)&Hs[mm][r0+2];
            float4 bv; bv.x=Ws[mm][c0]; bv.y=Ws[mm][c0+1]; bv.z=Ws[mm][c0+2]; bv.w=Ws[mm][c0+3];
            u64 b0=pk2(bv.x,bv.x), b1=pk2(bv.y,bv.y), b2=pk2(bv.z,bv.z), b3=pk2(bv.w,bv.w);
            acc[0][0]=fma2(a0,b0,acc[0][0]); acc[0][1]=fma2(a0,b1,acc[0][1]);
            acc[0][2]=fma2(a0,b2,acc[0][2]); acc[0][3]=fma2(a0,b3,acc[0][3]);
            acc[1][0]=fma2(a1,b0,acc[1][0]); acc[1][1]=fma2(a1,b1,acc[1][1]);
            acc[1][2]=fma2(a1,b2,acc[1][2]); acc[1][3]=fma2(a1,b3,acc[1][3]);
        }
    }
    #pragma unroll
    for(int p=0;p<2;p++){
        #pragma unroll
        for(int n=0;n<4;n++){
            float2 e = up2(acc[p][n]);
            int la=l0+r0+2*p, c=c0+n;
            out[(size_t)(b*64+c)*LL + la  ] = e.x + g_x2[(size_t)(b*LL+la  )*64+c];
            out[(size_t)(b*64+c)*LL + la+1] = e.y + g_x2[(size_t)(b*LL+la+1)*64+c];
        }
    }
}

// ---------------- launch --------------------------------------------------------
extern "C" void kernel_launch(void* const* d_in, const int* in_sizes, int n_in,
                              void* d_out, int out_size){
    (void)in_sizes; (void)n_in; (void)out_size;
    const float* enc       = (const float*)d_in[0];
    const float* snr       = (const float*)d_in[1];
    const float* attn_wq   = (const float*)d_in[2];
    const float* attn_wk   = (const float*)d_in[3];
    const float* attn_wv   = (const float*)d_in[4];
    const float* attn_fc   = (const float*)d_in[5];
    const float* attn_ln_w = (const float*)d_in[6];
    const float* attn_ln_b = (const float*)d_in[7];
    const float* ss_in_w   = (const float*)d_in[8];
    const float* ss_conv_w = (const float*)d_in[9];
    const float* ss_conv_b = (const float*)d_in[10];
    const float* ss_xproj  = (const float*)d_in[11];
    const float* ss_dt_w   = (const float*)d_in[12];
    const float* ss_dt_b   = (const float*)d_in[13];
    const float* ss_Alog   = (const float*)d_in[14];
    const float* ss_D      = (const float*)d_in[15];
    const float* ss_norm_w = (const float*)d_in[16];
    const float* ss_norm_b = (const float*)d_in[17];
    const float* ss_out_w  = (const float*)d_in[18];
    const float* ffn_ln_w  = (const float*)d_in[19];
    const float* ffn_ln_b  = (const float*)d_in[20];
    const float* ffn_w1    = (const float*)d_in[21];
    const float* ffn_dw    = (const float*)d_in[22];
    const float* ffn_w2    = (const float*)d_in[23];
    float* out = (float*)d_out;

    k_logsnr<<<(BB*LL+255)/256, 256>>>(snr);
    k_qkv   <<<dim3(LL/64, 32, BB), 256>>>(enc, attn_wq, attn_wk, attn_wv);
    k_flash <<<dim3(LL/128, BHN), 256>>>();
    k_attnout_part<<<dim3(LL/64, 4, BB), 256>>>(attn_fc);
    k_attnout_fin <<<dim3(LL/64, BB), 256>>>(enc, attn_ln_w, attn_ln_b);
    k_xz    <<<dim3(LL/64, 4, BB), 256>>>(ss_in_w);
    k_dwconv<<<dim3(DNN, BB), 256>>>(ss_conv_w, ss_conv_b);
    k_xdbl  <<<dim3(LL/32, 4, BB), 256>>>(ss_xproj, ss_dt_w, ss_dt_b);
    k_scan  <<<BB*4*DNN/2, 32>>>(ss_Alog);
    k_combine<<<dim3(LL, BB), 128>>>(enc, snr, ss_D, ss_norm_w, ss_norm_b,
                                     ss_out_w, ffn_ln_w, ffn_ln_b);
    k_ffn1  <<<dim3(LL/64, CM/64, BB), 256>>>(ffn_w1);
    k_dwgelu<<<dim3(CM, BB), 256>>>(ffn_dw);
    k_ffn2  <<<dim3(LL/64, BB), 256>>>(ffn_w2, out);
}

// round 9
// speedup vs baseline: 4.2204x; 1.0067x over previous
#include <cuda_runtime.h>
#include <cuda_bf16.h>
#include <math.h>

#define BB 2
#define CC 64
#define HHH 48
#define WWW 48
#define LL 2304
#define NHH 8
#define DKK 64
#define DVV 128
#define DNN 128
#define NSS 16
#define CM 256
#define BHN (BB*NHH)

typedef unsigned long long u64;

// ---------------- packed fp32 helpers (Blackwell f32x2) ----------------------
__device__ __forceinline__ u64 pk2(float x, float y){
    u64 r; asm("mov.b64 %0, {%1,%2};" : "=l"(r) : "f"(x), "f"(y)); return r;
}
__device__ __forceinline__ u64 fma2(u64 a, u64 b, u64 c){
    u64 d; asm("fma.rn.f32x2 %0, %1, %2, %3;" : "=l"(d) : "l"(a), "l"(b), "l"(c)); return d;
}
__device__ __forceinline__ float2 up2(u64 a){
    float2 f; asm("mov.b64 {%0,%1}, %2;" : "=f"(f.x), "=f"(f.y) : "l"(a)); return f;
}

// ---------------- bf16 mma helpers -------------------------------------------
__device__ __forceinline__ unsigned pkbf(float lo, float hi){
    unsigned r; asm("cvt.rn.bf16x2.f32 %0, %1, %2;" : "=r"(r) : "f"(hi), "f"(lo)); return r;
}
__device__ __forceinline__ void ldsm_x2(unsigned& r0, unsigned& r1, unsigned addr){
    asm volatile("ldmatrix.sync.aligned.m8n8.x2.shared.b16 {%0,%1}, [%2];"
        : "=r"(r0), "=r"(r1) : "r"(addr));
}
__device__ __forceinline__ void ldsm_x2t(unsigned& r0, unsigned& r1, unsigned addr){
    asm volatile("ldmatrix.sync.aligned.m8n8.x2.trans.shared.b16 {%0,%1}, [%2];"
        : "=r"(r0), "=r"(r1) : "r"(addr));
}
__device__ __forceinline__ void ldsm_x4(unsigned* r, unsigned addr){
    asm volatile("ldmatrix.sync.aligned.m8n8.x4.shared.b16 {%0,%1,%2,%3}, [%4];"
        : "=r"(r[0]), "=r"(r[1]), "=r"(r[2]), "=r"(r[3]) : "r"(addr));
}
__device__ __forceinline__ void mma_bf16(float& d0, float& d1, float& d2, float& d3,
    unsigned a0, unsigned a1, unsigned a2, unsigned a3, unsigned b0, unsigned b1){
    asm volatile("mma.sync.aligned.m16n8k16.row.col.f32.bf16.bf16.f32 "
        "{%0,%1,%2,%3}, {%4,%5,%6,%7}, {%8,%9}, {%0,%1,%2,%3};"
        : "+f"(d0), "+f"(d1), "+f"(d2), "+f"(d3)
        : "r"(a0), "r"(a1), "r"(a2), "r"(a3), "r"(b0), "r"(b1));
}
__device__ __forceinline__ void cpa16(unsigned smem, const void* g){
    asm volatile("cp.async.ca.shared.global [%0], [%1], 16;" :: "r"(smem), "l"(g));
}
__device__ __forceinline__ void cpa_commit(){
    asm volatile("cp.async.commit_group;" ::: "memory");
}
template<int N>
__device__ __forceinline__ void cpa_wait(){
    asm volatile("cp.async.wait_group %0;" :: "n"(N) : "memory");
}

// ---------------- scratch (static device globals; no runtime alloc) ----------
__device__ __nv_bfloat16 g_qh[BHN*LL*DKK];
__device__ __nv_bfloat16 g_kh[BHN*LL*DKK];
__device__ __nv_bfloat16 g_vh[BHN*LL*DVV];
__device__ float g_logsnr[BB*LL];
__device__ float g_o[BB*LL*NHH*DVV];
__device__ float g_opart[4*BB*LL*CC];
__device__ float g_tok[BB*LL*CC];
__device__ float g_z[BB*LL*DNN];
__device__ float g_x1pre[BB*DNN*LL];
__device__ float g_x1[BB*DNN*LL];
__device__ float g_dt[BB*4*DNN*LL];
__device__ float g_u[BB*4*DNN*LL];
__device__ float g_Bsc[BB*4*LL*NSS];
__device__ float g_Csc[BB*4*LL*NSS];
__device__ float g_ys[BB*4*DNN*LL];
__device__ float g_x2[BB*LL*CC];
__device__ float g_xn[BB*LL*CC];
__device__ float g_h1[BB*CM*LL];
__device__ float g_h2[BB*CM*LL];

// ---------------- helpers ----------------------------------------------------
__device__ __forceinline__ float silu_f(float x){ return x/(1.f+__expf(-x)); }
__device__ __forceinline__ float gelu_f(float x){ return 0.5f*x*(1.f+erff(x*0.70710678118654752440f)); }
__device__ __forceinline__ float softplus_f(float x){ return fmaxf(x,0.f)+log1pf(__expf(-fabsf(x))); }

// ---------------- K1: log(snr+1e-4) ------------------------------------------
__global__ void k_logsnr(const float* __restrict__ snr){
    int i = blockIdx.x*256 + threadIdx.x;
    if(i < BB*LL) g_logsnr[i] = logf(snr[i] + 1e-4f);
}

// ---------------- K2: QKV projections -> bf16 outputs --------------------------
__global__ void k_qkv(const float* __restrict__ enc, const float* __restrict__ wq,
                      const float* __restrict__ wk, const float* __restrict__ wv){
    __shared__ float Xs[64][68];  // [c][l]
    __shared__ float Ws[64][68];  // [c][j]
    int b = blockIdx.z;
    int l0 = blockIdx.x*64;
    int t  = blockIdx.y;
    const float* wptr; int j0, wwid, which;
    if(t < 8){ wptr=wq; j0=t*64; wwid=512; which=0; }
    else if(t < 16){ wptr=wk; j0=(t-8)*64; wwid=512; which=1; }
    else { wptr=wv; j0=(t-16)*64; wwid=1024; which=2; }
    int tid = threadIdx.x;
    for(int i=tid;i<4096;i+=256){
        int c=i>>6, ll=i&63;
        Xs[c][ll] = enc[(size_t)(b*CC+c)*LL + l0 + ll];
    }
    for(int i=tid;i<4096;i+=256){
        int c=i>>6, jj=i&63;
        Ws[c][jj] = wptr[(size_t)c*wwid + j0 + jj];
    }
    __syncthreads();
    int rg=tid>>4, cg=tid&15; int r0=rg*4, c0=cg*4;
    u64 acc[2][4] = {};
    #pragma unroll 4
    for(int c=0;c<64;c++){
        u64 a0=*(const u64*)&Xs[c][r0], a1=*(const u64*)&Xs[c][r0+2];
        float4 bv=*(const float4*)&Ws[c][c0];
        u64 b0=pk2(bv.x,bv.x), b1=pk2(bv.y,bv.y), b2=pk2(bv.z,bv.z), b3=pk2(bv.w,bv.w);
        acc[0][0]=fma2(a0,b0,acc[0][0]); acc[0][1]=fma2(a0,b1,acc[0][1]);
        acc[0][2]=fma2(a0,b2,acc[0][2]); acc[0][3]=fma2(a0,b3,acc[0][3]);
        acc[1][0]=fma2(a1,b0,acc[1][0]); acc[1][1]=fma2(a1,b1,acc[1][1]);
        acc[1][2]=fma2(a1,b2,acc[1][2]); acc[1][3]=fma2(a1,b3,acc[1][3]);
    }
    #pragma unroll
    for(int p=0;p<2;p++){
        #pragma unroll
        for(int n=0;n<4;n++){
            float2 e = up2(acc[p][n]);
            int j = j0+c0+n;
            int la = l0+r0+2*p, lb = la+1;
            if(which==0){ int h=j>>6, dk=j&63;
                g_qh[((size_t)(b*8+h)*LL+la)*64+dk]=__float2bfloat16(e.x);
                g_qh[((size_t)(b*8+h)*LL+lb)*64+dk]=__float2bfloat16(e.y); }
            else if(which==1){ int h=j>>6, dk=j&63;
                g_kh[((size_t)(b*8+h)*LL+la)*64+dk]=__float2bfloat16(e.x);
                g_kh[((size_t)(b*8+h)*LL+lb)*64+dk]=__float2bfloat16(e.y); }
            else { int h=j>>7, dv=j&127;
                g_vh[((size_t)(b*8+h)*LL+la)*128+dv]=__float2bfloat16(e.x);
                g_vh[((size_t)(b*8+h)*LL+lb)*128+dv]=__float2bfloat16(e.y); }
        }
    }
}

// ---------------- K3: flash attention, bf16 mma, cp.async double buffer --------
// dyn smem layout (bytes):
//   PQ   [128*72 bf16]      @ 0       (18432)
//   Ksm0/1 [64*72 bf16]     @ 18432 / 27648   (9216 each)
//   Vsm0/1 [64*136 bf16]    @ 36864 / 54272   (17408 each)
//   lsb0/1 [64 f32]         @ 71680 / 71936   (256 each)
//   lrow  [128 f32]         @ 72192   (512)    -> total 72704
#define FSM_TOTAL 72704
__global__ void __launch_bounds__(256,2) k_flash(const float* __restrict__ snr_unused){
    extern __shared__ char dynsm[];
    __nv_bfloat16* PQ  = (__nv_bfloat16*)dynsm;
    __nv_bfloat16* Ks0 = (__nv_bfloat16*)(dynsm + 18432);
    __nv_bfloat16* Vs0 = (__nv_bfloat16*)(dynsm + 36864);
    float* lsb0 = (float*)(dynsm + 71680);
    float* lrow = (float*)(dynsm + 72192);

    int bh = blockIdx.y; int b = bh>>3, h = bh&7;
    int i0 = blockIdx.x*128;
    int tid = threadIdx.x;
    int w = tid>>5, lane = tid&31;
    int qg = lane>>2, tg = lane&3;
    int m0 = w*16;
    const __nv_bfloat16* qp = g_qh + (size_t)bh*LL*64;
    const __nv_bfloat16* kp = g_kh + (size_t)bh*LL*64;
    const __nv_bfloat16* vp = g_vh + (size_t)bh*LL*128;
    const float* lsg = g_logsnr + b*LL;

    unsigned pqU = (unsigned)__cvta_generic_to_shared(PQ);
    unsigned ksU0 = (unsigned)__cvta_generic_to_shared(Ks0);
    unsigned vsU0 = (unsigned)__cvta_generic_to_shared(Vs0);
    unsigned lsU0 = (unsigned)__cvta_generic_to_shared(lsb0);

    // async stage of tile j0 into buffer bf (0/1)
    auto stage = [&](int j0, int bf){
        unsigned kb = ksU0 + bf*9216u;
        unsigned vb = vsU0 + bf*17408u;
        unsigned lb = lsU0 + bf*256u;
        #pragma unroll
        for(int it=0;it<2;it++){
            int idx = tid*8 + it*2048;
            int r=idx>>6, c=idx&63;
            cpa16(kb + (unsigned)((r*72+c)*2), kp + (size_t)(j0+r)*64 + c);
        }
        #pragma unroll
        for(int it=0;it<4;it++){
            int idx = tid*8 + it*2048;
            int r=idx>>7, c=idx&127;
            cpa16(vb + (unsigned)((r*136+c)*2), vp + (size_t)(j0+r)*128 + c);
        }
        if(tid<16) cpa16(lb + tid*16u, lsg + j0 + tid*4);
    };

    // kick off tile 0 staging first so it overlaps Q staging
    stage(0, 0);
    cpa_commit();

    // stage Q tile (synchronous bf16 copy)
    for(int idx=tid*8; idx<128*64; idx+=2048){
        int r=idx>>6, c=idx&63;
        *(uint4*)&PQ[r*72 + c] = *(const uint4*)(qp + (size_t)(i0+r)*64 + c);
    }
    if(tid<128) lrow[tid]=0.f;
    __syncthreads();

    unsigned aq[4][4];
    #pragma unroll
    for(int ks=0;ks<4;ks++){
        int colb = ks*16 + 2*tg;
        aq[ks][0] = *(const unsigned*)&PQ[(m0+qg  )*72 + colb    ];
        aq[ks][1] = *(const unsigned*)&PQ[(m0+8+qg)*72 + colb    ];
        aq[ks][2] = *(const unsigned*)&PQ[(m0+qg  )*72 + colb + 8];
        aq[ks][3] = *(const unsigned*)&PQ[(m0+8+qg)*72 + colb + 8];
    }

    float O[16][4];
    #pragma unroll
    for(int i=0;i<16;i++){ O[i][0]=0.f; O[i][1]=0.f; O[i][2]=0.f; O[i][3]=0.f; }

    int srow = lane&7, smat = (lane>>3)&1;
    int amat = lane>>3;
    unsigned pA = pqU + (unsigned)((((m0 + srow + 8*(amat&1))*72) + 8*(amat>>1))*2);

    for(int t=0;t<LL/64;t++){
        int cur = t&1;
        if(t+1 < LL/64){ stage((t+1)*64, cur^1); cpa_commit(); cpa_wait<1>(); }
        else cpa_wait<0>();
        __syncthreads();

        unsigned kB = ksU0 + cur*9216u  + (unsigned)((srow*72 + smat*8)*2);
        unsigned vB = vsU0 + cur*17408u + (unsigned)(((srow + 8*smat)*136)*2);
        const float* lssh = (const float*)(dynsm + 71680 + cur*256);

        // --- S = Q K^T, P = exp(S/8 + logsnr) ---
        float psLo=0.f, psHi=0.f;
        #pragma unroll
        for(int nt=0;nt<8;nt++){
            int n0=nt*8;
            float d0=0.f,d1=0.f,d2=0.f,d3=0.f;
            #pragma unroll
            for(int ks=0;ks<4;ks++){
                unsigned b0,b1;
                ldsm_x2(b0,b1, kB + (unsigned)((n0*72 + ks*16)*2));
                mma_bf16(d0,d1,d2,d3, aq[ks][0],aq[ks][1],aq[ks][2],aq[ks][3], b0,b1);
            }
            int c0=n0+2*tg;
            float ls0=lssh[c0], ls1=lssh[c0+1];
            float p0=__expf(d0*0.125f + ls0);
            float p1=__expf(d1*0.125f + ls1);
            float p2=__expf(d2*0.125f + ls0);
            float p3=__expf(d3*0.125f + ls1);
            psLo += p0+p1; psHi += p2+p3;
            *(unsigned*)&PQ[(m0+qg  )*72 + c0] = pkbf(p0,p1);
            *(unsigned*)&PQ[(m0+8+qg)*72 + c0] = pkbf(p2,p3);
        }
        psLo += __shfl_xor_sync(0xffffffffu, psLo, 1);
        psLo += __shfl_xor_sync(0xffffffffu, psLo, 2);
        psHi += __shfl_xor_sync(0xffffffffu, psHi, 1);
        psHi += __shfl_xor_sync(0xffffffffu, psHi, 2);
        if(tg==0){ lrow[m0+qg] += psLo; lrow[m0+8+qg] += psHi; }
        __syncwarp();

        // --- O += P @ V ---
        unsigned ap[4][4];
        #pragma unroll
        for(int ks=0;ks<4;ks++)
            ldsm_x4(ap[ks], pA + (unsigned)(ks*16*2));
        #pragma unroll
        for(int nt=0;nt<16;nt++){
            int n0=nt*8;
            #pragma unroll
            for(int ks=0;ks<4;ks++){
                unsigned b0,b1;
                ldsm_x2t(b0,b1, vB + (unsigned)((ks*16*136 + n0)*2));
                mma_bf16(O[nt][0],O[nt][1],O[nt][2],O[nt][3],
                         ap[ks][0],ap[ks][1],ap[ks][2],ap[ks][3], b0,b1);
            }
        }
        __syncthreads();
    }

    float invLo = 1.f/lrow[m0+qg];
    float invHi = 1.f/lrow[m0+8+qg];
    size_t oa = (size_t)(b*LL + i0 + m0 + qg  )*1024 + h*128;
    size_t ob = (size_t)(b*LL + i0 + m0 + 8+qg)*1024 + h*128;
    #pragma unroll
    for(int nt=0;nt<16;nt++){
        int dv = nt*8 + 2*tg;
        float2 wa; wa.x=O[nt][0]*invLo; wa.y=O[nt][1]*invLo;
        float2 wb; wb.x=O[nt][2]*invHi; wb.y=O[nt][3]*invHi;
        *(float2*)(g_o + oa + dv) = wa;
        *(float2*)(g_o + ob + dv) = wb;
    }
}

// ---------------- K6a: o@fc split-K partial GEMM -------------------------------
__global__ void k_attnout_part(const float* __restrict__ fc){
    __shared__ float Hs[64][68];
    __shared__ float Ws[64][68];
    int b=blockIdx.z, ky=blockIdx.y, l0=blockIdx.x*64, tid=threadIdx.x;
    int rg=tid>>4, cg=tid&15; int r0=rg*4, c0=cg*4;
    u64 acc[2][4]={};
    for(int m0=ky*256; m0<ky*256+256; m0+=64){
        __syncthreads();
        for(int i=tid;i<4096;i+=256){
            int mm=i&63, ll=i>>6;
            Hs[mm][ll]=g_o[(size_t)(b*LL+l0+ll)*1024 + m0+mm];
        }
        for(int i=tid;i<4096;i+=256){
            int c=i&63, mm=i>>6;
            Ws[mm][c]=fc[(size_t)(m0+mm)*64+c];
        }
        __syncthreads();
        #pragma unroll 4
        for(int mm=0;mm<64;mm++){
            u64 a0=*(const u64*)&Hs[mm][r0], a1=*(const u64*)&Hs[mm][r0+2];
            float4 bv=*(const float4*)&Ws[mm][c0];
            u64 b0=pk2(bv.x,bv.x), b1=pk2(bv.y,bv.y), b2=pk2(bv.z,bv.z), b3=pk2(bv.w,bv.w);
            acc[0][0]=fma2(a0,b0,acc[0][0]); acc[0][1]=fma2(a0,b1,acc[0][1]);
            acc[0][2]=fma2(a0,b2,acc[0][2]); acc[0][3]=fma2(a0,b3,acc[0][3]);
            acc[1][0]=fma2(a1,b0,acc[1][0]); acc[1][1]=fma2(a1,b1,acc[1][1]);
            acc[1][2]=fma2(a1,b2,acc[1][2]); acc[1][3]=fma2(a1,b3,acc[1][3]);
        }
    }
    size_t pb = ((size_t)(ky*BB + b)*LL + l0)*64;
    #pragma unroll
    for(int p=0;p<2;p++){
        #pragma unroll
        for(int n=0;n<4;n++){
            float2 e = up2(acc[p][n]);
            int r = r0+2*p, c = c0+n;
            g_opart[pb + (size_t)r*64 + c]     = e.x;
            g_opart[pb + (size_t)(r+1)*64 + c] = e.y;
        }
    }
}

// ---------------- K6b: sum partials + residual + attn LN -----------------------
__global__ void k_attnout_fin(const float* __restrict__ enc, const float* __restrict__ lnw,
                              const float* __restrict__ lnb){
    __shared__ float Hs[64][68];
    int b=blockIdx.y, l0=blockIdx.x*64, tid=threadIdx.x;
    for(int i=tid;i<4096;i+=256){
        int l=i>>6, c=i&63;
        size_t off = ((size_t)(b)*LL + l0+l)*64 + c;
        size_t stp = (size_t)BB*LL*64;
        float s = g_opart[off] + g_opart[off+stp] + g_opart[off+2*stp] + g_opart[off+3*stp]
                + enc[(size_t)(b*CC+c)*LL + l0+l];
        Hs[l][c]=s;
    }
    __syncthreads();
    int row=tid>>2, qq=tid&3;
    float s1=0.f, s2=0.f;
    #pragma unroll
    for(int c=qq*16;c<qq*16+16;c++){ float v=Hs[row][c]; s1+=v; s2+=v*v; }
    s1 += __shfl_xor_sync(0xffffffffu, s1, 1);
    s2 += __shfl_xor_sync(0xffffffffu, s2, 1);
    s1 += __shfl_xor_sync(0xffffffffu, s1, 2);
    s2 += __shfl_xor_sync(0xffffffffu, s2, 2);
    float mean = s1*(1.f/64.f);
    float var  = s2*(1.f/64.f) - mean*mean;
    float iv = rsqrtf(var+1e-5f);
    #pragma unroll
    for(int c=qq*16;c<qq*16+16;c++){
        g_tok[(size_t)(b*LL+l0+row)*64+c] = (Hs[row][c]-mean)*iv*lnw[c]+lnb[c];
    }
}

// ---------------- K7: tok @ ss_in_w -> x1pre (B,DN,L) & z (B,L,DN) -------------
__global__ void k_xz(const float* __restrict__ win){
    __shared__ float Xs[64][68];
    __shared__ float Ws[64][68];
    int b=blockIdx.z, j0=blockIdx.y*64, l0=blockIdx.x*64, tid=threadIdx.x;
    for(int i=tid;i<4096;i+=256){
        int ll=i>>6, c=i&63;
        Xs[c][ll] = g_tok[(size_t)(b*LL+l0+ll)*64 + c];
    }
    for(int i=tid;i<4096;i+=256){
        int c=i>>6, jj=i&63;
        Ws[c][jj] = win[(size_t)c*256 + j0 + jj];
    }
    __syncthreads();
    int rg=tid>>4, cg=tid&15; int r0=rg*4, c0=cg*4;
    u64 acc[2][4]={};
    #pragma unroll 4
    for(int c=0;c<64;c++){
        u64 a0=*(const u64*)&Xs[c][r0], a1=*(const u64*)&Xs[c][r0+2];
        float4 bv=*(const float4*)&Ws[c][c0];
        u64 b0=pk2(bv.x,bv.x), b1=pk2(bv.y,bv.y), b2=pk2(bv.z,bv.z), b3=pk2(bv.w,bv.w);
        acc[0][0]=fma2(a0,b0,acc[0][0]); acc[0][1]=fma2(a0,b1,acc[0][1]);
        acc[0][2]=fma2(a0,b2,acc[0][2]); acc[0][3]=fma2(a0,b3,acc[0][3]);
        acc[1][0]=fma2(a1,b0,acc[1][0]); acc[1][1]=fma2(a1,b1,acc[1][1]);
        acc[1][2]=fma2(a1,b2,acc[1][2]); acc[1][3]=fma2(a1,b3,acc[1][3]);
    }
    #pragma unroll
    for(int p=0;p<2;p++){
        #pragma unroll
        for(int n=0;n<4;n++){
            float2 e = up2(acc[p][n]);
            int j=j0+c0+n;
            int la=l0+r0+2*p, lb=la+1;
            if(j<128){
                g_x1pre[((size_t)b*128+j)*LL + la] = e.x;
                g_x1pre[((size_t)b*128+j)*LL + lb] = e.y;
            } else {
                g_z[(size_t)(b*LL+la)*128 + (j-128)] = e.x;
                g_z[(size_t)(b*LL+lb)*128 + (j-128)] = e.y;
            }
        }
    }
}

// ---------------- K8: depthwise 3x3 + bias + silu ------------------------------
__global__ void k_dwconv(const float* __restrict__ wconv, const float* __restrict__ bias){
    __shared__ float pl[HHH*WWW];
    int b=blockIdx.y, d=blockIdx.x, tid=threadIdx.x;
    const float* ip = g_x1pre + (size_t)(b*DNN+d)*LL;
    for(int i=tid;i<LL;i+=256) pl[i]=ip[i];
    __syncthreads();
    float w[9];
    #pragma unroll
    for(int i=0;i<9;i++) w[i]=wconv[d*9+i];
    float bb = bias[d];
    float* op = g_x1 + (size_t)(b*DNN+d)*LL;
    for(int p=tid;p<LL;p+=256){
        int h=p/WWW, x=p%WWW;
        float s=bb;
        #pragma unroll
        for(int kh=0;kh<3;kh++){
            int ih=h+kh-1;
            if(ih<0||ih>=HHH) continue;
            #pragma unroll
            for(int kw=0;kw<3;kw++){
                int iw=x+kw-1;
                if(iw<0||iw>=WWW) continue;
                s += w[kh*3+kw]*pl[ih*WWW+iw];
            }
        }
        op[p] = silu_f(s);
    }
}

// ---------------- K9: x_dbl + dts/B/C extraction -------------------------------
__global__ void k_xdbl(const float* __restrict__ xproj, const float* __restrict__ dtw,
                       const float* __restrict__ dtb){
    __shared__ float xs_s[128][32];
    __shared__ float pj_s[36*128];
    __shared__ float xd_s[36][33];
    int b=blockIdx.z, k=blockIdx.y, l0=blockIdx.x*32;
    int bk=b*4+k, tid=threadIdx.x;
    for(int i=tid;i<36*128;i+=256) pj_s[i]=xproj[(size_t)k*36*128+i];
    const float* x1p = g_x1 + (size_t)b*128*LL;
    for(int i=tid;i<128*32;i+=256){
        int d=i>>5, ll=i&31;
        int lp=l0+ll, src;
        if(k==0) src=lp;
        else if(k==1) src=(lp%48)*48 + lp/48;
        else if(k==2) src=LL-1-lp;
        else { int t2=LL-1-lp; src=(t2%48)*48 + t2/48; }
        xs_s[d][ll]=x1p[(size_t)d*LL+src];
    }
    __syncthreads();
    {
        int ll=tid&31, g=tid>>5;
        for(int c=g;c<36;c+=8){
            float s=0.f;
            #pragma unroll 8
            for(int d=0;d<128;d++) s += pj_s[c*128+d]*xs_s[d][ll];
            xd_s[c][ll]=s;
        }
    }
    __syncthreads();
    {
        int ll=tid&31, g=tid>>5;
        float r0v=xd_s[0][ll],r1v=xd_s[1][ll],r2v=xd_s[2][ll],r3v=xd_s[3][ll];
        for(int i=0;i<16;i++){
            int d=g*16+i;
            const float* w=dtw+((size_t)k*128+d)*4;
            float dv=r0v*w[0]+r1v*w[1]+r2v*w[2]+r3v*w[3]+dtb[k*128+d];
            float sp=softplus_f(dv);
            size_t o=((size_t)bk*128+d)*LL + l0+ll;
            g_dt[o]=sp;
            g_u[o]=sp*xs_s[d][ll];
        }
    }
    for(int idx=tid;idx<32*16;idx+=256){
        int ll=idx>>4, n=idx&15;
        size_t o=((size_t)bk*LL + l0+ll)*16 + n;
        g_Bsc[o]=xd_s[4+n][ll];
        g_Csc[o]=xd_s[20+n][ll];
    }
}

// ---------------- K10: selective scan ------------------------------------------
__global__ void k_scan(const float* __restrict__ Alog){
    int lane=threadIdx.x;
    int half=lane>>4, n=lane&15;
    int ci = blockIdx.x*2 + half;
    int bk = ci>>7, d = ci&127, k = bk&3;
    const float* dtp = g_dt + (size_t)ci*LL;
    const float* up  = g_u  + (size_t)ci*LL;
    const float* Bp  = g_Bsc + (size_t)bk*LL*16;
    const float* Cp  = g_Csc + (size_t)bk*LL*16;
    float* yp = g_ys + (size_t)ci*LL;
    float A = -__expf(Alog[((size_t)k*128+d)*16 + n]);
    float h = 0.f;
    #pragma unroll 4
    for(int l=0;l<LL;l++){
        float dt = dtp[l];
        float u  = up[l];
        float Bn = Bp[l*16+n];
        float Cn = Cp[l*16+n];
        float dA = __expf(dt*A);
        h = h*dA + u*Bn;
        float y = h*Cn;
        y += __shfl_xor_sync(0xffffffffu, y, 8);
        y += __shfl_xor_sync(0xffffffffu, y, 4);
        y += __shfl_xor_sync(0xffffffffu, y, 2);
        y += __shfl_xor_sync(0xffffffffu, y, 1);
        if(n==0) yp[l]=y;
    }
}

// ---------------- K11: direction merge + ss LN + gating + out proj + ffn LN ----
__global__ void k_combine(const float* __restrict__ enc, const float* __restrict__ snr,
                          const float* __restrict__ Dw,  const float* __restrict__ nw,
                          const float* __restrict__ nb,  const float* __restrict__ outw,
                          const float* __restrict__ fw,  const float* __restrict__ fb){
    __shared__ float yv[128];
    __shared__ float ra[128], rb[128];
    __shared__ float pbuf[128];
    __shared__ float x2s[64];
    __shared__ float rc[64], rd[64];
    int b=blockIdx.y, l=blockIdx.x, tid=threadIdx.x;
    int hh=l/48, ww=l%48;
    int m = ww*48 + hh;
    int fl = LL-1-l, fm = LL-1-m;
    int d = tid;
    size_t base = (size_t)b*4*128*LL;
    float y = g_ys[base + ((size_t)(0*128+d))*LL + l]
            + g_ys[base + ((size_t)(2*128+d))*LL + fl]
            + g_ys[base + ((size_t)(1*128+d))*LL + m]
            + g_ys[base + ((size_t)(3*128+d))*LL + fm];
    float sD = Dw[0*128+d]+Dw[1*128+d]+Dw[2*128+d]+Dw[3*128+d];
    y += sD * g_x1[(size_t)(b*128+d)*LL + l];
    ra[tid]=y; rb[tid]=y*y; __syncthreads();
    for(int s=64;s>0;s>>=1){ if(tid<s){ ra[tid]+=ra[tid+s]; rb[tid]+=rb[tid+s]; } __syncthreads(); }
    float mean = ra[0]*(1.f/128.f);
    float var  = rb[0]*(1.f/128.f)-mean*mean;
    float ln = (y-mean)*rsqrtf(var+1e-5f)*nw[d]+nb[d];
    float z  = g_z[(size_t)(b*LL+l)*128+d];
    yv[d] = ln * silu_f(z) * snr[b*LL+l];
    __syncthreads();
    int c=tid&63, hf=tid>>6;
    float acc=0.f;
    #pragma unroll 8
    for(int dd=hf*64; dd<hf*64+64; dd++) acc += yv[dd]*outw[(size_t)dd*64+c];
    pbuf[tid]=acc; __syncthreads();
    if(tid<64){
        float x2 = pbuf[tid]+pbuf[tid+64] + enc[(size_t)(b*CC+tid)*LL + l];
        x2s[tid]=x2;
        g_x2[(size_t)(b*LL+l)*64+tid]=x2;
        rc[tid]=x2; rd[tid]=x2*x2;
    }
    __syncthreads();
    for(int s=32;s>0;s>>=1){ if(tid<s){ rc[tid]+=rc[tid+s]; rd[tid]+=rd[tid+s]; } __syncthreads(); }
    if(tid<64){
        float mn=rc[0]*(1.f/64.f);
        float vr=rd[0]*(1.f/64.f)-mn*mn;
        g_xn[(size_t)(b*LL+l)*64+tid] = (x2s[tid]-mn)*rsqrtf(vr+1e-5f)*fw[tid]+fb[tid];
    }
}

// ---------------- K12: ffn1 = gelu(xn @ w1^T) -> (B,256,L) ---------------------
__global__ void k_ffn1(const float* __restrict__ w1){
    __shared__ float Xs[64][68];
    __shared__ float Ws[64][68];
    int b=blockIdx.z, o0=blockIdx.y*64, l0=blockIdx.x*64, tid=threadIdx.x;
    for(int i=tid;i<4096;i+=256){
        int ll=i>>6, c=i&63;
        Xs[c][ll]=g_xn[(size_t)(b*LL+l0+ll)*64+c];
    }
    for(int i=tid;i<4096;i+=256){
        int oo=i>>6, c=i&63;
        Ws[c][oo]=w1[(size_t)(o0+oo)*64+c];
    }
    __syncthreads();
    int rg=tid>>4, cg=tid&15; int r0=rg*4, c0=cg*4;
    u64 acc[2][4]={};
    #pragma unroll 4
    for(int c=0;c<64;c++){
        u64 a0=*(const u64*)&Xs[c][r0], a1=*(const u64*)&Xs[c][r0+2];
        float4 bv=*(const float4*)&Ws[c][c0];
        u64 b0=pk2(bv.x,bv.x), b1=pk2(bv.y,bv.y), b2=pk2(bv.z,bv.z), b3=pk2(bv.w,bv.w);
        acc[0][0]=fma2(a0,b0,acc[0][0]); acc[0][1]=fma2(a0,b1,acc[0][1]);
        acc[0][2]=fma2(a0,b2,acc[0][2]); acc[0][3]=fma2(a0,b3,acc[0][3]);
        acc[1][0]=fma2(a1,b0,acc[1][0]); acc[1][1]=fma2(a1,b1,acc[1][1]);
        acc[1][2]=fma2(a1,b2,acc[1][2]); acc[1][3]=fma2(a1,b3,acc[1][3]);
    }
    #pragma unroll
    for(int p=0;p<2;p++){
        #pragma unroll
        for(int n=0;n<4;n++){
            float2 e = up2(acc[p][n]);
            int la=l0+r0+2*p;
            g_h1[(size_t)(b*256+o0+c0+n)*LL + la  ] = gelu_f(e.x);
            g_h1[(size_t)(b*256+o0+c0+n)*LL + la+1] = gelu_f(e.y);
        }
    }
}

// ---------------- K13: depthwise 3x3 + gelu (256 ch) ---------------------------
__global__ void k_dwgelu(const float* __restrict__ wconv){
    __shared__ float pl[HHH*WWW];
    int b=blockIdx.y, d=blockIdx.x, tid=threadIdx.x;
    const float* ip = g_h1 + (size_t)(b*CM+d)*LL;
    for(int i=tid;i<LL;i+=256) pl[i]=ip[i];
    __syncthreads();
    float w[9];
    #pragma unroll
    for(int i=0;i<9;i++) w[i]=wconv[d*9+i];
    float* op = g_h2 + (size_t)(b*CM+d)*LL;
    for(int p=tid;p<LL;p+=256){
        int h=p/WWW, x=p%WWW;
        float s=0.f;
        #pragma unroll
        for(int kh=0;kh<3;kh++){
            int ih=h+kh-1;
            if(ih<0||ih>=HHH) continue;
            #pragma unroll
            for(int kw=0;kw<3;kw++){
                int iw=x+kw-1;
                if(iw<0||iw>=WWW) continue;
                s += w[kh*3+kw]*pl[ih*WWW+iw];
            }
        }
        op[p] = gelu_f(s);
    }
}

// ---------------- K14: ffn2 + residual + NCHW output ---------------------------
__global__ void k_ffn2(const float* __restrict__ w2, float* __restrict__ out){
    __shared__ float Hs[64][68];
    __shared__ float Ws[64][68];
    int b=blockIdx.y, l0=blockIdx.x*64, tid=threadIdx.x;
    int rg=tid>>4, cg=tid&15; int r0=rg*4, c0=cg*4;
    u64 acc[2][4]={};
    for(int m0=0;m0<256;m0+=64){
        __syncthreads();
        for(int i=tid;i<4096;i+=256){
            int mm=i>>6, ll=i&63;
            Hs[mm][ll]=g_h2[(size_t)(b*256+m0+mm)*LL + l0+ll];
        }
        for(int i=tid;i<4096;i+=256){
            int c=i&63, mm=i>>6;
            Ws[mm][c]=w2[(size_t)c*256 + m0+mm];
        }
        __syncthreads();
        #pragma unroll 4
        for(int mm=0;mm<64;mm++){
            u64 a0=*(const u64*)&Hs[mm][r0], a1=*(const u64*)&Hs[mm][r0+2];
            float4 bv; bv.x=Ws[mm][c0]; bv.y=Ws[mm][c0+1]; bv.z=Ws[mm][c0+2]; bv.w=Ws[mm][c0+3];
            u64 b0=pk2(bv.x,bv.x), b1=pk2(bv.y,bv.y), b2=pk2(bv.z,bv.z), b3=pk2(bv.w,bv.w);
            acc[0][0]=fma2(a0,b0,acc[0][0]); acc[0][1]=fma2(a0,b1,acc[0][1]);
            acc[0][2]=fma2(a0,b2,acc[0][2]); acc[0][3]=fma2(a0,b3,acc[0][3]);
            acc[1][0]=fma2(a1,b0,acc[1][0]); acc[1][1]=fma2(a1,b1,acc[1][1]);
            acc[1][2]=fma2(a1,b2,acc[1][2]); acc[1][3]=fma2(a1,b3,acc[1][3]);
        }
    }
    #pragma unroll
    for(int p=0;p<2;p++){
        #pragma unroll
        for(int n=0;n<4;n++){
            float2 e = up2(acc[p][n]);
            int la=l0+r0+2*p, c=c0+n;
            out[(size_t)(b*64+c)*LL + la  ] = e.x + g_x2[(size_t)(b*LL+la  )*64+c];
            out[(size_t)(b*64+c)*LL + la+1] = e.y + g_x2[(size_t)(b*LL+la+1)*64+c];
        }
    }
}

// ---------------- launch --------------------------------------------------------
extern "C" void kernel_launch(void* const* d_in, const int* in_sizes, int n_in,
                              void* d_out, int out_size){
    (void)in_sizes; (void)n_in; (void)out_size;
    const float* enc       = (const float*)d_in[0];
    const float* snr       = (const float*)d_in[1];
    const float* attn_wq   = (const float*)d_in[2];
    const float* attn_wk   = (const float*)d_in[3];
    const float* attn_wv   = (const float*)d_in[4];
    const float* attn_fc   = (const float*)d_in[5];
    const float* attn_ln_w = (const float*)d_in[6];
    const float* attn_ln_b = (const float*)d_in[7];
    const float* ss_in_w   = (const float*)d_in[8];
    const float* ss_conv_w = (const float*)d_in[9];
    const float* ss_conv_b = (const float*)d_in[10];
    const float* ss_xproj  = (const float*)d_in[11];
    const float* ss_dt_w   = (const float*)d_in[12];
    const float* ss_dt_b   = (const float*)d_in[13];
    const float* ss_Alog   = (const float*)d_in[14];
    const float* ss_D      = (const float*)d_in[15];
    const float* ss_norm_w = (const float*)d_in[16];
    const float* ss_norm_b = (const float*)d_in[17];
    const float* ss_out_w  = (const float*)d_in[18];
    const float* ffn_ln_w  = (const float*)d_in[19];
    const float* ffn_ln_b  = (const float*)d_in[20];
    const float* ffn_w1    = (const float*)d_in[21];
    const float* ffn_dw    = (const float*)d_in[22];
    const float* ffn_w2    = (const float*)d_in[23];
    float* out = (float*)d_out;

    cudaFuncSetAttribute(k_flash, cudaFuncAttributeMaxDynamicSharedMemorySize, FSM_TOTAL);

    k_logsnr<<<(BB*LL+255)/256, 256>>>(snr);
    k_qkv   <<<dim3(LL/64, 32, BB), 256>>>(enc, attn_wq, attn_wk, attn_wv);
    k_flash <<<dim3(LL/128, BHN), 256, FSM_TOTAL>>>(snr);
    k_attnout_part<<<dim3(LL/64, 4, BB), 256>>>(attn_fc);
    k_attnout_fin <<<dim3(LL/64, BB), 256>>>(enc, attn_ln_w, attn_ln_b);
    k_xz    <<<dim3(LL/64, 4, BB), 256>>>(ss_in_w);
    k_dwconv<<<dim3(DNN, BB), 256>>>(ss_conv_w, ss_conv_b);
    k_xdbl  <<<dim3(LL/32, 4, BB), 256>>>(ss_xproj, ss_dt_w, ss_dt_b);
    k_scan  <<<BB*4*DNN/2, 32>>>(ss_Alog);
    k_combine<<<dim3(LL, BB), 128>>>(enc, snr, ss_D, ss_norm_w, ss_norm_b,
                                     ss_out_w, ffn_ln_w, ffn_ln_b);
    k_ffn1  <<<dim3(LL/64, CM/64, BB), 256>>>(ffn_w1);
    k_dwgelu<<<dim3(CM, BB), 256>>>(ffn_dw);
    k_ffn2  <<<dim3(LL/64, BB), 256>>>(ffn_w2, out);
}

// round 12
// speedup vs baseline: 4.7595x; 1.1277x over previous
#include <cuda_runtime.h>
#include <cuda_bf16.h>
#include <math.h>

#define BB 2
#define CC 64
#define HHH 48
#define WWW 48
#define LL 2304
#define NHH 8
#define DKK 64
#define DVV 128
#define DNN 128
#define NSS 16
#define CM 256
#define BHN (BB*NHH)

typedef unsigned long long u64;

// ---------------- packed fp32 helpers (Blackwell f32x2) ----------------------
__device__ __forceinline__ u64 pk2(float x, float y){
    u64 r; asm("mov.b64 %0, {%1,%2};" : "=l"(r) : "f"(x), "f"(y)); return r;
}
__device__ __forceinline__ u64 fma2(u64 a, u64 b, u64 c){
    u64 d; asm("fma.rn.f32x2 %0, %1, %2, %3;" : "=l"(d) : "l"(a), "l"(b), "l"(c)); return d;
}
__device__ __forceinline__ float2 up2(u64 a){
    float2 f; asm("mov.b64 {%0,%1}, %2;" : "=f"(f.x), "=f"(f.y) : "l"(a)); return f;
}

// ---------------- bf16 mma helpers -------------------------------------------
__device__ __forceinline__ unsigned pkbf(float lo, float hi){
    unsigned r; asm("cvt.rn.bf16x2.f32 %0, %1, %2;" : "=r"(r) : "f"(hi), "f"(lo)); return r;
}
__device__ __forceinline__ void ldsm_x2(unsigned& r0, unsigned& r1, unsigned addr){
    asm volatile("ldmatrix.sync.aligned.m8n8.x2.shared.b16 {%0,%1}, [%2];"
        : "=r"(r0), "=r"(r1) : "r"(addr));
}
__device__ __forceinline__ void ldsm_x2t(unsigned& r0, unsigned& r1, unsigned addr){
    asm volatile("ldmatrix.sync.aligned.m8n8.x2.trans.shared.b16 {%0,%1}, [%2];"
        : "=r"(r0), "=r"(r1) : "r"(addr));
}
__device__ __forceinline__ void ldsm_x4(unsigned* r, unsigned addr){
    asm volatile("ldmatrix.sync.aligned.m8n8.x4.shared.b16 {%0,%1,%2,%3}, [%4];"
        : "=r"(r[0]), "=r"(r[1]), "=r"(r[2]), "=r"(r[3]) : "r"(addr));
}
__device__ __forceinline__ void mma_bf16(float& d0, float& d1, float& d2, float& d3,
    unsigned a0, unsigned a1, unsigned a2, unsigned a3, unsigned b0, unsigned b1){
    asm volatile("mma.sync.aligned.m16n8k16.row.col.f32.bf16.bf16.f32 "
        "{%0,%1,%2,%3}, {%4,%5,%6,%7}, {%8,%9}, {%0,%1,%2,%3};"
        : "+f"(d0), "+f"(d1), "+f"(d2), "+f"(d3)
        : "r"(a0), "r"(a1), "r"(a2), "r"(a3), "r"(b0), "r"(b1));
}
__device__ __forceinline__ void cpa16(unsigned smem, const void* g){
    asm volatile("cp.async.ca.shared.global [%0], [%1], 16;" :: "r"(smem), "l"(g));
}
__device__ __forceinline__ void cpa_commit(){
    asm volatile("cp.async.commit_group;" ::: "memory");
}
template<int N>
__device__ __forceinline__ void cpa_wait(){
    asm volatile("cp.async.wait_group %0;" :: "n"(N) : "memory");
}

// ---------------- scratch (static device globals; no runtime alloc) ----------
__device__ __nv_bfloat16 g_qh[BHN*LL*DKK];
__device__ __nv_bfloat16 g_kh[BHN*LL*DKK];
__device__ __nv_bfloat16 g_vh[BHN*LL*DVV];
__device__ float g_logsnr[BB*LL];
__device__ __nv_bfloat16 g_oh[BB*LL*NHH*DVV];
__device__ float g_opart[4*BB*LL*CC];
__device__ float g_tok[BB*LL*CC];
__device__ float g_z[BB*LL*DNN];
__device__ float g_x1pre[BB*DNN*LL];
__device__ float g_x1[BB*DNN*LL];
__device__ float g_dt[BB*4*DNN*LL];
__device__ float g_u[BB*4*DNN*LL];
__device__ float g_Bsc[BB*4*LL*NSS];
__device__ float g_Csc[BB*4*LL*NSS];
__device__ float g_ys[BB*4*DNN*LL];
__device__ float g_x2[BB*LL*CC];
__device__ float g_xn[BB*LL*CC];
__device__ float g_h1[BB*CM*LL];
__device__ float g_h2[BB*CM*LL];

// ---------------- helpers ----------------------------------------------------
__device__ __forceinline__ float silu_f(float x){ return x/(1.f+__expf(-x)); }
__device__ __forceinline__ float gelu_f(float x){ return 0.5f*x*(1.f+erff(x*0.70710678118654752440f)); }
__device__ __forceinline__ float softplus_f(float x){ return fmaxf(x,0.f)+log1pf(__expf(-fabsf(x))); }

// ---------------- K1: log(snr+1e-4) ------------------------------------------
__global__ void k_logsnr(const float* __restrict__ snr){
    int i = blockIdx.x*256 + threadIdx.x;
    if(i < BB*LL) g_logsnr[i] = logf(snr[i] + 1e-4f);
}

// ---------------- K_pre: trivial slot-filler so ncu profiles k_flash ----------
__global__ void k_pre(){
    int i = threadIdx.x;
    g_opart[i] = 0.f;   // overwritten by k_attnout_part before any read
}

// ---------------- K2: QKV projections -> bf16 outputs --------------------------
__global__ void k_qkv(const float* __restrict__ enc, const float* __restrict__ wq,
                      const float* __restrict__ wk, const float* __restrict__ wv){
    __shared__ float Xs[64][68];
    __shared__ float Ws[64][68];
    int b = blockIdx.z;
    int l0 = blockIdx.x*64;
    int t  = blockIdx.y;
    const float* wptr; int j0, wwid, which;
    if(t < 8){ wptr=wq; j0=t*64; wwid=512; which=0; }
    else if(t < 16){ wptr=wk; j0=(t-8)*64; wwid=512; which=1; }
    else { wptr=wv; j0=(t-16)*64; wwid=1024; which=2; }
    int tid = threadIdx.x;
    for(int i=tid;i<4096;i+=256){
        int c=i>>6, ll=i&63;
        Xs[c][ll] = enc[(size_t)(b*CC+c)*LL + l0 + ll];
    }
    for(int i=tid;i<4096;i+=256){
        int c=i>>6, jj=i&63;
        Ws[c][jj] = wptr[(size_t)c*wwid + j0 + jj];
    }
    __syncthreads();
    int rg=tid>>4, cg=tid&15; int r0=rg*4, c0=cg*4;
    u64 acc[2][4] = {};
    #pragma unroll 4
    for(int c=0;c<64;c++){
        u64 a0=*(const u64*)&Xs[c][r0], a1=*(const u64*)&Xs[c][r0+2];
        float4 bv=*(const float4*)&Ws[c][c0];
        u64 b0=pk2(bv.x,bv.x), b1=pk2(bv.y,bv.y), b2=pk2(bv.z,bv.z), b3=pk2(bv.w,bv.w);
        acc[0][0]=fma2(a0,b0,acc[0][0]); acc[0][1]=fma2(a0,b1,acc[0][1]);
        acc[0][2]=fma2(a0,b2,acc[0][2]); acc[0][3]=fma2(a0,b3,acc[0][3]);
        acc[1][0]=fma2(a1,b0,acc[1][0]); acc[1][1]=fma2(a1,b1,acc[1][1]);
        acc[1][2]=fma2(a1,b2,acc[1][2]); acc[1][3]=fma2(a1,b3,acc[1][3]);
    }
    #pragma unroll
    for(int p=0;p<2;p++){
        #pragma unroll
        for(int n=0;n<4;n++){
            float2 e = up2(acc[p][n]);
            int j = j0+c0+n;
            int la = l0+r0+2*p, lb = la+1;
            if(which==0){ int h=j>>6, dk=j&63;
                g_qh[((size_t)(b*8+h)*LL+la)*64+dk]=__float2bfloat16(e.x);
                g_qh[((size_t)(b*8+h)*LL+lb)*64+dk]=__float2bfloat16(e.y); }
            else if(which==1){ int h=j>>6, dk=j&63;
                g_kh[((size_t)(b*8+h)*LL+la)*64+dk]=__float2bfloat16(e.x);
                g_kh[((size_t)(b*8+h)*LL+lb)*64+dk]=__float2bfloat16(e.y); }
            else { int h=j>>7, dv=j&127;
                g_vh[((size_t)(b*8+h)*LL+la)*128+dv]=__float2bfloat16(e.x);
                g_vh[((size_t)(b*8+h)*LL+lb)*128+dv]=__float2bfloat16(e.y); }
        }
    }
}

// ---------------- K3: flash attention, bf16 mma, cp.async double buffer --------
#define FSM_TOTAL 72704
__global__ void __launch_bounds__(256,2) k_flash(){
    extern __shared__ char dynsm[];
    __nv_bfloat16* PQ  = (__nv_bfloat16*)dynsm;
    __nv_bfloat16* Ks0 = (__nv_bfloat16*)(dynsm + 18432);
    __nv_bfloat16* Vs0 = (__nv_bfloat16*)(dynsm + 36864);
    float* lsb0 = (float*)(dynsm + 71680);
    float* lrow = (float*)(dynsm + 72192);

    int bh = blockIdx.y; int b = bh>>3, h = bh&7;
    int i0 = blockIdx.x*128;
    int tid = threadIdx.x;
    int w = tid>>5, lane = tid&31;
    int qg = lane>>2, tg = lane&3;
    int m0 = w*16;
    const __nv_bfloat16* qp = g_qh + (size_t)bh*LL*64;
    const __nv_bfloat16* kp = g_kh + (size_t)bh*LL*64;
    const __nv_bfloat16* vp = g_vh + (size_t)bh*LL*128;
    const float* lsg = g_logsnr + b*LL;

    unsigned pqU = (unsigned)__cvta_generic_to_shared(PQ);
    unsigned ksU0 = (unsigned)__cvta_generic_to_shared(Ks0);
    unsigned vsU0 = (unsigned)__cvta_generic_to_shared(Vs0);
    unsigned lsU0 = (unsigned)__cvta_generic_to_shared(lsb0);

    auto stage = [&](int j0, int bf){
        unsigned kb = ksU0 + bf*9216u;
        unsigned vb = vsU0 + bf*17408u;
        unsigned lb = lsU0 + bf*256u;
        #pragma unroll
        for(int it=0;it<2;it++){
            int idx = tid*8 + it*2048;
            int r=idx>>6, c=idx&63;
            cpa16(kb + (unsigned)((r*72+c)*2), kp + (size_t)(j0+r)*64 + c);
        }
        #pragma unroll
        for(int it=0;it<4;it++){
            int idx = tid*8 + it*2048;
            int r=idx>>7, c=idx&127;
            cpa16(vb + (unsigned)((r*136+c)*2), vp + (size_t)(j0+r)*128 + c);
        }
        if(tid<16) cpa16(lb + tid*16u, lsg + j0 + tid*4);
    };

    stage(0, 0);
    cpa_commit();

    for(int idx=tid*8; idx<128*64; idx+=2048){
        int r=idx>>6, c=idx&63;
        *(uint4*)&PQ[r*72 + c] = *(const uint4*)(qp + (size_t)(i0+r)*64 + c);
    }
    if(tid<128) lrow[tid]=0.f;
    __syncthreads();

    unsigned aq[4][4];
    #pragma unroll
    for(int ks=0;ks<4;ks++){
        int colb = ks*16 + 2*tg;
        aq[ks][0] = *(const unsigned*)&PQ[(m0+qg  )*72 + colb    ];
        aq[ks][1] = *(const unsigned*)&PQ[(m0+8+qg)*72 + colb    ];
        aq[ks][2] = *(const unsigned*)&PQ[(m0+qg  )*72 + colb + 8];
        aq[ks][3] = *(const unsigned*)&PQ[(m0+8+qg)*72 + colb + 8];
    }

    float O[16][4];
    #pragma unroll
    for(int i=0;i<16;i++){ O[i][0]=0.f; O[i][1]=0.f; O[i][2]=0.f; O[i][3]=0.f; }

    int srow = lane&7, smat = (lane>>3)&1;
    int amat = lane>>3;
    unsigned pA = pqU + (unsigned)((((m0 + srow + 8*(amat&1))*72) + 8*(amat>>1))*2);

    for(int t=0;t<LL/64;t++){
        int cur = t&1;
        if(t+1 < LL/64){ stage((t+1)*64, cur^1); cpa_commit(); cpa_wait<1>(); }
        else cpa_wait<0>();
        __syncthreads();

        unsigned kB = ksU0 + cur*9216u  + (unsigned)((srow*72 + smat*8)*2);
        unsigned vB = vsU0 + cur*17408u + (unsigned)(((srow + 8*smat)*136)*2);
        const float* lssh = (const float*)(dynsm + 71680 + cur*256);

        float psLo=0.f, psHi=0.f;
        #pragma unroll
        for(int nt=0;nt<8;nt++){
            int n0=nt*8;
            float d0=0.f,d1=0.f,d2=0.f,d3=0.f;
            #pragma unroll
            for(int ks=0;ks<4;ks++){
                unsigned b0,b1;
                ldsm_x2(b0,b1, kB + (unsigned)((n0*72 + ks*16)*2));
                mma_bf16(d0,d1,d2,d3, aq[ks][0],aq[ks][1],aq[ks][2],aq[ks][3], b0,b1);
            }
            int c0=n0+2*tg;
            float ls0=lssh[c0], ls1=lssh[c0+1];
            float p0=__expf(d0*0.125f + ls0);
            float p1=__expf(d1*0.125f + ls1);
            float p2=__expf(d2*0.125f + ls0);
            float p3=__expf(d3*0.125f + ls1);
            psLo += p0+p1; psHi += p2+p3;
            *(unsigned*)&PQ[(m0+qg  )*72 + c0] = pkbf(p0,p1);
            *(unsigned*)&PQ[(m0+8+qg)*72 + c0] = pkbf(p2,p3);
        }
        psLo += __shfl_xor_sync(0xffffffffu, psLo, 1);
        psLo += __shfl_xor_sync(0xffffffffu, psLo, 2);
        psHi += __shfl_xor_sync(0xffffffffu, psHi, 1);
        psHi += __shfl_xor_sync(0xffffffffu, psHi, 2);
        if(tg==0){ lrow[m0+qg] += psLo; lrow[m0+8+qg] += psHi; }
        __syncwarp();

        unsigned ap[4][4];
        #pragma unroll
        for(int ks=0;ks<4;ks++)
            ldsm_x4(ap[ks], pA + (unsigned)(ks*16*2));
        #pragma unroll
        for(int nt=0;nt<16;nt++){
            int n0=nt*8;
            #pragma unroll
            for(int ks=0;ks<4;ks++){
                unsigned b0,b1;
                ldsm_x2t(b0,b1, vB + (unsigned)((ks*16*136 + n0)*2));
                mma_bf16(O[nt][0],O[nt][1],O[nt][2],O[nt][3],
                         ap[ks][0],ap[ks][1],ap[ks][2],ap[ks][3], b0,b1);
            }
        }
        __syncthreads();
    }

    float invLo = 1.f/lrow[m0+qg];
    float invHi = 1.f/lrow[m0+8+qg];
    size_t oa = (size_t)(b*LL + i0 + m0 + qg  )*1024 + h*128;
    size_t ob = (size_t)(b*LL + i0 + m0 + 8+qg)*1024 + h*128;
    #pragma unroll
    for(int nt=0;nt<16;nt++){
        int dv = nt*8 + 2*tg;
        *(unsigned*)(g_oh + oa + dv) = pkbf(O[nt][0]*invLo, O[nt][1]*invLo);
        *(unsigned*)(g_oh + ob + dv) = pkbf(O[nt][2]*invHi, O[nt][3]*invHi);
    }
}

// ---------------- K6a: o@fc split-K partial GEMM (bf16 o input) ----------------
__global__ void k_attnout_part(const float* __restrict__ fc){
    __shared__ float Hs[64][68];
    __shared__ float Ws[64][68];
    int b=blockIdx.z, ky=blockIdx.y, l0=blockIdx.x*64, tid=threadIdx.x;
    int rg=tid>>4, cg=tid&15; int r0=rg*4, c0=cg*4;
    u64 acc[2][4]={};
    for(int m0=ky*256; m0<ky*256+256; m0+=64){
        __syncthreads();
        for(int i=tid*8;i<4096;i+=2048){
            int mm=i&63, ll=i>>6;
            uint4 v = *(const uint4*)(g_oh + (size_t)(b*LL+l0+ll)*1024 + m0+mm);
            __nv_bfloat16 e[8];
            *(uint4*)e = v;
            #pragma unroll
            for(int s=0;s<8;s++) Hs[mm+s][ll] = __bfloat162float(e[s]);
        }
        for(int i=tid;i<4096;i+=256){
            int c=i&63, mm=i>>6;
            Ws[mm][c]=fc[(size_t)(m0+mm)*64+c];
        }
        __syncthreads();
        #pragma unroll 4
        for(int mm=0;mm<64;mm++){
            u64 a0=*(const u64*)&Hs[mm][r0], a1=*(const u64*)&Hs[mm][r0+2];
            float4 bv=*(const float4*)&Ws[mm][c0];
            u64 b0=pk2(bv.x,bv.x), b1=pk2(bv.y,bv.y), b2=pk2(bv.z,bv.z), b3=pk2(bv.w,bv.w);
            acc[0][0]=fma2(a0,b0,acc[0][0]); acc[0][1]=fma2(a0,b1,acc[0][1]);
            acc[0][2]=fma2(a0,b2,acc[0][2]); acc[0][3]=fma2(a0,b3,acc[0][3]);
            acc[1][0]=fma2(a1,b0,acc[1][0]); acc[1][1]=fma2(a1,b1,acc[1][1]);
            acc[1][2]=fma2(a1,b2,acc[1][2]); acc[1][3]=fma2(a1,b3,acc[1][3]);
        }
    }
    size_t pb = ((size_t)(ky*BB + b)*LL + l0)*64;
    #pragma unroll
    for(int p=0;p<2;p++){
        #pragma unroll
        for(int n=0;n<4;n++){
            float2 e = up2(acc[p][n]);
            int r = r0+2*p, c = c0+n;
            g_opart[pb + (size_t)r*64 + c]     = e.x;
            g_opart[pb + (size_t)(r+1)*64 + c] = e.y;
        }
    }
}

// ---------------- K6b: sum partials + residual + attn LN -----------------------
__global__ void k_attnout_fin(const float* __restrict__ enc, const float* __restrict__ lnw,
                              const float* __restrict__ lnb){
    __shared__ float Hs[64][68];
    int b=blockIdx.y, l0=blockIdx.x*64, tid=threadIdx.x;
    for(int i=tid;i<4096;i+=256){
        int l=i>>6, c=i&63;
        size_t off = ((size_t)(b)*LL + l0+l)*64 + c;
        size_t stp = (size_t)BB*LL*64;
        float s = g_opart[off] + g_opart[off+stp] + g_opart[off+2*stp] + g_opart[off+3*stp]
                + enc[(size_t)(b*CC+c)*LL + l0+l];
        Hs[l][c]=s;
    }
    __syncthreads();
    int row=tid>>2, qq=tid&3;
    float s1=0.f, s2=0.f;
    #pragma unroll
    for(int c=qq*16;c<qq*16+16;c++){ float v=Hs[row][c]; s1+=v; s2+=v*v; }
    s1 += __shfl_xor_sync(0xffffffffu, s1, 1);
    s2 += __shfl_xor_sync(0xffffffffu, s2, 1);
    s1 += __shfl_xor_sync(0xffffffffu, s1, 2);
    s2 += __shfl_xor_sync(0xffffffffu, s2, 2);
    float mean = s1*(1.f/64.f);
    float var  = s2*(1.f/64.f) - mean*mean;
    float iv = rsqrtf(var+1e-5f);
    #pragma unroll
    for(int c=qq*16;c<qq*16+16;c++){
        g_tok[(size_t)(b*LL+l0+row)*64+c] = (Hs[row][c]-mean)*iv*lnw[c]+lnb[c];
    }
}

// ---------------- K7: tok @ ss_in_w -> x1pre (B,DN,L) & z (B,L,DN) -------------
__global__ void k_xz(const float* __restrict__ win){
    __shared__ float Xs[64][68];
    __shared__ float Ws[64][68];
    int b=blockIdx.z, j0=blockIdx.y*64, l0=blockIdx.x*64, tid=threadIdx.x;
    for(int i=tid;i<4096;i+=256){
        int ll=i>>6, c=i&63;
        Xs[c][ll] = g_tok[(size_t)(b*LL+l0+ll)*64 + c];
    }
    for(int i=tid;i<4096;i+=256){
        int c=i>>6, jj=i&63;
        Ws[c][jj] = win[(size_t)c*256 + j0 + jj];
    }
    __syncthreads();
    int rg=tid>>4, cg=tid&15; int r0=rg*4, c0=cg*4;
    u64 acc[2][4]={};
    #pragma unroll 4
    for(int c=0;c<64;c++){
        u64 a0=*(const u64*)&Xs[c][r0], a1=*(const u64*)&Xs[c][r0+2];
        float4 bv=*(const float4*)&Ws[c][c0];
        u64 b0=pk2(bv.x,bv.x), b1=pk2(bv.y,bv.y), b2=pk2(bv.z,bv.z), b3=pk2(bv.w,bv.w);
        acc[0][0]=fma2(a0,b0,acc[0][0]); acc[0][1]=fma2(a0,b1,acc[0][1]);
        acc[0][2]=fma2(a0,b2,acc[0][2]); acc[0][3]=fma2(a0,b3,acc[0][3]);
        acc[1][0]=fma2(a1,b0,acc[1][0]); acc[1][1]=fma2(a1,b1,acc[1][1]);
        acc[1][2]=fma2(a1,b2,acc[1][2]); acc[1][3]=fma2(a1,b3,acc[1][3]);
    }
    #pragma unroll
    for(int p=0;p<2;p++){
        #pragma unroll
        for(int n=0;n<4;n++){
            float2 e = up2(acc[p][n]);
            int j=j0+c0+n;
            int la=l0+r0+2*p, lb=la+1;
            if(j<128){
                g_x1pre[((size_t)b*128+j)*LL + la] = e.x;
                g_x1pre[((size_t)b*128+j)*LL + lb] = e.y;
            } else {
                g_z[(size_t)(b*LL+la)*128 + (j-128)] = e.x;
                g_z[(size_t)(b*LL+lb)*128 + (j-128)] = e.y;
            }
        }
    }
}

// ---------------- K8: depthwise 3x3 + bias + silu ------------------------------
__global__ void k_dwconv(const float* __restrict__ wconv, const float* __restrict__ bias){
    __shared__ float pl[HHH*WWW];
    int b=blockIdx.y, d=blockIdx.x, tid=threadIdx.x;
    const float* ip = g_x1pre + (size_t)(b*DNN+d)*LL;
    for(int i=tid;i<LL;i+=256) pl[i]=ip[i];
    __syncthreads();
    float w[9];
    #pragma unroll
    for(int i=0;i<9;i++) w[i]=wconv[d*9+i];
    float bb = bias[d];
    float* op = g_x1 + (size_t)(b*DNN+d)*LL;
    for(int p=tid;p<LL;p+=256){
        int h=p/WWW, x=p%WWW;
        float s=bb;
        #pragma unroll
        for(int kh=0;kh<3;kh++){
            int ih=h+kh-1;
            if(ih<0||ih>=HHH) continue;
            #pragma unroll
            for(int kw=0;kw<3;kw++){
                int iw=x+kw-1;
                if(iw<0||iw>=WWW) continue;
                s += w[kh*3+kw]*pl[ih*WWW+iw];
            }
        }
        op[p] = silu_f(s);
    }
}

// ---------------- K9: x_dbl + dts/B/C extraction -------------------------------
__global__ void k_xdbl(const float* __restrict__ xproj, const float* __restrict__ dtw,
                       const float* __restrict__ dtb){
    __shared__ float xs_s[128][32];
    __shared__ float pj_s[36*128];
    __shared__ float xd_s[36][33];
    int b=blockIdx.z, k=blockIdx.y, l0=blockIdx.x*32;
    int bk=b*4+k, tid=threadIdx.x;
    for(int i=tid;i<36*128;i+=256) pj_s[i]=xproj[(size_t)k*36*128+i];
    const float* x1p = g_x1 + (size_t)b*128*LL;
    for(int i=tid;i<128*32;i+=256){
        int d=i>>5, ll=i&31;
        int lp=l0+ll, src;
        if(k==0) src=lp;
        else if(k==1) src=(lp%48)*48 + lp/48;
        else if(k==2) src=LL-1-lp;
        else { int t2=LL-1-lp; src=(t2%48)*48 + t2/48; }
        xs_s[d][ll]=x1p[(size_t)d*LL+src];
    }
    __syncthreads();
    {
        int ll=tid&31, g=tid>>5;
        for(int c=g;c<36;c+=8){
            float s=0.f;
            #pragma unroll 8
            for(int d=0;d<128;d++) s += pj_s[c*128+d]*xs_s[d][ll];
            xd_s[c][ll]=s;
        }
    }
    __syncthreads();
    {
        int ll=tid&31, g=tid>>5;
        float r0v=xd_s[0][ll],r1v=xd_s[1][ll],r2v=xd_s[2][ll],r3v=xd_s[3][ll];
        for(int i=0;i<16;i++){
            int d=g*16+i;
            const float* w=dtw+((size_t)k*128+d)*4;
            float dv=r0v*w[0]+r1v*w[1]+r2v*w[2]+r3v*w[3]+dtb[k*128+d];
            float sp=softplus_f(dv);
            size_t o=((size_t)bk*128+d)*LL + l0+ll;
            g_dt[o]=sp;
            g_u[o]=sp*xs_s[d][ll];
        }
    }
    for(int idx=tid;idx<32*16;idx+=256){
        int ll=idx>>4, n=idx&15;
        size_t o=((size_t)bk*LL + l0+ll)*16 + n;
        g_Bsc[o]=xd_s[4+n][ll];
        g_Csc[o]=xd_s[20+n][ll];
    }
}

// ---------------- K10: selective scan ------------------------------------------
__global__ void k_scan(const float* __restrict__ Alog){
    int lane=threadIdx.x;
    int half=lane>>4, n=lane&15;
    int ci = blockIdx.x*2 + half;
    int bk = ci>>7, d = ci&127, k = bk&3;
    const float* dtp = g_dt + (size_t)ci*LL;
    const float* up  = g_u  + (size_t)ci*LL;
    const float* Bp  = g_Bsc + (size_t)bk*LL*16;
    const float* Cp  = g_Csc + (size_t)bk*LL*16;
    float* yp = g_ys + (size_t)ci*LL;
    float A = -__expf(Alog[((size_t)k*128+d)*16 + n]);
    float h = 0.f;
    #pragma unroll 4
    for(int l=0;l<LL;l++){
        float dt = dtp[l];
        float u  = up[l];
        float Bn = Bp[l*16+n];
        float Cn = Cp[l*16+n];
        float dA = __expf(dt*A);
        h = h*dA + u*Bn;
        float y = h*Cn;
        y += __shfl_xor_sync(0xffffffffu, y, 8);
        y += __shfl_xor_sync(0xffffffffu, y, 4);
        y += __shfl_xor_sync(0xffffffffu, y, 2);
        y += __shfl_xor_sync(0xffffffffu, y, 1);
        if(n==0) yp[l]=y;
    }
}

// ---------------- K11: direction merge + ss LN + gating + out proj + ffn LN ----
__global__ void k_combine(const float* __restrict__ enc, const float* __restrict__ snr,
                          const float* __restrict__ Dw,  const float* __restrict__ nw,
                          const float* __restrict__ nb,  const float* __restrict__ outw,
                          const float* __restrict__ fw,  const float* __restrict__ fb){
    __shared__ float yv[128];
    __shared__ float ra[128], rb[128];
    __shared__ float pbuf[128];
    __shared__ float x2s[64];
    __shared__ float rc[64], rd[64];
    int b=blockIdx.y, l=blockIdx.x, tid=threadIdx.x;
    int hh=l/48, ww=l%48;
    int m = ww*48 + hh;
    int fl = LL-1-l, fm = LL-1-m;
    int d = tid;
    size_t base = (size_t)b*4*128*LL;
    float y = g_ys[base + ((size_t)(0*128+d))*LL + l]
            + g_ys[base + ((size_t)(2*128+d))*LL + fl]
            + g_ys[base + ((size_t)(1*128+d))*LL + m]
            + g_ys[base + ((size_t)(3*128+d))*LL + fm];
    float sD = Dw[0*128+d]+Dw[1*128+d]+Dw[2*128+d]+Dw[3*128+d];
    y += sD * g_x1[(size_t)(b*128+d)*LL + l];
    ra[tid]=y; rb[tid]=y*y; __syncthreads();
    for(int s=64;s>0;s>>=1){ if(tid<s){ ra[tid]+=ra[tid+s]; rb[tid]+=rb[tid+s]; } __syncthreads(); }
    float mean = ra[0]*(1.f/128.f);
    float var  = rb[0]*(1.f/128.f)-mean*mean;
    float ln = (y-mean)*rsqrtf(var+1e-5f)*nw[d]+nb[d];
    float z  = g_z[(size_t)(b*LL+l)*128+d];
    yv[d] = ln * silu_f(z) * snr[b*LL+l];
    __syncthreads();
    int c=tid&63, hf=tid>>6;
    float acc=0.f;
    #pragma unroll 8
    for(int dd=hf*64; dd<hf*64+64; dd++) acc += yv[dd]*outw[(size_t)dd*64+c];
    pbuf[tid]=acc; __syncthreads();
    if(tid<64){
        float x2 = pbuf[tid]+pbuf[tid+64] + enc[(size_t)(b*CC+tid)*LL + l];
        x2s[tid]=x2;
        g_x2[(size_t)(b*LL+l)*64+tid]=x2;
        rc[tid]=x2; rd[tid]=x2*x2;
    }
    __syncthreads();
    for(int s=32;s>0;s>>=1){ if(tid<s){ rc[tid]+=rc[tid+s]; rd[tid]+=rd[tid+s]; } __syncthreads(); }
    if(tid<64){
        float mn=rc[0]*(1.f/64.f);
        float vr=rd[0]*(1.f/64.f)-mn*mn;
        g_xn[(size_t)(b*LL+l)*64+tid] = (x2s[tid]-mn)*rsqrtf(vr+1e-5f)*fw[tid]+fb[tid];
    }
}

// ---------------- K12: ffn1 = gelu(xn @ w1^T) -> (B,256,L) ---------------------
__global__ void k_ffn1(const float* __restrict__ w1){
    __shared__ float Xs[64][68];
    __shared__ float Ws[64][68];
    int b=blockIdx.z, o0=blockIdx.y*64, l0=blockIdx.x*64, tid=threadIdx.x;
    for(int i=tid;i<4096;i+=256){
        int ll=i>>6, c=i&63;
        Xs[c][ll]=g_xn[(size_t)(b*LL+l0+ll)*64+c];
    }
    for(int i=tid;i<4096;i+=256){
        int oo=i>>6, c=i&63;
        Ws[c][oo]=w1[(size_t)(o0+oo)*64+c];
    }
    __syncthreads();
    int rg=tid>>4, cg=tid&15; int r0=rg*4, c0=cg*4;
    u64 acc[2][4]={};
    #pragma unroll 4
    for(int c=0;c<64;c++){
        u64 a0=*(const u64*)&Xs[c][r0], a1=*(const u64*)&Xs[c][r0+2];
        float4 bv=*(const float4*)&Ws[c][c0];
        u64 b0=pk2(bv.x,bv.x), b1=pk2(bv.y,bv.y), b2=pk2(bv.z,bv.z), b3=pk2(bv.w,bv.w);
        acc[0][0]=fma2(a0,b0,acc[0][0]); acc[0][1]=fma2(a0,b1,acc[0][1]);
        acc[0][2]=fma2(a0,b2,acc[0][2]); acc[0][3]=fma2(a0,b3,acc[0][3]);
        acc[1][0]=fma2(a1,b0,acc[1][0]); acc[1][1]=fma2(a1,b1,acc[1][1]);
        acc[1][2]=fma2(a1,b2,acc[1][2]); acc[1][3]=fma2(a1,b3,acc[1][3]);
    }
    #pragma unroll
    for(int p=0;p<2;p++){
        #pragma unroll
        for(int n=0;n<4;n++){
            float2 e = up2(acc[p][n]);
            int la=l0+r0+2*p;
            g_h1[(size_t)(b*256+o0+c0+n)*LL + la  ] = gelu_f(e.x);
            g_h1[(size_t)(b*256+o0+c0+n)*LL + la+1] = gelu_f(e.y);
        }
    }
}

// ---------------- K13: depthwise 3x3 + gelu (256 ch) ---------------------------
__global__ void k_dwgelu(const float* __restrict__ wconv){
    __shared__ float pl[HHH*WWW];
    int b=blockIdx.y, d=blockIdx.x, tid=threadIdx.x;
    const float* ip = g_h1 + (size_t)(b*CM+d)*LL;
    for(int i=tid;i<LL;i+=256) pl[i]=ip[i];
    __syncthreads();
    float w[9];
    #pragma unroll
    for(int i=0;i<9;i++) w[i]=wconv[d*9+i];
    float* op = g_h2 + (size_t)(b*CM+d)*LL;
    for(int p=tid;p<LL;p+=256){
        int h=p/WWW, x=p%WWW;
        float s=0.f;
        #pragma unroll
        for(int kh=0;kh<3;kh++){
            int ih=h+kh-1;
            if(ih<0||ih>=HHH) continue;
            #pragma unroll
            for(int kw=0;kw<3;kw++){
                int iw=x+kw-1;
                if(iw<0||iw>=WWW) continue;
                s += w[kh*3+kw]*pl[ih*WWW+iw];
            }
        }
        op[p] = gelu_f(s);
    }
}

// ---------------- K14: ffn2 + residual + NCHW output ---------------------------
__global__ void k_ffn2(const float* __restrict__ w2, float* __restrict__ out){
    __shared__ float Hs[64][68];
    __shared__ float Ws[64][68];
    int b=blockIdx.y, l0=blockIdx.x*64, tid=threadIdx.x;
    int rg=tid>>4, cg=tid&15; int r0=rg*4, c0=cg*4;
    u64 acc[2][4]={};
    for(int m0=0;m0<256;m0+=64){
        __syncthreads();
        for(int i=tid;i<4096;i+=256){
            int mm=i>>6, ll=i&63;
            Hs[mm][ll]=g_h2[(size_t)(b*256+m0+mm)*LL + l0+ll];
        }
        for(int i=tid;i<4096;i+=256){
            int c=i&63, mm=i>>6;
            Ws[mm][c]=w2[(size_t)c*256 + m0+mm];
        }
        __syncthreads();
        #pragma unroll 4
        for(int mm=0;mm<64;mm++){
            u64 a0=*(const u64*)&Hs[mm][r0], a1=*(const u64*)&Hs[mm][r0+2];
            float4 bv; bv.x=Ws[mm][c0]; bv.y=Ws[mm][c0+1]; bv.z=Ws[mm][c0+2]; bv.w=Ws[mm][c0+3];
            u64 b0=pk2(bv.x,bv.x), b1=pk2(bv.y,bv.y), b2=pk2(bv.z,bv.z), b3=pk2(bv.w,bv.w);
            acc[0][0]=fma2(a0,b0,acc[0][0]); acc[0][1]=fma2(a0,b1,acc[0][1]);
            acc[0][2]=fma2(a0,b2,acc[0][2]); acc[0][3]=fma2(a0,b3,acc[0][3]);
            acc[1][0]=fma2(a1,b0,acc[1][0]); acc[1][1]=fma2(a1,b1,acc[1][1]);
            acc[1][2]=fma2(a1,b2,acc[1][2]); acc[1][3]=fma2(a1,b3,acc[1][3]);
        }
    }
    #pragma unroll
    for(int p=0;p<2;p++){
        #pragma unroll
        for(int n=0;n<4;n++){
            float2 e = up2(acc[p][n]);
            int la=l0+r0+2*p, c=c0+n;
            out[(size_t)(b*64+c)*LL + la  ] = e.x + g_x2[(size_t)(b*LL+la  )*64+c];
            out[(size_t)(b*64+c)*LL + la+1] = e.y + g_x2[(size_t)(b*LL+la+1)*64+c];
        }
    }
}

// ---------------- launch --------------------------------------------------------
extern "C" void kernel_launch(void* const* d_in, const int* in_sizes, int n_in,
                              void* d_out, int out_size){
    (void)in_sizes; (void)n_in; (void)out_size;
    const float* enc       = (const float*)d_in[0];
    const float* snr       = (const float*)d_in[1];
    const float* attn_wq   = (const float*)d_in[2];
    const float* attn_wk   = (const float*)d_in[3];
    const float* attn_wv   = (const float*)d_in[4];
    const float* attn_fc   = (const float*)d_in[5];
    const float* attn_ln_w = (const float*)d_in[6];
    const float* attn_ln_b = (const float*)d_in[7];
    const float* ss_in_w   = (const float*)d_in[8];
    const float* ss_conv_w = (const float*)d_in[9];
    const float* ss_conv_b = (const float*)d_in[10];
    const float* ss_xproj  = (const float*)d_in[11];
    const float* ss_dt_w   = (const float*)d_in[12];
    const float* ss_dt_b   = (const float*)d_in[13];
    const float* ss_Alog   = (const float*)d_in[14];
    const float* ss_D      = (const float*)d_in[15];
    const float* ss_norm_w = (const float*)d_in[16];
    const float* ss_norm_b = (const float*)d_in[17];
    const float* ss_out_w  = (const float*)d_in[18];
    const float* ffn_ln_w  = (const float*)d_in[19];
    const float* ffn_ln_b  = (const float*)d_in[20];
    const float* ffn_w1    = (const float*)d_in[21];
    const float* ffn_dw    = (const float*)d_in[22];
    const float* ffn_w2    = (const float*)d_in[23];
    float* out = (float*)d_out;

    cudaFuncSetAttribute(k_flash, cudaFuncAttributeMaxDynamicSharedMemorySize, FSM_TOTAL);

    k_logsnr<<<(BB*LL+255)/256, 256>>>(snr);
    k_qkv   <<<dim3(LL/64, 32, BB), 256>>>(enc, attn_wq, attn_wk, attn_wv);
    k_pre   <<<1, 256>>>();
    k_flash <<<dim3(LL/128, BHN), 256, FSM_TOTAL>>>();
    k_attnout_part<<<dim3(LL/64, 4, BB), 256>>>(attn_fc);
    k_attnout_fin <<<dim3(LL/64, BB), 256>>>(enc, attn_ln_w, attn_ln_b);
    k_xz    <<<dim3(LL/64, 4, BB), 256>>>(ss_in_w);
    k_dwconv<<<dim3(DNN, BB), 256>>>(ss_conv_w, ss_conv_b);
    k_xdbl  <<<dim3(LL/32, 4, BB), 256>>>(ss_xproj, ss_dt_w, ss_dt_b);
    k_scan  <<<BB*4*DNN/2, 32>>>(ss_Alog);
    k_combine<<<dim3(LL, BB), 128>>>(enc, snr, ss_D, ss_norm_w, ss_norm_b,
                                     ss_out_w, ffn_ln_w, ffn_ln_b);
    k_ffn1  <<<dim3(LL/64, CM/64, BB), 256>>>(ffn_w1);
    k_dwgelu<<<dim3(CM, BB), 256>>>(ffn_dw);
    k_ffn2  <<<dim3(LL/64, BB), 256>>>(ffn_w2, out);
}